// round 9
// baseline (speedup 1.0000x reference)
#include <cuda_runtime.h>
#include <cuda_bf16.h>
#include <math.h>
#include <stdint.h>

// ---------------- scratch ----------------
#define Bsz 8
#define Nseq 1024
#define Cdim 768
#define Hh 8
#define Dd 96
#define Qq 8
#define NTOK (Bsz * Hh * Nseq)   // 65536, ordered m=(b,n,h)

__device__ uint32_t g_qkv_bf[Bsz * Nseq * 3 * Cdim / 2];   // bf16x2
__device__ uint32_t g_fused_bf[Bsz * Nseq * Cdim / 2];     // bf16x2
__device__ float g_qout[Bsz * Nseq * Cdim];
__device__ float g_y[Bsz * Nseq * Cdim];
__device__ float g_xmean[Bsz * Cdim];
__device__ float g_fw[Bsz * Cdim];
__device__ float g_hq[NTOK * 64];
__device__ float g_hk[NTOK * 64];
__device__ float g_meas[NTOK * 8];

// ---------------- mma helpers ----------------
__device__ __forceinline__ float to_tf32(float x) {
    uint32_t u;
    asm("cvt.rna.tf32.f32 %0, %1;" : "=r"(u) : "f"(x));
    return __uint_as_float(u);
}

__device__ __forceinline__ uint32_t pkbf(float x, float y) {
    __nv_bfloat162 t = __floats2bfloat162_rn(x, y);
    return *(uint32_t*)&t;
}

__device__ __forceinline__ void mma_tf32(float* c, const uint32_t* a, const uint32_t* b) {
    asm volatile(
        "mma.sync.aligned.m16n8k8.row.col.f32.tf32.tf32.f32 "
        "{%0,%1,%2,%3}, {%4,%5,%6,%7}, {%8,%9}, {%0,%1,%2,%3};"
        : "+f"(c[0]), "+f"(c[1]), "+f"(c[2]), "+f"(c[3])
        : "r"(a[0]), "r"(a[1]), "r"(a[2]), "r"(a[3]), "r"(b[0]), "r"(b[1]));
}

__device__ __forceinline__ void mma_bf16(float* c, const uint32_t* a, const uint32_t* b) {
    asm volatile(
        "mma.sync.aligned.m16n8k16.row.col.f32.bf16.bf16.f32 "
        "{%0,%1,%2,%3}, {%4,%5,%6,%7}, {%8,%9}, {%0,%1,%2,%3};"
        : "+f"(c[0]), "+f"(c[1]), "+f"(c[2]), "+f"(c[3])
        : "r"(a[0]), "r"(a[1]), "r"(a[2]), "r"(a[3]), "r"(b[0]), "r"(b[1]));
}

__device__ __forceinline__ void ldsm4(uint32_t& r0, uint32_t& r1, uint32_t& r2, uint32_t& r3,
                                      uint32_t addr) {
    asm volatile("ldmatrix.sync.aligned.m8n8.x4.shared.b16 {%0,%1,%2,%3}, [%4];"
                 : "=r"(r0), "=r"(r1), "=r"(r2), "=r"(r3) : "r"(addr));
}

// ================= ldmatrix-based bf16 GEMM tiles =================
// smem tile: 128 rows x 12 u32 (16 bf16 data + 4 u32 pad). BUFB bytes per buffer.
#define LDW 12
#define BUFB (128 * LDW * 4)

// ================= qkv GEMM: A fp32, B fp32, out bf16 =================
__global__ __launch_bounds__(256)
void mma_qkv(const float* __restrict__ A, const float* __restrict__ B,
             const float* __restrict__ bias, uint32_t* __restrict__ Cbf,
             int K, int lda, int ldb, int ldc) {
    __shared__ uint32_t As[2][128 * LDW];
    __shared__ uint32_t Bs[2][128 * LDW];
    int tid = threadIdx.x;
    int m0 = blockIdx.y * 128, n0 = blockIdx.x * 128;
    int arow = tid >> 1, apart = tid & 1;
    int bk2 = tid >> 5, bcol = (tid & 31) * 4;
    const float* Ap = A + (size_t)(m0 + arow) * lda + apart * 8;
    const float* Bp0 = B + (size_t)(2 * bk2) * ldb + n0 + bcol;
    const float* Bp1 = Bp0 + ldb;

    int wid = tid >> 5, lane = tid & 31;
    int wm = (wid >> 2) * 64, wn = (wid & 3) * 32;
    int grp = lane >> 2, tig = lane & 3;
    float acc[4][4][4] = {};

    uint32_t asb = (uint32_t)__cvta_generic_to_shared(&As[0][0]);
    uint32_t bsb = (uint32_t)__cvta_generic_to_shared(&Bs[0][0]);
    uint32_t a_off[4], b_off[2];
#pragma unroll
    for (int mi = 0; mi < 4; mi++)
        a_off[mi] = ((wm + mi * 16 + (lane & 15)) * LDW + (lane >> 4) * 4) * 4;
#pragma unroll
    for (int nb = 0; nb < 2; nb++)
        b_off[nb] = ((wn + nb * 16 + (lane & 7) + ((lane >> 4) << 3)) * LDW +
                     ((lane >> 3) & 1) * 4) * 4;

    {
        float4 a0 = *(const float4*)Ap;
        float4 a1 = *(const float4*)(Ap + 4);
        *(uint4*)&As[0][arow * LDW + apart * 4] =
            make_uint4(pkbf(a0.x, a0.y), pkbf(a0.z, a0.w), pkbf(a1.x, a1.y), pkbf(a1.z, a1.w));
        float4 b0 = *(const float4*)Bp0;
        float4 b1 = *(const float4*)Bp1;
        Bs[0][(bcol + 0) * LDW + bk2] = pkbf(b0.x, b1.x);
        Bs[0][(bcol + 1) * LDW + bk2] = pkbf(b0.y, b1.y);
        Bs[0][(bcol + 2) * LDW + bk2] = pkbf(b0.z, b1.z);
        Bs[0][(bcol + 3) * LDW + bk2] = pkbf(b0.w, b1.w);
    }
    __syncthreads();

    int S = K / 16, buf = 0;
    for (int s = 1; s <= S; s++) {
        bool more = (s < S);
        float4 a0, a1, b0, b1;
        if (more) {
            int k0 = s * 16;
            a0 = *(const float4*)(Ap + k0);
            a1 = *(const float4*)(Ap + k0 + 4);
            b0 = *(const float4*)(Bp0 + (size_t)k0 * ldb);
            b1 = *(const float4*)(Bp1 + (size_t)k0 * ldb);
        }
        uint32_t a[4][4], b[4][2];
        uint32_t ab = asb + buf * BUFB, bb = bsb + buf * BUFB;
#pragma unroll
        for (int mi = 0; mi < 4; mi++)
            ldsm4(a[mi][0], a[mi][1], a[mi][2], a[mi][3], ab + a_off[mi]);
#pragma unroll
        for (int nb = 0; nb < 2; nb++) {
            uint32_t r0, r1, r2, r3;
            ldsm4(r0, r1, r2, r3, bb + b_off[nb]);
            b[2 * nb][0] = r0; b[2 * nb][1] = r1;
            b[2 * nb + 1][0] = r2; b[2 * nb + 1][1] = r3;
        }
#pragma unroll
        for (int mi = 0; mi < 4; mi++)
#pragma unroll
            for (int nj = 0; nj < 4; nj++) mma_bf16(acc[mi][nj], a[mi], b[nj]);
        if (more) {
            *(uint4*)&As[buf ^ 1][arow * LDW + apart * 4] =
                make_uint4(pkbf(a0.x, a0.y), pkbf(a0.z, a0.w), pkbf(a1.x, a1.y), pkbf(a1.z, a1.w));
            Bs[buf ^ 1][(bcol + 0) * LDW + bk2] = pkbf(b0.x, b1.x);
            Bs[buf ^ 1][(bcol + 1) * LDW + bk2] = pkbf(b0.y, b1.y);
            Bs[buf ^ 1][(bcol + 2) * LDW + bk2] = pkbf(b0.z, b1.z);
            Bs[buf ^ 1][(bcol + 3) * LDW + bk2] = pkbf(b0.w, b1.w);
            __syncthreads();
            buf ^= 1;
        }
    }

#pragma unroll
    for (int nj = 0; nj < 4; nj++) {
        int c = n0 + wn + nj * 8 + tig * 2;
        float bi0 = bias[c], bi1 = bias[c + 1];
#pragma unroll
        for (int mi = 0; mi < 4; mi++) {
            size_t r = m0 + wm + mi * 16 + grp;
            Cbf[(r * ldc + c) >> 1] = pkbf(acc[mi][nj][0] + bi0, acc[mi][nj][1] + bi1);
            Cbf[((r + 8) * ldc + c) >> 1] = pkbf(acc[mi][nj][2] + bi0, acc[mi][nj][3] + bi1);
        }
    }
}

// ================= proj GEMM: A bf16, B fp32, out fp32 + resid =================
__global__ __launch_bounds__(256)
void mma_proj(const uint32_t* __restrict__ Abf, const float* __restrict__ B,
              const float* __restrict__ bias, const float* __restrict__ resid,
              float* __restrict__ C, int K, int lda, int ldb, int ldc) {
    __shared__ uint32_t As[2][128 * LDW];
    __shared__ uint32_t Bs[2][128 * LDW];
    int tid = threadIdx.x;
    int m0 = blockIdx.y * 128, n0 = blockIdx.x * 128;
    int arow = tid >> 1, apart = tid & 1;
    int bk2 = tid >> 5, bcol = (tid & 31) * 4;
    const uint4* Ap4 = (const uint4*)(Abf + (size_t)(m0 + arow) * (lda / 2)) + apart;
    const float* Bp0 = B + (size_t)(2 * bk2) * ldb + n0 + bcol;
    const float* Bp1 = Bp0 + ldb;

    int wid = tid >> 5, lane = tid & 31;
    int wm = (wid >> 2) * 64, wn = (wid & 3) * 32;
    int grp = lane >> 2, tig = lane & 3;
    float acc[4][4][4] = {};

    uint32_t asb = (uint32_t)__cvta_generic_to_shared(&As[0][0]);
    uint32_t bsb = (uint32_t)__cvta_generic_to_shared(&Bs[0][0]);
    uint32_t a_off[4], b_off[2];
#pragma unroll
    for (int mi = 0; mi < 4; mi++)
        a_off[mi] = ((wm + mi * 16 + (lane & 15)) * LDW + (lane >> 4) * 4) * 4;
#pragma unroll
    for (int nb = 0; nb < 2; nb++)
        b_off[nb] = ((wn + nb * 16 + (lane & 7) + ((lane >> 4) << 3)) * LDW +
                     ((lane >> 3) & 1) * 4) * 4;

    {
        uint4 av = Ap4[0];
        *(uint4*)&As[0][arow * LDW + apart * 4] = av;
        float4 b0 = *(const float4*)Bp0;
        float4 b1 = *(const float4*)Bp1;
        Bs[0][(bcol + 0) * LDW + bk2] = pkbf(b0.x, b1.x);
        Bs[0][(bcol + 1) * LDW + bk2] = pkbf(b0.y, b1.y);
        Bs[0][(bcol + 2) * LDW + bk2] = pkbf(b0.z, b1.z);
        Bs[0][(bcol + 3) * LDW + bk2] = pkbf(b0.w, b1.w);
    }
    __syncthreads();

    int S = K / 16, buf = 0;
    for (int s = 1; s <= S; s++) {
        bool more = (s < S);
        uint4 av;
        float4 b0, b1;
        if (more) {
            av = Ap4[s * 2];
            int k0 = s * 16;
            b0 = *(const float4*)(Bp0 + (size_t)k0 * ldb);
            b1 = *(const float4*)(Bp1 + (size_t)k0 * ldb);
        }
        uint32_t a[4][4], b[4][2];
        uint32_t ab = asb + buf * BUFB, bb = bsb + buf * BUFB;
#pragma unroll
        for (int mi = 0; mi < 4; mi++)
            ldsm4(a[mi][0], a[mi][1], a[mi][2], a[mi][3], ab + a_off[mi]);
#pragma unroll
        for (int nb = 0; nb < 2; nb++) {
            uint32_t r0, r1, r2, r3;
            ldsm4(r0, r1, r2, r3, bb + b_off[nb]);
            b[2 * nb][0] = r0; b[2 * nb][1] = r1;
            b[2 * nb + 1][0] = r2; b[2 * nb + 1][1] = r3;
        }
#pragma unroll
        for (int mi = 0; mi < 4; mi++)
#pragma unroll
            for (int nj = 0; nj < 4; nj++) mma_bf16(acc[mi][nj], a[mi], b[nj]);
        if (more) {
            *(uint4*)&As[buf ^ 1][arow * LDW + apart * 4] = av;
            Bs[buf ^ 1][(bcol + 0) * LDW + bk2] = pkbf(b0.x, b1.x);
            Bs[buf ^ 1][(bcol + 1) * LDW + bk2] = pkbf(b0.y, b1.y);
            Bs[buf ^ 1][(bcol + 2) * LDW + bk2] = pkbf(b0.z, b1.z);
            Bs[buf ^ 1][(bcol + 3) * LDW + bk2] = pkbf(b0.w, b1.w);
            __syncthreads();
            buf ^= 1;
        }
    }

#pragma unroll
    for (int nj = 0; nj < 4; nj++) {
        int c = n0 + wn + nj * 8 + tig * 2;
        float bi0 = bias[c], bi1 = bias[c + 1];
#pragma unroll
        for (int mi = 0; mi < 4; mi++) {
            size_t r = m0 + wm + mi * 16 + grp;
            float2 r0 = *(const float2*)(resid + r * ldc + c);
            float2 r1 = *(const float2*)(resid + (r + 8) * ldc + c);
            *(float2*)(C + r * ldc + c) =
                make_float2(acc[mi][nj][0] + bi0 + r0.x, acc[mi][nj][1] + bi1 + r0.y);
            *(float2*)(C + (r + 8) * ldc + c) =
                make_float2(acc[mi][nj][2] + bi0 + r1.x, acc[mi][nj][3] + bi1 + r1.y);
        }
    }
}

// ================= fused flash attention (bf16 in/out) + gate blend =================
#define LDQ 136
#define LDV 104
#define FLASH_SMEM ((2 * 48 * LDQ + 64 * LDV) * 4)

__global__ __launch_bounds__(256, 1)
void flash_kernel(const uint32_t* __restrict__ qkvbf, const float* __restrict__ qout,
                  const float* __restrict__ fw, uint32_t* __restrict__ fusedbf) {
    extern __shared__ uint32_t smu[];
    uint32_t* Qs = smu;
    uint32_t* Ks = smu + 48 * LDQ;
    uint32_t* Vs = smu + 2 * 48 * LDQ;

    int tid = threadIdx.x;
    int z = blockIdx.y;
    int b = z >> 3, h = z & 7;
    int q0 = blockIdx.x * 128;
    const uint32_t* qb32 = qkvbf + (size_t)b * Nseq * 1152 + h * 48;
    const uint32_t* kb32 = qb32 + 384;
    const uint32_t* vb32 = qb32 + 768;

    int lane = tid & 31, wid = tid >> 5;
    int grp = lane >> 2, tig = lane & 3;
    int wrow = wid * 16;

    for (int i = tid; i < 6144; i += 256) {
        int d2 = i % 48, r = i / 48;
        Qs[d2 * LDQ + r] = qb32[(size_t)(q0 + r) * 1152 + d2];
    }

    float o[12][4] = {};
    float m0 = -1e30f, m1 = -1e30f, l0 = 0.f, l1 = 0.f;
    const float scale = 0.10206207261596577f;

    for (int t = 0; t < 8; t++) {
        __syncthreads();
        int kv0 = t * 128;
        for (int i = tid; i < 6144; i += 256) {
            int d2 = i % 48, r = i / 48;
            Ks[d2 * LDQ + r] = kb32[(size_t)(kv0 + r) * 1152 + d2];
        }
        for (int i = tid; i < 3072; i += 256) {
            int j2 = i / 48, k = i % 48;
            uint32_t u0 = vb32[(size_t)(kv0 + 2 * j2) * 1152 + k];
            uint32_t u1 = vb32[(size_t)(kv0 + 2 * j2 + 1) * 1152 + k];
            Vs[j2 * LDV + 2 * k]     = __byte_perm(u0, u1, 0x5410);
            Vs[j2 * LDV + 2 * k + 1] = __byte_perm(u0, u1, 0x7632);
        }
        __syncthreads();

        float s[16][4] = {};
#pragma unroll
        for (int ks = 0; ks < 6; ks++) {
            uint32_t a[4];
            a[0] = Qs[(ks * 8 + tig) * LDQ + wrow + grp];
            a[1] = Qs[(ks * 8 + tig) * LDQ + wrow + grp + 8];
            a[2] = Qs[(ks * 8 + tig + 4) * LDQ + wrow + grp];
            a[3] = Qs[(ks * 8 + tig + 4) * LDQ + wrow + grp + 8];
#pragma unroll
            for (int n = 0; n < 16; n++) {
                uint32_t bb[2];
                bb[0] = Ks[(ks * 8 + tig) * LDQ + n * 8 + grp];
                bb[1] = Ks[(ks * 8 + tig + 4) * LDQ + n * 8 + grp];
                mma_bf16(s[n], a, bb);
            }
        }

        float mx0 = -1e30f, mx1 = -1e30f;
#pragma unroll
        for (int n = 0; n < 16; n++) {
            mx0 = fmaxf(mx0, fmaxf(s[n][0], s[n][1]));
            mx1 = fmaxf(mx1, fmaxf(s[n][2], s[n][3]));
        }
        mx0 = fmaxf(mx0, __shfl_xor_sync(~0u, mx0, 1));
        mx0 = fmaxf(mx0, __shfl_xor_sync(~0u, mx0, 2));
        mx1 = fmaxf(mx1, __shfl_xor_sync(~0u, mx1, 1));
        mx1 = fmaxf(mx1, __shfl_xor_sync(~0u, mx1, 2));
        float nm0 = fmaxf(m0, mx0 * scale);
        float nm1 = fmaxf(m1, mx1 * scale);
        float al0 = __expf(m0 - nm0), al1 = __expf(m1 - nm1);
        m0 = nm0; m1 = nm1;
        float sum0 = 0.f, sum1 = 0.f;
#pragma unroll
        for (int n = 0; n < 16; n++) {
            float p0 = __expf(s[n][0] * scale - nm0);
            float p1 = __expf(s[n][1] * scale - nm0);
            float p2 = __expf(s[n][2] * scale - nm1);
            float p3 = __expf(s[n][3] * scale - nm1);
            sum0 += p0 + p1; sum1 += p2 + p3;
            s[n][0] = p0; s[n][1] = p1; s[n][2] = p2; s[n][3] = p3;
        }
        sum0 += __shfl_xor_sync(~0u, sum0, 1);
        sum0 += __shfl_xor_sync(~0u, sum0, 2);
        sum1 += __shfl_xor_sync(~0u, sum1, 1);
        sum1 += __shfl_xor_sync(~0u, sum1, 2);
        l0 = l0 * al0 + sum0;
        l1 = l1 * al1 + sum1;
#pragma unroll
        for (int n = 0; n < 12; n++) {
            o[n][0] *= al0; o[n][1] *= al0;
            o[n][2] *= al1; o[n][3] *= al1;
        }

#pragma unroll
        for (int jb = 0; jb < 8; jb++) {
            uint32_t a[4];
            a[0] = pkbf(s[2 * jb][0], s[2 * jb][1]);
            a[1] = pkbf(s[2 * jb][2], s[2 * jb][3]);
            a[2] = pkbf(s[2 * jb + 1][0], s[2 * jb + 1][1]);
            a[3] = pkbf(s[2 * jb + 1][2], s[2 * jb + 1][3]);
#pragma unroll
            for (int n = 0; n < 12; n++) {
                uint32_t bb[2];
                bb[0] = Vs[(jb * 8 + tig) * LDV + n * 8 + grp];
                bb[1] = Vs[(jb * 8 + tig + 4) * LDV + n * 8 + grp];
                mma_bf16(o[n], a, bb);
            }
        }
    }

    float inv0 = 1.f / l0, inv1 = 1.f / l1;
    int row0 = q0 + wrow + grp;
#pragma unroll
    for (int n = 0; n < 12; n++) {
        int c = n * 8 + tig * 2;
        float f0 = fw[b * Cdim + h * Dd + c];
        float f1 = fw[b * Cdim + h * Dd + c + 1];
        size_t ob0 = ((size_t)b * Nseq + row0) * Cdim + h * Dd + c;
        size_t ob1 = ((size_t)b * Nseq + row0 + 8) * Cdim + h * Dd + c;
        float2 qv0 = *(const float2*)(qout + ob0);
        float2 qv1 = *(const float2*)(qout + ob1);
        fusedbf[ob0 >> 1] = pkbf(f0 * qv0.x + (1.f - f0) * o[n][0] * inv0,
                                 f1 * qv0.y + (1.f - f1) * o[n][1] * inv0);
        fusedbf[ob1 >> 1] = pkbf(f0 * qv1.x + (1.f - f0) * o[n][2] * inv1,
                                 f1 * qv1.y + (1.f - f1) * o[n][3] * inv1);
    }
}

// ================= quantum embed GEMM (bf16 A): H = relu(A @ W1 + b1) =================
__global__ __launch_bounds__(256)
void embed_gemm(const uint32_t* __restrict__ qkvbf,
                const float* __restrict__ qW1, const float* __restrict__ qb1,
                const float* __restrict__ kW1, const float* __restrict__ kb1,
                float* __restrict__ Hq, float* __restrict__ Hk) {
    __shared__ uint32_t As[2][8][136];
    __shared__ uint32_t Bs[48][72];
    int tid = threadIdx.x;
    int m0 = blockIdx.x * 128;
    int pass = blockIdx.y;
    const float* W1 = pass ? kW1 : qW1;
    const float* b1 = pass ? kb1 : qb1;
    float* H = pass ? Hk : Hq;
    int qk_off32 = pass * 384;

    for (int i = tid; i < 768; i += 256) {
        int k2 = i >> 4, c4 = i & 15;
        float4 w0 = *(const float4*)(W1 + (2 * k2) * 64 + c4 * 4);
        float4 w1 = *(const float4*)(W1 + (2 * k2 + 1) * 64 + c4 * 4);
        *(uint4*)&Bs[k2][c4 * 4] = make_uint4(pkbf(w0.x, w1.x), pkbf(w0.y, w1.y),
                                              pkbf(w0.z, w1.z), pkbf(w0.w, w1.w));
    }

    int arow = tid >> 1, apart = tid & 1;
    int mrow = m0 + arow;
    const uint4* Ap4 = (const uint4*)(qkvbf + (size_t)(mrow >> 3) * 1152 + qk_off32 + (mrow & 7) * 48);

    int wid = tid >> 5, lane = tid & 31;
    int wm = (wid >> 2) * 64, wn = (wid & 3) * 16;
    int grp = lane >> 2, tig = lane & 3;
    float acc[4][2][4] = {};

    {
        uint4 av = Ap4[apart];
        As[0][apart * 4 + 0][arow] = av.x;
        As[0][apart * 4 + 1][arow] = av.y;
        As[0][apart * 4 + 2][arow] = av.z;
        As[0][apart * 4 + 3][arow] = av.w;
    }
    __syncthreads();

    int buf = 0;
    for (int s = 1; s <= 6; s++) {
        bool more = (s < 6);
        uint4 av;
        if (more) av = Ap4[s * 2 + apart];
        int kb = (s - 1) * 8;
        uint32_t a[4][4], b[2][2];
#pragma unroll
        for (int mi = 0; mi < 4; mi++) {
            int r = wm + mi * 16 + grp;
            a[mi][0] = As[buf][tig][r];
            a[mi][1] = As[buf][tig][r + 8];
            a[mi][2] = As[buf][tig + 4][r];
            a[mi][3] = As[buf][tig + 4][r + 8];
        }
#pragma unroll
        for (int nj = 0; nj < 2; nj++) {
            int c = wn + nj * 8 + grp;
            b[nj][0] = Bs[kb + tig][c];
            b[nj][1] = Bs[kb + tig + 4][c];
        }
#pragma unroll
        for (int mi = 0; mi < 4; mi++)
#pragma unroll
            for (int nj = 0; nj < 2; nj++) mma_bf16(acc[mi][nj], a[mi], b[nj]);
        if (more) {
            As[buf ^ 1][apart * 4 + 0][arow] = av.x;
            As[buf ^ 1][apart * 4 + 1][arow] = av.y;
            As[buf ^ 1][apart * 4 + 2][arow] = av.z;
            As[buf ^ 1][apart * 4 + 3][arow] = av.w;
            __syncthreads();
            buf ^= 1;
        }
    }

#pragma unroll
    for (int nj = 0; nj < 2; nj++) {
        int c = wn + nj * 8 + tig * 2;
        float bi0 = __ldg(&b1[c]), bi1 = __ldg(&b1[c + 1]);
#pragma unroll
        for (int mi = 0; mi < 4; mi++) {
            size_t r = m0 + wm + mi * 16 + grp;
            *(float2*)(H + r * 64 + c) =
                make_float2(fmaxf(acc[mi][nj][0] + bi0, 0.f), fmaxf(acc[mi][nj][1] + bi1, 0.f));
            *(float2*)(H + (r + 8) * 64 + c) =
                make_float2(fmaxf(acc[mi][nj][2] + bi0, 0.f), fmaxf(acc[mi][nj][3] + bi1, 0.f));
        }
    }
}

// ================= quantum middle: e -> state -> meas =================
__global__ __launch_bounds__(128)
void quantum_mid(const float* __restrict__ Hq, const float* __restrict__ Hk,
                 const float* __restrict__ qe_w2, const float* __restrict__ qe_b2,
                 const float* __restrict__ ke_w2, const float* __restrict__ ke_b2,
                 const float* __restrict__ gate_params, const float* __restrict__ ent_params,
                 const float* __restrict__ gumbel, float* __restrict__ meas_out) {
    __shared__ float w2q[1024], w2k[1024];
    __shared__ float gf[2][8], gcz[2][8], gsz[2][8], gs[2][8];
    int tid = threadIdx.x;
    for (int i = tid; i < 256; i += 128) {
        ((float4*)w2q)[i] = ((const float4*)qe_w2)[i];
        ((float4*)w2k)[i] = ((const float4*)ke_w2)[i];
    }
    if (tid < 16) {
        int l = tid >> 3, i = tid & 7;
        float ry = gate_params[(l * 8 + i) * 3 + 1];
        float rz = gate_params[(l * 8 + i) * 3 + 2];
        gf[l][i] = cosf(0.5f * ry);
        gcz[l][i] = cosf(rz);
        gsz[l][i] = sinf(rz);
    } else if (tid < 30) {
        int t = tid - 16, l = t / 7, i = t % 7;
        gs[l][i + 1] = 1.f / (1.f + expf(-ent_params[l * 7 + i]));
    }
    __syncthreads();

    int m = blockIdx.x * 128 + tid;
    float sre[8], sim[8];

#pragma unroll
    for (int pass = 0; pass < 2; pass++) {
        const float* Hrow = (pass == 0 ? Hq : Hk) + (size_t)m * 64;
        const float* w2 = (pass == 0 ? w2q : w2k);
        const float* b2 = (pass == 0 ? qe_b2 : ke_b2);
        float e[16];
#pragma unroll
        for (int i = 0; i < 16; i++) e[i] = __ldg(&b2[i]);
        const float4* h4 = (const float4*)Hrow;
#pragma unroll
        for (int j4 = 0; j4 < 16; j4++) {
            float4 hv = h4[j4];
            float hs[4] = {hv.x, hv.y, hv.z, hv.w};
#pragma unroll
            for (int s = 0; s < 4; s++) {
                float hj = hs[s];
                const float4* wr = (const float4*)&w2[(j4 * 4 + s) * 16];
#pragma unroll
                for (int i4 = 0; i4 < 4; i4++) {
                    float4 w = wr[i4];
                    e[i4 * 4 + 0] += hj * w.x; e[i4 * 4 + 1] += hj * w.y;
                    e[i4 * 4 + 2] += hj * w.z; e[i4 * 4 + 3] += hj * w.w;
                }
            }
        }
        float mx = e[0];
#pragma unroll
        for (int i = 1; i < 8; i++) mx = fmaxf(mx, e[i]);
        float ex[8], ssum = 0.f;
#pragma unroll
        for (int i = 0; i < 8; i++) { ex[i] = __expf(e[i] - mx); ssum += ex[i]; }
        float inv = 1.f / ssum;
#pragma unroll
        for (int i = 0; i < 8; i++) {
            float amp = ex[i] * inv;
            float cr = amp * __cosf(e[8 + i]), ci = amp * __sinf(e[8 + i]);
            if (pass == 0) { sre[i] = cr; sim[i] = ci; }
            else           { sre[i] += cr; sim[i] += ci; }
        }
    }

#pragma unroll
    for (int l = 0; l < 2; l++) {
#pragma unroll
        for (int i = 0; i < 8; i++) {
            float nr = sre[i] * gcz[l][i] - sim[i] * gsz[l][i];
            float ni = sre[i] * gsz[l][i] + sim[i] * gcz[l][i];
            sre[i] = nr * gf[l][i];
            sim[i] = ni * gf[l][i];
        }
#pragma unroll
        for (int i = 7; i >= 1; i--) {
            sre[i] += gs[l][i] * sre[i - 1];
            sim[i] += gs[l][i] * sim[i - 1];
        }
    }

    float p[8], mx = -1e30f;
#pragma unroll
    for (int i = 0; i < 8; i++) { p[i] = sre[i] * sre[i] + sim[i] * sim[i]; mx = fmaxf(mx, p[i]); }
    float ssum = 0.f;
#pragma unroll
    for (int i = 0; i < 8; i++) { p[i] = __expf(p[i] - mx); ssum += p[i]; }
    float sinv = 1.f / ssum;
    int b = m >> 13, n = (m >> 3) & 1023, h = m & 7;
    size_t goff = (size_t)(((b * 8 + h) << 10) + n) * 8;
    float4 g0 = __ldg((const float4*)(gumbel + goff));
    float4 g1 = __ldg((const float4*)(gumbel + goff + 4));
    float gv[8] = {g0.x, g0.y, g0.z, g0.w, g1.x, g1.y, g1.z, g1.w};
    float lg[8], mx2 = -1e30f;
#pragma unroll
    for (int i = 0; i < 8; i++) {
        lg[i] = 2.f * (__logf(p[i] * sinv + 1e-10f) + gv[i]);
        mx2 = fmaxf(mx2, lg[i]);
    }
    float meas[8], msum = 0.f;
#pragma unroll
    for (int i = 0; i < 8; i++) { meas[i] = __expf(lg[i] - mx2); msum += meas[i]; }
    float minv = 1.f / msum;
    float4 o0 = make_float4(meas[0] * minv, meas[1] * minv, meas[2] * minv, meas[3] * minv);
    float4 o1 = make_float4(meas[4] * minv, meas[5] * minv, meas[6] * minv, meas[7] * minv);
    *(float4*)(meas_out + (size_t)m * 8) = o0;
    *(float4*)(meas_out + (size_t)m * 8 + 4) = o1;
}

// ================= fused measure MLP (tf32): qout = (relu(meas@W1+b1)@W2+b2)*v =================
#define MD_T1_LD 136
#define MD_W2_LD 104
#define MD_SMEM ((8 * 136 + 8 * 72 + 64 * MD_T1_LD + 64 * MD_W2_LD) * 4)

__global__ __launch_bounds__(256)
void md_fused(const float* __restrict__ meas,
              const float* __restrict__ W1, const float* __restrict__ b1,
              const float* __restrict__ W2, const float* __restrict__ b2,
              const uint32_t* __restrict__ qkvbf, float* __restrict__ qout) {
    extern __shared__ float sm[];
    float* As8 = sm;
    float* W1s = sm + 8 * 136;
    float* T1  = sm + 8 * 136 + 8 * 72;
    float* W2s = T1 + 64 * MD_T1_LD;

    int tid = threadIdx.x;
    int m0 = blockIdx.x * 128;
    int wid = tid >> 5, lane = tid & 31;
    int grp = lane >> 2, tig = lane & 3;
    int wm = (wid >> 2) * 64;

    {
        int arow = tid >> 1, ak = (tid & 1) * 4;
        float4 v = *(const float4*)(meas + (size_t)(m0 + arow) * 8 + ak);
        As8[(ak + 0) * 136 + arow] = to_tf32(v.x);
        As8[(ak + 1) * 136 + arow] = to_tf32(v.y);
        As8[(ak + 2) * 136 + arow] = to_tf32(v.z);
        As8[(ak + 3) * 136 + arow] = to_tf32(v.w);
    }
    for (int i = tid; i < 128; i += 256) {
        int d = i >> 4, n4 = i & 15;
        float4 w = ((const float4*)W1)[i];
        float4 wc = make_float4(to_tf32(w.x), to_tf32(w.y), to_tf32(w.z), to_tf32(w.w));
        *(float4*)&W1s[d * 72 + n4 * 4] = wc;
    }
    for (int i = tid; i < 1536; i += 256) {
        int d = i / 24, n4 = i % 24;
        float4 w = ((const float4*)W2)[i];
        float4 wc = make_float4(to_tf32(w.x), to_tf32(w.y), to_tf32(w.z), to_tf32(w.w));
        *(float4*)&W2s[d * MD_W2_LD + n4 * 4] = wc;
    }
    __syncthreads();

    {
        int wn1 = (wid & 3) * 16;
        float acc1[4][2][4] = {};
        uint32_t a[4][4], b[2][2];
#pragma unroll
        for (int mi = 0; mi < 4; mi++) {
            int r = wm + mi * 16 + grp;
            a[mi][0] = __float_as_uint(As8[tig * 136 + r]);
            a[mi][1] = __float_as_uint(As8[tig * 136 + r + 8]);
            a[mi][2] = __float_as_uint(As8[(tig + 4) * 136 + r]);
            a[mi][3] = __float_as_uint(As8[(tig + 4) * 136 + r + 8]);
        }
#pragma unroll
        for (int nj = 0; nj < 2; nj++) {
            int c = wn1 + nj * 8 + grp;
            b[nj][0] = __float_as_uint(W1s[tig * 72 + c]);
            b[nj][1] = __float_as_uint(W1s[(tig + 4) * 72 + c]);
        }
#pragma unroll
        for (int mi = 0; mi < 4; mi++)
#pragma unroll
            for (int nj = 0; nj < 2; nj++) mma_tf32(acc1[mi][nj], a[mi], b[nj]);

#pragma unroll
        for (int nj = 0; nj < 2; nj++) {
            int c = wn1 + nj * 8 + tig * 2;
            float bi0 = __ldg(&b1[c]), bi1 = __ldg(&b1[c + 1]);
#pragma unroll
            for (int mi = 0; mi < 4; mi++) {
                int r = wm + mi * 16 + grp;
                T1[c * MD_T1_LD + r]           = to_tf32(fmaxf(acc1[mi][nj][0] + bi0, 0.f));
                T1[(c + 1) * MD_T1_LD + r]     = to_tf32(fmaxf(acc1[mi][nj][1] + bi1, 0.f));
                T1[c * MD_T1_LD + r + 8]       = to_tf32(fmaxf(acc1[mi][nj][2] + bi0, 0.f));
                T1[(c + 1) * MD_T1_LD + r + 8] = to_tf32(fmaxf(acc1[mi][nj][3] + bi1, 0.f));
            }
        }
    }
    __syncthreads();

    int wn = (wid & 3) * 24;
    float acc2[4][3][4] = {};
#pragma unroll
    for (int ks = 0; ks < 8; ks++) {
        uint32_t a[4][4], b[3][2];
#pragma unroll
        for (int mi = 0; mi < 4; mi++) {
            int r = wm + mi * 16 + grp;
            a[mi][0] = __float_as_uint(T1[(ks * 8 + tig) * MD_T1_LD + r]);
            a[mi][1] = __float_as_uint(T1[(ks * 8 + tig) * MD_T1_LD + r + 8]);
            a[mi][2] = __float_as_uint(T1[(ks * 8 + tig + 4) * MD_T1_LD + r]);
            a[mi][3] = __float_as_uint(T1[(ks * 8 + tig + 4) * MD_T1_LD + r + 8]);
        }
#pragma unroll
        for (int nj = 0; nj < 3; nj++) {
            int c = wn + nj * 8 + grp;
            b[nj][0] = __float_as_uint(W2s[(ks * 8 + tig) * MD_W2_LD + c]);
            b[nj][1] = __float_as_uint(W2s[(ks * 8 + tig + 4) * MD_W2_LD + c]);
        }
#pragma unroll
        for (int mi = 0; mi < 4; mi++)
#pragma unroll
            for (int nj = 0; nj < 3; nj++) mma_tf32(acc2[mi][nj], a[mi], b[nj]);
    }

#pragma unroll
    for (int nj = 0; nj < 3; nj++) {
        int c = wn + nj * 8 + tig * 2;
        float bi0 = __ldg(&b2[c]), bi1 = __ldg(&b2[c + 1]);
#pragma unroll
        for (int mi = 0; mi < 4; mi++) {
            int m = m0 + wm + mi * 16 + grp;
#pragma unroll
            for (int half = 0; half < 2; half++) {
                int mm = m + half * 8;
                size_t qrow = (size_t)(mm >> 3);
                int hh = mm & 7;
                uint32_t u = qkvbf[(qrow * 2304 + 1536 + hh * 96 + c) >> 1];
                float2 vv = __bfloat1622float2(*(__nv_bfloat162*)&u);
                float o0 = (acc2[mi][nj][half * 2 + 0] + bi0) * vv.x;
                float o1 = (acc2[mi][nj][half * 2 + 1] + bi1) * vv.y;
                *(float2*)(qout + qrow * 768 + hh * 96 + c) = make_float2(o0, o1);
            }
        }
    }
}

// ================= mean over N =================
__global__ void colmean_kernel(const float* __restrict__ x, float* __restrict__ xmean) {
    int b = blockIdx.y;
    int c = blockIdx.x * 256 + threadIdx.x;
    const float* p = x + (size_t)b * Nseq * Cdim + c;
    float s = 0.f;
    for (int n = 0; n < Nseq; n++) s += p[(size_t)n * Cdim];
    xmean[b * Cdim + c] = s * (1.0f / 1024.0f);
}

// ================= fw = sigmoid(xmean @ w_proj + b_proj) =================
__global__ void fw_kernel(const float* __restrict__ xmean, const float* __restrict__ w_proj,
                          const float* __restrict__ b_proj, float* __restrict__ fw) {
    __shared__ float xm[768];
    int b = blockIdx.x;
    int c = threadIdx.x;
    xm[c] = xmean[b * Cdim + c];
    __syncthreads();
    float s = b_proj[c];
    for (int k = 0; k < 768; k++) s += xm[k] * w_proj[(size_t)k * 768 + c];
    fw[b * Cdim + c] = 1.f / (1.f + expf(-s));
}

// ================= layernorm =================
__global__ void layernorm_kernel(const float* __restrict__ y, const float* __restrict__ gamma,
                                 const float* __restrict__ beta, float* __restrict__ out) {
    __shared__ float red1[8], red2[8];
    size_t row = blockIdx.x;
    const float* p = y + row * Cdim;
    int tid = threadIdx.x;
    float v[3];
    float s = 0.f;
#pragma unroll
    for (int i = 0; i < 3; i++) { v[i] = p[tid + i * 256]; s += v[i]; }
#pragma unroll
    for (int o = 16; o > 0; o >>= 1) s += __shfl_xor_sync(~0u, s, o);
    int w = tid >> 5, lane = tid & 31;
    if (lane == 0) red1[w] = s;
    __syncthreads();
    s = 0.f;
#pragma unroll
    for (int i = 0; i < 8; i++) s += red1[i];
    float mu = s * (1.0f / 768.0f);
    float vs = 0.f;
#pragma unroll
    for (int i = 0; i < 3; i++) { float d = v[i] - mu; vs += d * d; }
#pragma unroll
    for (int o = 16; o > 0; o >>= 1) vs += __shfl_xor_sync(~0u, vs, o);
    if (lane == 0) red2[w] = vs;
    __syncthreads();
    vs = 0.f;
#pragma unroll
    for (int i = 0; i < 8; i++) vs += red2[i];
    float inv = rsqrtf(vs * (1.0f / 768.0f) + 1e-5f);
#pragma unroll
    for (int i = 0; i < 3; i++) {
        int c = tid + i * 256;
        out[row * Cdim + c] = (v[i] - mu) * inv * gamma[c] + beta[c];
    }
}

// ================= launch =================
extern "C" void kernel_launch(void* const* d_in, const int* in_sizes, int n_in,
                              void* d_out, int out_size) {
    const float* x      = (const float*)d_in[0];
    const float* w_qkv  = (const float*)d_in[1];
    const float* b_qkv  = (const float*)d_in[2];
    const float* w_proj = (const float*)d_in[3];
    const float* b_proj = (const float*)d_in[4];
    const float* gamma  = (const float*)d_in[5];
    const float* beta   = (const float*)d_in[6];
    const float* qe_w1  = (const float*)d_in[7];
    const float* qe_b1  = (const float*)d_in[8];
    const float* qe_w2  = (const float*)d_in[9];
    const float* qe_b2  = (const float*)d_in[10];
    const float* ke_w1  = (const float*)d_in[11];
    const float* ke_b1  = (const float*)d_in[12];
    const float* ke_w2  = (const float*)d_in[13];
    const float* ke_b2  = (const float*)d_in[14];
    const float* gate_params = (const float*)d_in[19];
    const float* ent_params  = (const float*)d_in[20];
    const float* md_w1  = (const float*)d_in[21];
    const float* md_b1  = (const float*)d_in[22];
    const float* md_w2  = (const float*)d_in[23];
    const float* md_b2  = (const float*)d_in[24];
    const float* gumbel = (const float*)d_in[25];
    float* out = (float*)d_out;

    uint32_t *qkvbf, *fusedbf;
    float *qout, *y, *xmean, *fw, *hq, *hk, *meas;
    cudaGetSymbolAddress((void**)&qkvbf, g_qkv_bf);
    cudaGetSymbolAddress((void**)&fusedbf, g_fused_bf);
    cudaGetSymbolAddress((void**)&qout, g_qout);
    cudaGetSymbolAddress((void**)&y, g_y);
    cudaGetSymbolAddress((void**)&xmean, g_xmean);
    cudaGetSymbolAddress((void**)&fw, g_fw);
    cudaGetSymbolAddress((void**)&hq, g_hq);
    cudaGetSymbolAddress((void**)&hk, g_hk);
    cudaGetSymbolAddress((void**)&meas, g_meas);

    cudaFuncSetAttribute(flash_kernel, cudaFuncAttributeMaxDynamicSharedMemorySize, FLASH_SMEM);
    cudaFuncSetAttribute(md_fused, cudaFuncAttributeMaxDynamicSharedMemorySize, MD_SMEM);

    // gate path (depends only on x)
    colmean_kernel<<<dim3(3, 8), 256>>>(x, xmean);
    fw_kernel<<<8, 768>>>(xmean, w_proj, b_proj, fw);
    // qkv = x @ w_qkv + b_qkv  -> bf16
    mma_qkv<<<dim3(2304 / 128, 8192 / 128), 256>>>(x, w_qkv, b_qkv, qkvbf,
                                                   768, 768, 2304, 2304);
    // quantum path: embeds (GEMM) -> mid -> measure MLP (GEMM) -> qout
    embed_gemm<<<dim3(NTOK / 128, 2), 256>>>(qkvbf, qe_w1, qe_b1, ke_w1, ke_b1, hq, hk);
    quantum_mid<<<NTOK / 128, 128>>>(hq, hk, qe_w2, qe_b2, ke_w2, ke_b2,
                                     gate_params, ent_params, gumbel, meas);
    md_fused<<<NTOK / 128, 256, MD_SMEM>>>(meas, md_w1, md_b1, md_w2, md_b2, qkvbf, qout);
    // fused classical attention + gate blend -> fused (bf16)
    flash_kernel<<<dim3(8, 64), 256, FLASH_SMEM>>>(qkvbf, qout, fw, fusedbf);
    // y = x + fused @ w_proj + b_proj
    mma_proj<<<dim3(768 / 128, 8192 / 128), 256>>>(fusedbf, w_proj, b_proj, x, y,
                                                   768, 768, 768, 768);
    // layernorm
    layernorm_kernel<<<8192, 256>>>(y, gamma, beta, out);
}

// round 10
// speedup vs baseline: 1.1748x; 1.1748x over previous
#include <cuda_runtime.h>
#include <cuda_bf16.h>
#include <math.h>
#include <stdint.h>

// ---------------- scratch ----------------
#define Bsz 8
#define Nseq 1024
#define Cdim 768
#define Hh 8
#define Dd 96
#define Qq 8
#define NTOK (Bsz * Hh * Nseq)   // 65536, ordered m=(b,n,h)

__device__ uint32_t g_qkv_bf[Bsz * Nseq * 3 * Cdim / 2];   // bf16x2
__device__ uint32_t g_fused_bf[Bsz * Nseq * Cdim / 2];     // bf16x2
__device__ float g_qout[Bsz * Nseq * Cdim];
__device__ float g_y[Bsz * Nseq * Cdim];
__device__ float g_xmean[Bsz * Cdim];
__device__ float g_fw[Bsz * Cdim];
__device__ float g_hq[NTOK * 64];
__device__ float g_hk[NTOK * 64];
__device__ float g_meas[NTOK * 8];

// ---------------- mma helpers ----------------
__device__ __forceinline__ float to_tf32(float x) {
    uint32_t u;
    asm("cvt.rna.tf32.f32 %0, %1;" : "=r"(u) : "f"(x));
    return __uint_as_float(u);
}

__device__ __forceinline__ uint32_t pkbf(float x, float y) {
    __nv_bfloat162 t = __floats2bfloat162_rn(x, y);
    return *(uint32_t*)&t;
}

__device__ __forceinline__ void mma_tf32(float* c, const uint32_t* a, const uint32_t* b) {
    asm volatile(
        "mma.sync.aligned.m16n8k8.row.col.f32.tf32.tf32.f32 "
        "{%0,%1,%2,%3}, {%4,%5,%6,%7}, {%8,%9}, {%0,%1,%2,%3};"
        : "+f"(c[0]), "+f"(c[1]), "+f"(c[2]), "+f"(c[3])
        : "r"(a[0]), "r"(a[1]), "r"(a[2]), "r"(a[3]), "r"(b[0]), "r"(b[1]));
}

__device__ __forceinline__ void mma_bf16(float* c, const uint32_t* a, const uint32_t* b) {
    asm volatile(
        "mma.sync.aligned.m16n8k16.row.col.f32.bf16.bf16.f32 "
        "{%0,%1,%2,%3}, {%4,%5,%6,%7}, {%8,%9}, {%0,%1,%2,%3};"
        : "+f"(c[0]), "+f"(c[1]), "+f"(c[2]), "+f"(c[3])
        : "r"(a[0]), "r"(a[1]), "r"(a[2]), "r"(a[3]), "r"(b[0]), "r"(b[1]));
}

__device__ __forceinline__ void ldsm4(uint32_t& r0, uint32_t& r1, uint32_t& r2, uint32_t& r3,
                                      uint32_t addr) {
    asm volatile("ldmatrix.sync.aligned.m8n8.x4.shared.b16 {%0,%1,%2,%3}, [%4];"
                 : "=r"(r0), "=r"(r1), "=r"(r2), "=r"(r3) : "r"(addr));
}

// XOR-swizzled tile: [128 rows][8 u32]; 16B group "part" swapped on (row>>2)&1.
// Conflict-free for STS.128 staging and ldmatrix reads (see analysis).
#define SWZ(row, part) ((row) * 8 + (((part) ^ (((row) >> 2) & 1)) * 4))
#define TILE_U32 (128 * 8)
#define TILE_B (TILE_U32 * 4)

// ================= qkv GEMM: A fp32, B fp32, out bf16 =================
__global__ __launch_bounds__(256)
void mma_qkv(const float* __restrict__ A, const float* __restrict__ B,
             const float* __restrict__ bias, uint32_t* __restrict__ Cbf,
             int K, int lda, int ldb, int ldc) {
    __shared__ uint32_t As[2][TILE_U32];
    __shared__ uint32_t Bs[2][TILE_U32];
    int tid = threadIdx.x;
    int m0 = blockIdx.y * 128, n0 = blockIdx.x * 128;
    // A staging: row = tid>>1 (0..127), part = tid&1
    int arow = tid >> 1, apart = tid & 1;
    const float* Ap = A + (size_t)(m0 + arow) * lda + apart * 8;
    uint32_t a_st = SWZ(arow, apart);
    // B staging: col = tid&127, part = tid>>7 ; 8 k-rows per part
    int bcol = tid & 127, bpart = tid >> 7;
    const float* Bp = B + (size_t)(bpart * 8) * ldb + n0 + bcol;
    uint32_t b_st = SWZ(bcol, bpart);

    int wid = tid >> 5, lane = tid & 31;
    int wm = (wid >> 2) * 64, wn = (wid & 3) * 32;
    int grp = lane >> 2, tig = lane & 3;
    float acc[4][4][4] = {};

    uint32_t asb = (uint32_t)__cvta_generic_to_shared(&As[0][0]);
    uint32_t bsb = (uint32_t)__cvta_generic_to_shared(&Bs[0][0]);
    uint32_t a_off[4], b_off[2];
#pragma unroll
    for (int mi = 0; mi < 4; mi++) {
        int r = wm + mi * 16 + (lane & 15);
        a_off[mi] = SWZ(r, lane >> 4) * 4;
    }
#pragma unroll
    for (int nb = 0; nb < 2; nb++) {
        int r = wn + nb * 16 + (lane & 7) + ((lane >> 4) << 3);
        b_off[nb] = SWZ(r, (lane >> 3) & 1) * 4;
    }

    {
        float4 a0 = *(const float4*)Ap;
        float4 a1 = *(const float4*)(Ap + 4);
        *(uint4*)&As[0][a_st] =
            make_uint4(pkbf(a0.x, a0.y), pkbf(a0.z, a0.w), pkbf(a1.x, a1.y), pkbf(a1.z, a1.w));
        float bv[8];
#pragma unroll
        for (int j = 0; j < 8; j++) bv[j] = Bp[(size_t)j * ldb];
        *(uint4*)&Bs[0][b_st] =
            make_uint4(pkbf(bv[0], bv[1]), pkbf(bv[2], bv[3]), pkbf(bv[4], bv[5]), pkbf(bv[6], bv[7]));
    }
    __syncthreads();

    int S = K / 16, buf = 0;
    for (int s = 1; s <= S; s++) {
        bool more = (s < S);
        float4 a0, a1;
        float bv[8];
        if (more) {
            int k0 = s * 16;
            a0 = *(const float4*)(Ap + k0);
            a1 = *(const float4*)(Ap + k0 + 4);
#pragma unroll
            for (int j = 0; j < 8; j++) bv[j] = Bp[(size_t)(k0 + j) * ldb];
        }
        uint32_t a[4][4], b[4][2];
        uint32_t ab = asb + buf * TILE_B, bb = bsb + buf * TILE_B;
#pragma unroll
        for (int mi = 0; mi < 4; mi++)
            ldsm4(a[mi][0], a[mi][1], a[mi][2], a[mi][3], ab + a_off[mi]);
#pragma unroll
        for (int nb = 0; nb < 2; nb++) {
            uint32_t r0, r1, r2, r3;
            ldsm4(r0, r1, r2, r3, bb + b_off[nb]);
            b[2 * nb][0] = r0; b[2 * nb][1] = r1;
            b[2 * nb + 1][0] = r2; b[2 * nb + 1][1] = r3;
        }
#pragma unroll
        for (int mi = 0; mi < 4; mi++)
#pragma unroll
            for (int nj = 0; nj < 4; nj++) mma_bf16(acc[mi][nj], a[mi], b[nj]);
        if (more) {
            *(uint4*)&As[buf ^ 1][a_st] =
                make_uint4(pkbf(a0.x, a0.y), pkbf(a0.z, a0.w), pkbf(a1.x, a1.y), pkbf(a1.z, a1.w));
            *(uint4*)&Bs[buf ^ 1][b_st] =
                make_uint4(pkbf(bv[0], bv[1]), pkbf(bv[2], bv[3]), pkbf(bv[4], bv[5]), pkbf(bv[6], bv[7]));
            __syncthreads();
            buf ^= 1;
        }
    }

#pragma unroll
    for (int nj = 0; nj < 4; nj++) {
        int c = n0 + wn + nj * 8 + tig * 2;
        float bi0 = bias[c], bi1 = bias[c + 1];
#pragma unroll
        for (int mi = 0; mi < 4; mi++) {
            size_t r = m0 + wm + mi * 16 + grp;
            Cbf[(r * ldc + c) >> 1] = pkbf(acc[mi][nj][0] + bi0, acc[mi][nj][1] + bi1);
            Cbf[((r + 8) * ldc + c) >> 1] = pkbf(acc[mi][nj][2] + bi0, acc[mi][nj][3] + bi1);
        }
    }
}

// ================= proj GEMM: A bf16, B fp32, out fp32 + resid =================
__global__ __launch_bounds__(256)
void mma_proj(const uint32_t* __restrict__ Abf, const float* __restrict__ B,
              const float* __restrict__ bias, const float* __restrict__ resid,
              float* __restrict__ C, int K, int lda, int ldb, int ldc) {
    __shared__ uint32_t As[2][TILE_U32];
    __shared__ uint32_t Bs[2][TILE_U32];
    int tid = threadIdx.x;
    int m0 = blockIdx.y * 128, n0 = blockIdx.x * 128;
    int arow = tid >> 1, apart = tid & 1;
    const uint4* Ap4 = (const uint4*)(Abf + (size_t)(m0 + arow) * (lda / 2)) + apart;
    uint32_t a_st = SWZ(arow, apart);
    int bcol = tid & 127, bpart = tid >> 7;
    const float* Bp = B + (size_t)(bpart * 8) * ldb + n0 + bcol;
    uint32_t b_st = SWZ(bcol, bpart);

    int wid = tid >> 5, lane = tid & 31;
    int wm = (wid >> 2) * 64, wn = (wid & 3) * 32;
    int grp = lane >> 2, tig = lane & 3;
    float acc[4][4][4] = {};

    uint32_t asb = (uint32_t)__cvta_generic_to_shared(&As[0][0]);
    uint32_t bsb = (uint32_t)__cvta_generic_to_shared(&Bs[0][0]);
    uint32_t a_off[4], b_off[2];
#pragma unroll
    for (int mi = 0; mi < 4; mi++) {
        int r = wm + mi * 16 + (lane & 15);
        a_off[mi] = SWZ(r, lane >> 4) * 4;
    }
#pragma unroll
    for (int nb = 0; nb < 2; nb++) {
        int r = wn + nb * 16 + (lane & 7) + ((lane >> 4) << 3);
        b_off[nb] = SWZ(r, (lane >> 3) & 1) * 4;
    }

    {
        *(uint4*)&As[0][a_st] = Ap4[0];
        float bv[8];
#pragma unroll
        for (int j = 0; j < 8; j++) bv[j] = Bp[(size_t)j * ldb];
        *(uint4*)&Bs[0][b_st] =
            make_uint4(pkbf(bv[0], bv[1]), pkbf(bv[2], bv[3]), pkbf(bv[4], bv[5]), pkbf(bv[6], bv[7]));
    }
    __syncthreads();

    int S = K / 16, buf = 0;
    for (int s = 1; s <= S; s++) {
        bool more = (s < S);
        uint4 av;
        float bv[8];
        if (more) {
            av = Ap4[s * 2];
            int k0 = s * 16;
#pragma unroll
            for (int j = 0; j < 8; j++) bv[j] = Bp[(size_t)(k0 + j) * ldb];
        }
        uint32_t a[4][4], b[4][2];
        uint32_t ab = asb + buf * TILE_B, bb = bsb + buf * TILE_B;
#pragma unroll
        for (int mi = 0; mi < 4; mi++)
            ldsm4(a[mi][0], a[mi][1], a[mi][2], a[mi][3], ab + a_off[mi]);
#pragma unroll
        for (int nb = 0; nb < 2; nb++) {
            uint32_t r0, r1, r2, r3;
            ldsm4(r0, r1, r2, r3, bb + b_off[nb]);
            b[2 * nb][0] = r0; b[2 * nb][1] = r1;
            b[2 * nb + 1][0] = r2; b[2 * nb + 1][1] = r3;
        }
#pragma unroll
        for (int mi = 0; mi < 4; mi++)
#pragma unroll
            for (int nj = 0; nj < 4; nj++) mma_bf16(acc[mi][nj], a[mi], b[nj]);
        if (more) {
            *(uint4*)&As[buf ^ 1][a_st] = av;
            *(uint4*)&Bs[buf ^ 1][b_st] =
                make_uint4(pkbf(bv[0], bv[1]), pkbf(bv[2], bv[3]), pkbf(bv[4], bv[5]), pkbf(bv[6], bv[7]));
            __syncthreads();
            buf ^= 1;
        }
    }

#pragma unroll
    for (int nj = 0; nj < 4; nj++) {
        int c = n0 + wn + nj * 8 + tig * 2;
        float bi0 = bias[c], bi1 = bias[c + 1];
#pragma unroll
        for (int mi = 0; mi < 4; mi++) {
            size_t r = m0 + wm + mi * 16 + grp;
            float2 r0 = *(const float2*)(resid + r * ldc + c);
            float2 r1 = *(const float2*)(resid + (r + 8) * ldc + c);
            *(float2*)(C + r * ldc + c) =
                make_float2(acc[mi][nj][0] + bi0 + r0.x, acc[mi][nj][1] + bi1 + r0.y);
            *(float2*)(C + (r + 8) * ldc + c) =
                make_float2(acc[mi][nj][2] + bi0 + r1.x, acc[mi][nj][3] + bi1 + r1.y);
        }
    }
}

// ================= fused flash attention (bf16 in/out) + gate blend =================
#define LDQ 136
#define LDV 104
#define FLASH_SMEM ((2 * 48 * LDQ + 64 * LDV) * 4)

__global__ __launch_bounds__(256, 1)
void flash_kernel(const uint32_t* __restrict__ qkvbf, const float* __restrict__ qout,
                  const float* __restrict__ fw, uint32_t* __restrict__ fusedbf) {
    extern __shared__ uint32_t smu[];
    uint32_t* Qs = smu;
    uint32_t* Ks = smu + 48 * LDQ;
    uint32_t* Vs = smu + 2 * 48 * LDQ;

    int tid = threadIdx.x;
    int z = blockIdx.y;
    int b = z >> 3, h = z & 7;
    int q0 = blockIdx.x * 128;
    const uint32_t* qb32 = qkvbf + (size_t)b * Nseq * 1152 + h * 48;
    const uint32_t* kb32 = qb32 + 384;
    const uint32_t* vb32 = qb32 + 768;

    int lane = tid & 31, wid = tid >> 5;
    int grp = lane >> 2, tig = lane & 3;
    int wrow = wid * 16;

    for (int i = tid; i < 6144; i += 256) {
        int d2 = i % 48, r = i / 48;
        Qs[d2 * LDQ + r] = qb32[(size_t)(q0 + r) * 1152 + d2];
    }

    float o[12][4] = {};
    float m0 = -1e30f, m1 = -1e30f, l0 = 0.f, l1 = 0.f;
    const float scale = 0.10206207261596577f;

    for (int t = 0; t < 8; t++) {
        __syncthreads();
        int kv0 = t * 128;
        for (int i = tid; i < 6144; i += 256) {
            int d2 = i % 48, r = i / 48;
            Ks[d2 * LDQ + r] = kb32[(size_t)(kv0 + r) * 1152 + d2];
        }
        for (int i = tid; i < 3072; i += 256) {
            int j2 = i / 48, k = i % 48;
            uint32_t u0 = vb32[(size_t)(kv0 + 2 * j2) * 1152 + k];
            uint32_t u1 = vb32[(size_t)(kv0 + 2 * j2 + 1) * 1152 + k];
            Vs[j2 * LDV + 2 * k]     = __byte_perm(u0, u1, 0x5410);
            Vs[j2 * LDV + 2 * k + 1] = __byte_perm(u0, u1, 0x7632);
        }
        __syncthreads();

        float s[16][4] = {};
#pragma unroll
        for (int ks = 0; ks < 6; ks++) {
            uint32_t a[4];
            a[0] = Qs[(ks * 8 + tig) * LDQ + wrow + grp];
            a[1] = Qs[(ks * 8 + tig) * LDQ + wrow + grp + 8];
            a[2] = Qs[(ks * 8 + tig + 4) * LDQ + wrow + grp];
            a[3] = Qs[(ks * 8 + tig + 4) * LDQ + wrow + grp + 8];
#pragma unroll
            for (int n = 0; n < 16; n++) {
                uint32_t bb[2];
                bb[0] = Ks[(ks * 8 + tig) * LDQ + n * 8 + grp];
                bb[1] = Ks[(ks * 8 + tig + 4) * LDQ + n * 8 + grp];
                mma_bf16(s[n], a, bb);
            }
        }

        float mx0 = -1e30f, mx1 = -1e30f;
#pragma unroll
        for (int n = 0; n < 16; n++) {
            mx0 = fmaxf(mx0, fmaxf(s[n][0], s[n][1]));
            mx1 = fmaxf(mx1, fmaxf(s[n][2], s[n][3]));
        }
        mx0 = fmaxf(mx0, __shfl_xor_sync(~0u, mx0, 1));
        mx0 = fmaxf(mx0, __shfl_xor_sync(~0u, mx0, 2));
        mx1 = fmaxf(mx1, __shfl_xor_sync(~0u, mx1, 1));
        mx1 = fmaxf(mx1, __shfl_xor_sync(~0u, mx1, 2));
        float nm0 = fmaxf(m0, mx0 * scale);
        float nm1 = fmaxf(m1, mx1 * scale);
        float al0 = __expf(m0 - nm0), al1 = __expf(m1 - nm1);
        m0 = nm0; m1 = nm1;
        float sum0 = 0.f, sum1 = 0.f;
#pragma unroll
        for (int n = 0; n < 16; n++) {
            float p0 = __expf(s[n][0] * scale - nm0);
            float p1 = __expf(s[n][1] * scale - nm0);
            float p2 = __expf(s[n][2] * scale - nm1);
            float p3 = __expf(s[n][3] * scale - nm1);
            sum0 += p0 + p1; sum1 += p2 + p3;
            s[n][0] = p0; s[n][1] = p1; s[n][2] = p2; s[n][3] = p3;
        }
        sum0 += __shfl_xor_sync(~0u, sum0, 1);
        sum0 += __shfl_xor_sync(~0u, sum0, 2);
        sum1 += __shfl_xor_sync(~0u, sum1, 1);
        sum1 += __shfl_xor_sync(~0u, sum1, 2);
        l0 = l0 * al0 + sum0;
        l1 = l1 * al1 + sum1;
#pragma unroll
        for (int n = 0; n < 12; n++) {
            o[n][0] *= al0; o[n][1] *= al0;
            o[n][2] *= al1; o[n][3] *= al1;
        }

#pragma unroll
        for (int jb = 0; jb < 8; jb++) {
            uint32_t a[4];
            a[0] = pkbf(s[2 * jb][0], s[2 * jb][1]);
            a[1] = pkbf(s[2 * jb][2], s[2 * jb][3]);
            a[2] = pkbf(s[2 * jb + 1][0], s[2 * jb + 1][1]);
            a[3] = pkbf(s[2 * jb + 1][2], s[2 * jb + 1][3]);
#pragma unroll
            for (int n = 0; n < 12; n++) {
                uint32_t bb[2];
                bb[0] = Vs[(jb * 8 + tig) * LDV + n * 8 + grp];
                bb[1] = Vs[(jb * 8 + tig + 4) * LDV + n * 8 + grp];
                mma_bf16(o[n], a, bb);
            }
        }
    }

    float inv0 = 1.f / l0, inv1 = 1.f / l1;
    int row0 = q0 + wrow + grp;
#pragma unroll
    for (int n = 0; n < 12; n++) {
        int c = n * 8 + tig * 2;
        float f0 = fw[b * Cdim + h * Dd + c];
        float f1 = fw[b * Cdim + h * Dd + c + 1];
        size_t ob0 = ((size_t)b * Nseq + row0) * Cdim + h * Dd + c;
        size_t ob1 = ((size_t)b * Nseq + row0 + 8) * Cdim + h * Dd + c;
        float2 qv0 = *(const float2*)(qout + ob0);
        float2 qv1 = *(const float2*)(qout + ob1);
        fusedbf[ob0 >> 1] = pkbf(f0 * qv0.x + (1.f - f0) * o[n][0] * inv0,
                                 f1 * qv0.y + (1.f - f1) * o[n][1] * inv0);
        fusedbf[ob1 >> 1] = pkbf(f0 * qv1.x + (1.f - f0) * o[n][2] * inv1,
                                 f1 * qv1.y + (1.f - f1) * o[n][3] * inv1);
    }
}

// ================= quantum embed GEMM (bf16 A): H = relu(A @ W1 + b1) =================
__global__ __launch_bounds__(256)
void embed_gemm(const uint32_t* __restrict__ qkvbf,
                const float* __restrict__ qW1, const float* __restrict__ qb1,
                const float* __restrict__ kW1, const float* __restrict__ kb1,
                float* __restrict__ Hq, float* __restrict__ Hk) {
    __shared__ uint32_t As[2][8][136];
    __shared__ uint32_t Bs[48][72];
    int tid = threadIdx.x;
    int m0 = blockIdx.x * 128;
    int pass = blockIdx.y;
    const float* W1 = pass ? kW1 : qW1;
    const float* b1 = pass ? kb1 : qb1;
    float* H = pass ? Hk : Hq;
    int qk_off32 = pass * 384;

    for (int i = tid; i < 768; i += 256) {
        int k2 = i >> 4, c4 = i & 15;
        float4 w0 = *(const float4*)(W1 + (2 * k2) * 64 + c4 * 4);
        float4 w1 = *(const float4*)(W1 + (2 * k2 + 1) * 64 + c4 * 4);
        *(uint4*)&Bs[k2][c4 * 4] = make_uint4(pkbf(w0.x, w1.x), pkbf(w0.y, w1.y),
                                              pkbf(w0.z, w1.z), pkbf(w0.w, w1.w));
    }

    int arow = tid >> 1, apart = tid & 1;
    int mrow = m0 + arow;
    const uint4* Ap4 = (const uint4*)(qkvbf + (size_t)(mrow >> 3) * 1152 + qk_off32 + (mrow & 7) * 48);

    int wid = tid >> 5, lane = tid & 31;
    int wm = (wid >> 2) * 64, wn = (wid & 3) * 16;
    int grp = lane >> 2, tig = lane & 3;
    float acc[4][2][4] = {};

    {
        uint4 av = Ap4[apart];
        As[0][apart * 4 + 0][arow] = av.x;
        As[0][apart * 4 + 1][arow] = av.y;
        As[0][apart * 4 + 2][arow] = av.z;
        As[0][apart * 4 + 3][arow] = av.w;
    }
    __syncthreads();

    int buf = 0;
    for (int s = 1; s <= 6; s++) {
        bool more = (s < 6);
        uint4 av;
        if (more) av = Ap4[s * 2 + apart];
        int kb = (s - 1) * 8;
        uint32_t a[4][4], b[2][2];
#pragma unroll
        for (int mi = 0; mi < 4; mi++) {
            int r = wm + mi * 16 + grp;
            a[mi][0] = As[buf][tig][r];
            a[mi][1] = As[buf][tig][r + 8];
            a[mi][2] = As[buf][tig + 4][r];
            a[mi][3] = As[buf][tig + 4][r + 8];
        }
#pragma unroll
        for (int nj = 0; nj < 2; nj++) {
            int c = wn + nj * 8 + grp;
            b[nj][0] = Bs[kb + tig][c];
            b[nj][1] = Bs[kb + tig + 4][c];
        }
#pragma unroll
        for (int mi = 0; mi < 4; mi++)
#pragma unroll
            for (int nj = 0; nj < 2; nj++) mma_bf16(acc[mi][nj], a[mi], b[nj]);
        if (more) {
            As[buf ^ 1][apart * 4 + 0][arow] = av.x;
            As[buf ^ 1][apart * 4 + 1][arow] = av.y;
            As[buf ^ 1][apart * 4 + 2][arow] = av.z;
            As[buf ^ 1][apart * 4 + 3][arow] = av.w;
            __syncthreads();
            buf ^= 1;
        }
    }

#pragma unroll
    for (int nj = 0; nj < 2; nj++) {
        int c = wn + nj * 8 + tig * 2;
        float bi0 = __ldg(&b1[c]), bi1 = __ldg(&b1[c + 1]);
#pragma unroll
        for (int mi = 0; mi < 4; mi++) {
            size_t r = m0 + wm + mi * 16 + grp;
            *(float2*)(H + r * 64 + c) =
                make_float2(fmaxf(acc[mi][nj][0] + bi0, 0.f), fmaxf(acc[mi][nj][1] + bi1, 0.f));
            *(float2*)(H + (r + 8) * 64 + c) =
                make_float2(fmaxf(acc[mi][nj][2] + bi0, 0.f), fmaxf(acc[mi][nj][3] + bi1, 0.f));
        }
    }
}

// ================= quantum middle: e -> state -> meas =================
__global__ __launch_bounds__(128)
void quantum_mid(const float* __restrict__ Hq, const float* __restrict__ Hk,
                 const float* __restrict__ qe_w2, const float* __restrict__ qe_b2,
                 const float* __restrict__ ke_w2, const float* __restrict__ ke_b2,
                 const float* __restrict__ gate_params, const float* __restrict__ ent_params,
                 const float* __restrict__ gumbel, float* __restrict__ meas_out) {
    __shared__ float w2q[1024], w2k[1024];
    __shared__ float gf[2][8], gcz[2][8], gsz[2][8], gs[2][8];
    int tid = threadIdx.x;
    for (int i = tid; i < 256; i += 128) {
        ((float4*)w2q)[i] = ((const float4*)qe_w2)[i];
        ((float4*)w2k)[i] = ((const float4*)ke_w2)[i];
    }
    if (tid < 16) {
        int l = tid >> 3, i = tid & 7;
        float ry = gate_params[(l * 8 + i) * 3 + 1];
        float rz = gate_params[(l * 8 + i) * 3 + 2];
        gf[l][i] = cosf(0.5f * ry);
        gcz[l][i] = cosf(rz);
        gsz[l][i] = sinf(rz);
    } else if (tid < 30) {
        int t = tid - 16, l = t / 7, i = t % 7;
        gs[l][i + 1] = 1.f / (1.f + expf(-ent_params[l * 7 + i]));
    }
    __syncthreads();

    int m = blockIdx.x * 128 + tid;
    float sre[8], sim[8];

#pragma unroll
    for (int pass = 0; pass < 2; pass++) {
        const float* Hrow = (pass == 0 ? Hq : Hk) + (size_t)m * 64;
        const float* w2 = (pass == 0 ? w2q : w2k);
        const float* b2 = (pass == 0 ? qe_b2 : ke_b2);
        float e[16];
#pragma unroll
        for (int i = 0; i < 16; i++) e[i] = __ldg(&b2[i]);
        const float4* h4 = (const float4*)Hrow;
#pragma unroll
        for (int j4 = 0; j4 < 16; j4++) {
            float4 hv = h4[j4];
            float hs[4] = {hv.x, hv.y, hv.z, hv.w};
#pragma unroll
            for (int s = 0; s < 4; s++) {
                float hj = hs[s];
                const float4* wr = (const float4*)&w2[(j4 * 4 + s) * 16];
#pragma unroll
                for (int i4 = 0; i4 < 4; i4++) {
                    float4 w = wr[i4];
                    e[i4 * 4 + 0] += hj * w.x; e[i4 * 4 + 1] += hj * w.y;
                    e[i4 * 4 + 2] += hj * w.z; e[i4 * 4 + 3] += hj * w.w;
                }
            }
        }
        float mx = e[0];
#pragma unroll
        for (int i = 1; i < 8; i++) mx = fmaxf(mx, e[i]);
        float ex[8], ssum = 0.f;
#pragma unroll
        for (int i = 0; i < 8; i++) { ex[i] = __expf(e[i] - mx); ssum += ex[i]; }
        float inv = 1.f / ssum;
#pragma unroll
        for (int i = 0; i < 8; i++) {
            float amp = ex[i] * inv;
            float cr = amp * __cosf(e[8 + i]), ci = amp * __sinf(e[8 + i]);
            if (pass == 0) { sre[i] = cr; sim[i] = ci; }
            else           { sre[i] += cr; sim[i] += ci; }
        }
    }

#pragma unroll
    for (int l = 0; l < 2; l++) {
#pragma unroll
        for (int i = 0; i < 8; i++) {
            float nr = sre[i] * gcz[l][i] - sim[i] * gsz[l][i];
            float ni = sre[i] * gsz[l][i] + sim[i] * gcz[l][i];
            sre[i] = nr * gf[l][i];
            sim[i] = ni * gf[l][i];
        }
#pragma unroll
        for (int i = 7; i >= 1; i--) {
            sre[i] += gs[l][i] * sre[i - 1];
            sim[i] += gs[l][i] * sim[i - 1];
        }
    }

    float p[8], mx = -1e30f;
#pragma unroll
    for (int i = 0; i < 8; i++) { p[i] = sre[i] * sre[i] + sim[i] * sim[i]; mx = fmaxf(mx, p[i]); }
    float ssum = 0.f;
#pragma unroll
    for (int i = 0; i < 8; i++) { p[i] = __expf(p[i] - mx); ssum += p[i]; }
    float sinv = 1.f / ssum;
    int b = m >> 13, n = (m >> 3) & 1023, h = m & 7;
    size_t goff = (size_t)(((b * 8 + h) << 10) + n) * 8;
    float4 g0 = __ldg((const float4*)(gumbel + goff));
    float4 g1 = __ldg((const float4*)(gumbel + goff + 4));
    float gv[8] = {g0.x, g0.y, g0.z, g0.w, g1.x, g1.y, g1.z, g1.w};
    float lg[8], mx2 = -1e30f;
#pragma unroll
    for (int i = 0; i < 8; i++) {
        lg[i] = 2.f * (__logf(p[i] * sinv + 1e-10f) + gv[i]);
        mx2 = fmaxf(mx2, lg[i]);
    }
    float meas[8], msum = 0.f;
#pragma unroll
    for (int i = 0; i < 8; i++) { meas[i] = __expf(lg[i] - mx2); msum += meas[i]; }
    float minv = 1.f / msum;
    float4 o0 = make_float4(meas[0] * minv, meas[1] * minv, meas[2] * minv, meas[3] * minv);
    float4 o1 = make_float4(meas[4] * minv, meas[5] * minv, meas[6] * minv, meas[7] * minv);
    *(float4*)(meas_out + (size_t)m * 8) = o0;
    *(float4*)(meas_out + (size_t)m * 8 + 4) = o1;
}

// ================= fused measure MLP (tf32): qout = (relu(meas@W1+b1)@W2+b2)*v =================
#define MD_T1_LD 136
#define MD_W2_LD 104
#define MD_SMEM ((8 * 136 + 8 * 72 + 64 * MD_T1_LD + 64 * MD_W2_LD) * 4)

__global__ __launch_bounds__(256)
void md_fused(const float* __restrict__ meas,
              const float* __restrict__ W1, const float* __restrict__ b1,
              const float* __restrict__ W2, const float* __restrict__ b2,
              const uint32_t* __restrict__ qkvbf, float* __restrict__ qout) {
    extern __shared__ float sm[];
    float* As8 = sm;
    float* W1s = sm + 8 * 136;
    float* T1  = sm + 8 * 136 + 8 * 72;
    float* W2s = T1 + 64 * MD_T1_LD;

    int tid = threadIdx.x;
    int m0 = blockIdx.x * 128;
    int wid = tid >> 5, lane = tid & 31;
    int grp = lane >> 2, tig = lane & 3;
    int wm = (wid >> 2) * 64;

    {
        int arow = tid >> 1, ak = (tid & 1) * 4;
        float4 v = *(const float4*)(meas + (size_t)(m0 + arow) * 8 + ak);
        As8[(ak + 0) * 136 + arow] = to_tf32(v.x);
        As8[(ak + 1) * 136 + arow] = to_tf32(v.y);
        As8[(ak + 2) * 136 + arow] = to_tf32(v.z);
        As8[(ak + 3) * 136 + arow] = to_tf32(v.w);
    }
    for (int i = tid; i < 128; i += 256) {
        int d = i >> 4, n4 = i & 15;
        float4 w = ((const float4*)W1)[i];
        float4 wc = make_float4(to_tf32(w.x), to_tf32(w.y), to_tf32(w.z), to_tf32(w.w));
        *(float4*)&W1s[d * 72 + n4 * 4] = wc;
    }
    for (int i = tid; i < 1536; i += 256) {
        int d = i / 24, n4 = i % 24;
        float4 w = ((const float4*)W2)[i];
        float4 wc = make_float4(to_tf32(w.x), to_tf32(w.y), to_tf32(w.z), to_tf32(w.w));
        *(float4*)&W2s[d * MD_W2_LD + n4 * 4] = wc;
    }
    __syncthreads();

    {
        int wn1 = (wid & 3) * 16;
        float acc1[4][2][4] = {};
        uint32_t a[4][4], b[2][2];
#pragma unroll
        for (int mi = 0; mi < 4; mi++) {
            int r = wm + mi * 16 + grp;
            a[mi][0] = __float_as_uint(As8[tig * 136 + r]);
            a[mi][1] = __float_as_uint(As8[tig * 136 + r + 8]);
            a[mi][2] = __float_as_uint(As8[(tig + 4) * 136 + r]);
            a[mi][3] = __float_as_uint(As8[(tig + 4) * 136 + r + 8]);
        }
#pragma unroll
        for (int nj = 0; nj < 2; nj++) {
            int c = wn1 + nj * 8 + grp;
            b[nj][0] = __float_as_uint(W1s[tig * 72 + c]);
            b[nj][1] = __float_as_uint(W1s[(tig + 4) * 72 + c]);
        }
#pragma unroll
        for (int mi = 0; mi < 4; mi++)
#pragma unroll
            for (int nj = 0; nj < 2; nj++) mma_tf32(acc1[mi][nj], a[mi], b[nj]);

#pragma unroll
        for (int nj = 0; nj < 2; nj++) {
            int c = wn1 + nj * 8 + tig * 2;
            float bi0 = __ldg(&b1[c]), bi1 = __ldg(&b1[c + 1]);
#pragma unroll
            for (int mi = 0; mi < 4; mi++) {
                int r = wm + mi * 16 + grp;
                T1[c * MD_T1_LD + r]           = to_tf32(fmaxf(acc1[mi][nj][0] + bi0, 0.f));
                T1[(c + 1) * MD_T1_LD + r]     = to_tf32(fmaxf(acc1[mi][nj][1] + bi1, 0.f));
                T1[c * MD_T1_LD + r + 8]       = to_tf32(fmaxf(acc1[mi][nj][2] + bi0, 0.f));
                T1[(c + 1) * MD_T1_LD + r + 8] = to_tf32(fmaxf(acc1[mi][nj][3] + bi1, 0.f));
            }
        }
    }
    __syncthreads();

    int wn = (wid & 3) * 24;
    float acc2[4][3][4] = {};
#pragma unroll
    for (int ks = 0; ks < 8; ks++) {
        uint32_t a[4][4], b[3][2];
#pragma unroll
        for (int mi = 0; mi < 4; mi++) {
            int r = wm + mi * 16 + grp;
            a[mi][0] = __float_as_uint(T1[(ks * 8 + tig) * MD_T1_LD + r]);
            a[mi][1] = __float_as_uint(T1[(ks * 8 + tig) * MD_T1_LD + r + 8]);
            a[mi][2] = __float_as_uint(T1[(ks * 8 + tig + 4) * MD_T1_LD + r]);
            a[mi][3] = __float_as_uint(T1[(ks * 8 + tig + 4) * MD_T1_LD + r + 8]);
        }
#pragma unroll
        for (int nj = 0; nj < 3; nj++) {
            int c = wn + nj * 8 + grp;
            b[nj][0] = __float_as_uint(W2s[(ks * 8 + tig) * MD_W2_LD + c]);
            b[nj][1] = __float_as_uint(W2s[(ks * 8 + tig + 4) * MD_W2_LD + c]);
        }
#pragma unroll
        for (int mi = 0; mi < 4; mi++)
#pragma unroll
            for (int nj = 0; nj < 3; nj++) mma_tf32(acc2[mi][nj], a[mi], b[nj]);
    }

#pragma unroll
    for (int nj = 0; nj < 3; nj++) {
        int c = wn + nj * 8 + tig * 2;
        float bi0 = __ldg(&b2[c]), bi1 = __ldg(&b2[c + 1]);
#pragma unroll
        for (int mi = 0; mi < 4; mi++) {
            int m = m0 + wm + mi * 16 + grp;
#pragma unroll
            for (int half = 0; half < 2; half++) {
                int mm = m + half * 8;
                size_t qrow = (size_t)(mm >> 3);
                int hh = mm & 7;
                uint32_t u = qkvbf[(qrow * 2304 + 1536 + hh * 96 + c) >> 1];
                float2 vv = __bfloat1622float2(*(__nv_bfloat162*)&u);
                float o0 = (acc2[mi][nj][half * 2 + 0] + bi0) * vv.x;
                float o1 = (acc2[mi][nj][half * 2 + 1] + bi1) * vv.y;
                *(float2*)(qout + qrow * 768 + hh * 96 + c) = make_float2(o0, o1);
            }
        }
    }
}

// ================= mean over N =================
__global__ void colmean_kernel(const float* __restrict__ x, float* __restrict__ xmean) {
    int b = blockIdx.y;
    int c = blockIdx.x * 256 + threadIdx.x;
    const float* p = x + (size_t)b * Nseq * Cdim + c;
    float s = 0.f;
    for (int n = 0; n < Nseq; n++) s += p[(size_t)n * Cdim];
    xmean[b * Cdim + c] = s * (1.0f / 1024.0f);
}

// ================= fw = sigmoid(xmean @ w_proj + b_proj) =================
__global__ void fw_kernel(const float* __restrict__ xmean, const float* __restrict__ w_proj,
                          const float* __restrict__ b_proj, float* __restrict__ fw) {
    __shared__ float xm[768];
    int b = blockIdx.x;
    int c = threadIdx.x;
    xm[c] = xmean[b * Cdim + c];
    __syncthreads();
    float s = b_proj[c];
    for (int k = 0; k < 768; k++) s += xm[k] * w_proj[(size_t)k * 768 + c];
    fw[b * Cdim + c] = 1.f / (1.f + expf(-s));
}

// ================= layernorm =================
__global__ void layernorm_kernel(const float* __restrict__ y, const float* __restrict__ gamma,
                                 const float* __restrict__ beta, float* __restrict__ out) {
    __shared__ float red1[8], red2[8];
    size_t row = blockIdx.x;
    const float* p = y + row * Cdim;
    int tid = threadIdx.x;
    float v[3];
    float s = 0.f;
#pragma unroll
    for (int i = 0; i < 3; i++) { v[i] = p[tid + i * 256]; s += v[i]; }
#pragma unroll
    for (int o = 16; o > 0; o >>= 1) s += __shfl_xor_sync(~0u, s, o);
    int w = tid >> 5, lane = tid & 31;
    if (lane == 0) red1[w] = s;
    __syncthreads();
    s = 0.f;
#pragma unroll
    for (int i = 0; i < 8; i++) s += red1[i];
    float mu = s * (1.0f / 768.0f);
    float vs = 0.f;
#pragma unroll
    for (int i = 0; i < 3; i++) { float d = v[i] - mu; vs += d * d; }
#pragma unroll
    for (int o = 16; o > 0; o >>= 1) vs += __shfl_xor_sync(~0u, vs, o);
    if (lane == 0) red2[w] = vs;
    __syncthreads();
    vs = 0.f;
#pragma unroll
    for (int i = 0; i < 8; i++) vs += red2[i];
    float inv = rsqrtf(vs * (1.0f / 768.0f) + 1e-5f);
#pragma unroll
    for (int i = 0; i < 3; i++) {
        int c = tid + i * 256;
        out[row * Cdim + c] = (v[i] - mu) * inv * gamma[c] + beta[c];
    }
}

// ================= launch =================
extern "C" void kernel_launch(void* const* d_in, const int* in_sizes, int n_in,
                              void* d_out, int out_size) {
    const float* x      = (const float*)d_in[0];
    const float* w_qkv  = (const float*)d_in[1];
    const float* b_qkv  = (const float*)d_in[2];
    const float* w_proj = (const float*)d_in[3];
    const float* b_proj = (const float*)d_in[4];
    const float* gamma  = (const float*)d_in[5];
    const float* beta   = (const float*)d_in[6];
    const float* qe_w1  = (const float*)d_in[7];
    const float* qe_b1  = (const float*)d_in[8];
    const float* qe_w2  = (const float*)d_in[9];
    const float* qe_b2  = (const float*)d_in[10];
    const float* ke_w1  = (const float*)d_in[11];
    const float* ke_b1  = (const float*)d_in[12];
    const float* ke_w2  = (const float*)d_in[13];
    const float* ke_b2  = (const float*)d_in[14];
    const float* gate_params = (const float*)d_in[19];
    const float* ent_params  = (const float*)d_in[20];
    const float* md_w1  = (const float*)d_in[21];
    const float* md_b1  = (const float*)d_in[22];
    const float* md_w2  = (const float*)d_in[23];
    const float* md_b2  = (const float*)d_in[24];
    const float* gumbel = (const float*)d_in[25];
    float* out = (float*)d_out;

    uint32_t *qkvbf, *fusedbf;
    float *qout, *y, *xmean, *fw, *hq, *hk, *meas;
    cudaGetSymbolAddress((void**)&qkvbf, g_qkv_bf);
    cudaGetSymbolAddress((void**)&fusedbf, g_fused_bf);
    cudaGetSymbolAddress((void**)&qout, g_qout);
    cudaGetSymbolAddress((void**)&y, g_y);
    cudaGetSymbolAddress((void**)&xmean, g_xmean);
    cudaGetSymbolAddress((void**)&fw, g_fw);
    cudaGetSymbolAddress((void**)&hq, g_hq);
    cudaGetSymbolAddress((void**)&hk, g_hk);
    cudaGetSymbolAddress((void**)&meas, g_meas);

    cudaFuncSetAttribute(flash_kernel, cudaFuncAttributeMaxDynamicSharedMemorySize, FLASH_SMEM);
    cudaFuncSetAttribute(md_fused, cudaFuncAttributeMaxDynamicSharedMemorySize, MD_SMEM);

    // gate path (depends only on x)
    colmean_kernel<<<dim3(3, 8), 256>>>(x, xmean);
    fw_kernel<<<8, 768>>>(xmean, w_proj, b_proj, fw);
    // qkv = x @ w_qkv + b_qkv  -> bf16
    mma_qkv<<<dim3(2304 / 128, 8192 / 128), 256>>>(x, w_qkv, b_qkv, qkvbf,
                                                   768, 768, 2304, 2304);
    // quantum path: embeds (GEMM) -> mid -> measure MLP (GEMM) -> qout
    embed_gemm<<<dim3(NTOK / 128, 2), 256>>>(qkvbf, qe_w1, qe_b1, ke_w1, ke_b1, hq, hk);
    quantum_mid<<<NTOK / 128, 128>>>(hq, hk, qe_w2, qe_b2, ke_w2, ke_b2,
                                     gate_params, ent_params, gumbel, meas);
    md_fused<<<NTOK / 128, 256, MD_SMEM>>>(meas, md_w1, md_b1, md_w2, md_b2, qkvbf, qout);
    // fused classical attention + gate blend -> fused (bf16)
    flash_kernel<<<dim3(8, 64), 256, FLASH_SMEM>>>(qkvbf, qout, fw, fusedbf);
    // y = x + fused @ w_proj + b_proj
    mma_proj<<<dim3(768 / 128, 8192 / 128), 256>>>(fusedbf, w_proj, b_proj, x, y,
                                                   768, 768, 768, 768);
    // layernorm
    layernorm_kernel<<<8192, 256>>>(y, gamma, beta, out);
}

// round 12
// speedup vs baseline: 1.2617x; 1.0740x over previous
#include <cuda_runtime.h>
#include <cuda_bf16.h>
#include <math.h>
#include <stdint.h>

// ---------------- scratch ----------------
#define Bsz 8
#define Nseq 1024
#define Cdim 768
#define Hh 8
#define Dd 96
#define Qq 8
#define NTOK (Bsz * Hh * Nseq)   // 65536, ordered m=(b,n,h)

__device__ uint32_t g_qkv_bf[Bsz * Nseq * 3 * Cdim / 2];   // bf16x2
__device__ uint32_t g_fused_bf[Bsz * Nseq * Cdim / 2];     // bf16x2
__device__ float g_qout[Bsz * Nseq * Cdim];
__device__ float g_y[Bsz * Nseq * Cdim];
__device__ float g_xmean[Bsz * Cdim];
__device__ float g_fw[Bsz * Cdim];
__device__ float g_hq[NTOK * 64];
__device__ float g_hk[NTOK * 64];
__device__ float g_meas[NTOK * 8];

// ---------------- mma helpers ----------------
__device__ __forceinline__ float to_tf32(float x) {
    uint32_t u;
    asm("cvt.rna.tf32.f32 %0, %1;" : "=r"(u) : "f"(x));
    return __uint_as_float(u);
}

__device__ __forceinline__ uint32_t pkbf(float x, float y) {
    __nv_bfloat162 t = __floats2bfloat162_rn(x, y);
    return *(uint32_t*)&t;
}

__device__ __forceinline__ void mma_tf32(float* c, const uint32_t* a, const uint32_t* b) {
    asm volatile(
        "mma.sync.aligned.m16n8k8.row.col.f32.tf32.tf32.f32 "
        "{%0,%1,%2,%3}, {%4,%5,%6,%7}, {%8,%9}, {%0,%1,%2,%3};"
        : "+f"(c[0]), "+f"(c[1]), "+f"(c[2]), "+f"(c[3])
        : "r"(a[0]), "r"(a[1]), "r"(a[2]), "r"(a[3]), "r"(b[0]), "r"(b[1]));
}

__device__ __forceinline__ void mma_bf16(float* c, const uint32_t* a, const uint32_t* b) {
    asm volatile(
        "mma.sync.aligned.m16n8k16.row.col.f32.bf16.bf16.f32 "
        "{%0,%1,%2,%3}, {%4,%5,%6,%7}, {%8,%9}, {%0,%1,%2,%3};"
        : "+f"(c[0]), "+f"(c[1]), "+f"(c[2]), "+f"(c[3])
        : "r"(a[0]), "r"(a[1]), "r"(a[2]), "r"(a[3]), "r"(b[0]), "r"(b[1]));
}

__device__ __forceinline__ void ldsm4(uint32_t& r0, uint32_t& r1, uint32_t& r2, uint32_t& r3,
                                      uint32_t addr) {
    asm volatile("ldmatrix.sync.aligned.m8n8.x4.shared.b16 {%0,%1,%2,%3}, [%4];"
                 : "=r"(r0), "=r"(r1), "=r"(r2), "=r"(r3) : "r"(addr));
}

__device__ __forceinline__ void ldsm4t(uint32_t& r0, uint32_t& r1, uint32_t& r2, uint32_t& r3,
                                       uint32_t addr) {
    asm volatile("ldmatrix.sync.aligned.m8n8.x4.trans.shared.b16 {%0,%1,%2,%3}, [%4];"
                 : "=r"(r0), "=r"(r1), "=r"(r2), "=r"(r3) : "r"(addr));
}

// XOR-swizzled tile (GEMM): [128 rows][8 u32]; part swapped on (row>>2)&1.
#define SWZ(row, part) ((row) * 8 + (((part) ^ (((row) >> 2) & 1)) * 4))
#define TILE_U32 (128 * 8)
#define TILE_B (TILE_U32 * 4)

// ================= qkv GEMM: A fp32, B fp32, out bf16 =================
__global__ __launch_bounds__(256)
void mma_qkv(const float* __restrict__ A, const float* __restrict__ B,
             const float* __restrict__ bias, uint32_t* __restrict__ Cbf,
             int K, int lda, int ldb, int ldc) {
    __shared__ uint32_t As[2][TILE_U32];
    __shared__ uint32_t Bs[2][TILE_U32];
    int tid = threadIdx.x;
    int m0 = blockIdx.y * 128, n0 = blockIdx.x * 128;
    int arow = tid >> 1, apart = tid & 1;
    const float* Ap = A + (size_t)(m0 + arow) * lda + apart * 8;
    uint32_t a_st = SWZ(arow, apart);
    int bcol = tid & 127, bpart = tid >> 7;
    const float* Bp = B + (size_t)(bpart * 8) * ldb + n0 + bcol;
    uint32_t b_st = SWZ(bcol, bpart);

    int wid = tid >> 5, lane = tid & 31;
    int wm = (wid >> 2) * 64, wn = (wid & 3) * 32;
    int grp = lane >> 2, tig = lane & 3;
    float acc[4][4][4] = {};

    uint32_t asb = (uint32_t)__cvta_generic_to_shared(&As[0][0]);
    uint32_t bsb = (uint32_t)__cvta_generic_to_shared(&Bs[0][0]);
    uint32_t a_off[4], b_off[2];
#pragma unroll
    for (int mi = 0; mi < 4; mi++) {
        int r = wm + mi * 16 + (lane & 15);
        a_off[mi] = SWZ(r, lane >> 4) * 4;
    }
#pragma unroll
    for (int nb = 0; nb < 2; nb++) {
        int r = wn + nb * 16 + (lane & 7) + ((lane >> 4) << 3);
        b_off[nb] = SWZ(r, (lane >> 3) & 1) * 4;
    }

    {
        float4 a0 = *(const float4*)Ap;
        float4 a1 = *(const float4*)(Ap + 4);
        *(uint4*)&As[0][a_st] =
            make_uint4(pkbf(a0.x, a0.y), pkbf(a0.z, a0.w), pkbf(a1.x, a1.y), pkbf(a1.z, a1.w));
        float bv[8];
#pragma unroll
        for (int j = 0; j < 8; j++) bv[j] = Bp[(size_t)j * ldb];
        *(uint4*)&Bs[0][b_st] =
            make_uint4(pkbf(bv[0], bv[1]), pkbf(bv[2], bv[3]), pkbf(bv[4], bv[5]), pkbf(bv[6], bv[7]));
    }
    __syncthreads();

    int S = K / 16, buf = 0;
    for (int s = 1; s <= S; s++) {
        bool more = (s < S);
        float4 a0, a1;
        float bv[8];
        if (more) {
            int k0 = s * 16;
            a0 = *(const float4*)(Ap + k0);
            a1 = *(const float4*)(Ap + k0 + 4);
#pragma unroll
            for (int j = 0; j < 8; j++) bv[j] = Bp[(size_t)(k0 + j) * ldb];
        }
        uint32_t a[4][4], b[4][2];
        uint32_t ab = asb + buf * TILE_B, bb = bsb + buf * TILE_B;
#pragma unroll
        for (int mi = 0; mi < 4; mi++)
            ldsm4(a[mi][0], a[mi][1], a[mi][2], a[mi][3], ab + a_off[mi]);
#pragma unroll
        for (int nb = 0; nb < 2; nb++) {
            uint32_t r0, r1, r2, r3;
            ldsm4(r0, r1, r2, r3, bb + b_off[nb]);
            b[2 * nb][0] = r0; b[2 * nb][1] = r1;
            b[2 * nb + 1][0] = r2; b[2 * nb + 1][1] = r3;
        }
#pragma unroll
        for (int mi = 0; mi < 4; mi++)
#pragma unroll
            for (int nj = 0; nj < 4; nj++) mma_bf16(acc[mi][nj], a[mi], b[nj]);
        if (more) {
            *(uint4*)&As[buf ^ 1][a_st] =
                make_uint4(pkbf(a0.x, a0.y), pkbf(a0.z, a0.w), pkbf(a1.x, a1.y), pkbf(a1.z, a1.w));
            *(uint4*)&Bs[buf ^ 1][b_st] =
                make_uint4(pkbf(bv[0], bv[1]), pkbf(bv[2], bv[3]), pkbf(bv[4], bv[5]), pkbf(bv[6], bv[7]));
            __syncthreads();
            buf ^= 1;
        }
    }

#pragma unroll
    for (int nj = 0; nj < 4; nj++) {
        int c = n0 + wn + nj * 8 + tig * 2;
        float bi0 = bias[c], bi1 = bias[c + 1];
#pragma unroll
        for (int mi = 0; mi < 4; mi++) {
            size_t r = m0 + wm + mi * 16 + grp;
            Cbf[(r * ldc + c) >> 1] = pkbf(acc[mi][nj][0] + bi0, acc[mi][nj][1] + bi1);
            Cbf[((r + 8) * ldc + c) >> 1] = pkbf(acc[mi][nj][2] + bi0, acc[mi][nj][3] + bi1);
        }
    }
}

// ================= proj GEMM: A bf16, B fp32, out fp32 + resid =================
__global__ __launch_bounds__(256)
void mma_proj(const uint32_t* __restrict__ Abf, const float* __restrict__ B,
              const float* __restrict__ bias, const float* __restrict__ resid,
              float* __restrict__ C, int K, int lda, int ldb, int ldc) {
    __shared__ uint32_t As[2][TILE_U32];
    __shared__ uint32_t Bs[2][TILE_U32];
    int tid = threadIdx.x;
    int m0 = blockIdx.y * 128, n0 = blockIdx.x * 128;
    int arow = tid >> 1, apart = tid & 1;
    const uint4* Ap4 = (const uint4*)(Abf + (size_t)(m0 + arow) * (lda / 2)) + apart;
    uint32_t a_st = SWZ(arow, apart);
    int bcol = tid & 127, bpart = tid >> 7;
    const float* Bp = B + (size_t)(bpart * 8) * ldb + n0 + bcol;
    uint32_t b_st = SWZ(bcol, bpart);

    int wid = tid >> 5, lane = tid & 31;
    int wm = (wid >> 2) * 64, wn = (wid & 3) * 32;
    int grp = lane >> 2, tig = lane & 3;
    float acc[4][4][4] = {};

    uint32_t asb = (uint32_t)__cvta_generic_to_shared(&As[0][0]);
    uint32_t bsb = (uint32_t)__cvta_generic_to_shared(&Bs[0][0]);
    uint32_t a_off[4], b_off[2];
#pragma unroll
    for (int mi = 0; mi < 4; mi++) {
        int r = wm + mi * 16 + (lane & 15);
        a_off[mi] = SWZ(r, lane >> 4) * 4;
    }
#pragma unroll
    for (int nb = 0; nb < 2; nb++) {
        int r = wn + nb * 16 + (lane & 7) + ((lane >> 4) << 3);
        b_off[nb] = SWZ(r, (lane >> 3) & 1) * 4;
    }

    {
        *(uint4*)&As[0][a_st] = Ap4[0];
        float bv[8];
#pragma unroll
        for (int j = 0; j < 8; j++) bv[j] = Bp[(size_t)j * ldb];
        *(uint4*)&Bs[0][b_st] =
            make_uint4(pkbf(bv[0], bv[1]), pkbf(bv[2], bv[3]), pkbf(bv[4], bv[5]), pkbf(bv[6], bv[7]));
    }
    __syncthreads();

    int S = K / 16, buf = 0;
    for (int s = 1; s <= S; s++) {
        bool more = (s < S);
        uint4 av;
        float bv[8];
        if (more) {
            av = Ap4[s * 2];
            int k0 = s * 16;
#pragma unroll
            for (int j = 0; j < 8; j++) bv[j] = Bp[(size_t)(k0 + j) * ldb];
        }
        uint32_t a[4][4], b[4][2];
        uint32_t ab = asb + buf * TILE_B, bb = bsb + buf * TILE_B;
#pragma unroll
        for (int mi = 0; mi < 4; mi++)
            ldsm4(a[mi][0], a[mi][1], a[mi][2], a[mi][3], ab + a_off[mi]);
#pragma unroll
        for (int nb = 0; nb < 2; nb++) {
            uint32_t r0, r1, r2, r3;
            ldsm4(r0, r1, r2, r3, bb + b_off[nb]);
            b[2 * nb][0] = r0; b[2 * nb][1] = r1;
            b[2 * nb + 1][0] = r2; b[2 * nb + 1][1] = r3;
        }
#pragma unroll
        for (int mi = 0; mi < 4; mi++)
#pragma unroll
            for (int nj = 0; nj < 4; nj++) mma_bf16(acc[mi][nj], a[mi], b[nj]);
        if (more) {
            *(uint4*)&As[buf ^ 1][a_st] = av;
            *(uint4*)&Bs[buf ^ 1][b_st] =
                make_uint4(pkbf(bv[0], bv[1]), pkbf(bv[2], bv[3]), pkbf(bv[4], bv[5]), pkbf(bv[6], bv[7]));
            __syncthreads();
            buf ^= 1;
        }
    }

#pragma unroll
    for (int nj = 0; nj < 4; nj++) {
        int c = n0 + wn + nj * 8 + tig * 2;
        float bi0 = bias[c], bi1 = bias[c + 1];
#pragma unroll
        for (int mi = 0; mi < 4; mi++) {
            size_t r = m0 + wm + mi * 16 + grp;
            float2 r0 = *(const float2*)(resid + r * ldc + c);
            float2 r1 = *(const float2*)(resid + (r + 8) * ldc + c);
            *(float2*)(C + r * ldc + c) =
                make_float2(acc[mi][nj][0] + bi0 + r0.x, acc[mi][nj][1] + bi1 + r0.y);
            *(float2*)(C + (r + 8) * ldc + c) =
                make_float2(acc[mi][nj][2] + bi0 + r1.x, acc[mi][nj][3] + bi1 + r1.y);
        }
    }
}

// ================= fused flash attention (ldmatrix everywhere) =================
// Tiles: [128 rows][64 u32 padded], data in groups p=0..11 (48 u32 = 96 bf16),
// swizzle p' = p ^ (row & 7). Conflict-free ldmatrix phases.
#define FROW 64
#define FSWZ(row, p) ((row) * FROW + (((p) ^ ((row) & 7)) << 2))
#define FTILE_U32 (128 * FROW)
#define FLASH_SMEM (3 * FTILE_U32 * 4)

__global__ __launch_bounds__(256, 1)
void flash_kernel(const uint32_t* __restrict__ qkvbf, const float* __restrict__ qout,
                  const float* __restrict__ fw, uint32_t* __restrict__ fusedbf) {
    extern __shared__ uint32_t smu[];
    uint32_t* Qs = smu;
    uint32_t* Ks = smu + FTILE_U32;
    uint32_t* Vs = smu + 2 * FTILE_U32;

    int tid = threadIdx.x;
    int z = blockIdx.y;
    int b = z >> 3, h = z & 7;
    int q0 = blockIdx.x * 128;
    const uint32_t* qb32 = qkvbf + (size_t)b * Nseq * 1152 + h * 48;
    const uint32_t* kb32 = qb32 + 384;
    const uint32_t* vb32 = qb32 + 768;

    int lane = tid & 31, wid = tid >> 5;
    int grp = lane >> 2, tig = lane & 3;
    int wrow = wid * 16;

    uint32_t qsb = (uint32_t)__cvta_generic_to_shared(Qs);
    uint32_t ksb = (uint32_t)__cvta_generic_to_shared(Ks);
    uint32_t vsb = (uint32_t)__cvta_generic_to_shared(Vs);

    // precomputed fragment address components
    int a_row = wrow + (lane & 15);
    int a_bit = lane >> 4;               // 16B half within k-chunk
    uint32_t a_base = qsb + a_row * FROW * 4;
    int a_c = a_row & 7;
    int b_rloc = (lane & 7) + ((lane >> 4) << 3);  // within 16-col block
    int b_bit = (lane >> 3) & 1;
    int v_rloc = (lane & 7) + (((lane >> 3) & 1) << 3);
    int v_bit = lane >> 4;
    int v_c = v_rloc & 7;

    // stage Q (rows q0..q0+127)
    for (int i = tid; i < 1536; i += 256) {
        int r = i / 12, p = i % 12;
        uint4 v = *(const uint4*)(qb32 + (size_t)(q0 + r) * 1152 + p * 4);
        *(uint4*)&Qs[FSWZ(r, p)] = v;
    }

    float o[12][4] = {};
    float m0 = -1e30f, m1 = -1e30f, l0 = 0.f, l1 = 0.f;
    const float scale = 0.10206207261596577f;

    for (int t = 0; t < 8; t++) {
        __syncthreads();
        int kv0 = t * 128;
        for (int i = tid; i < 1536; i += 256) {
            int r = i / 12, p = i % 12;
            uint4 v = *(const uint4*)(kb32 + (size_t)(kv0 + r) * 1152 + p * 4);
            *(uint4*)&Ks[FSWZ(r, p)] = v;
            uint4 w = *(const uint4*)(vb32 + (size_t)(kv0 + r) * 1152 + p * 4);
            *(uint4*)&Vs[FSWZ(r, p)] = w;
        }
        __syncthreads();

        // S = Q @ K^T : per ks, 1 A-ldsm + 8 B-ldsm + 16 mma
        float s[16][4] = {};
#pragma unroll
        for (int ks = 0; ks < 6; ks++) {
            uint32_t a[4];
            ldsm4(a[0], a[1], a[2], a[3],
                  a_base + (((2 * ks + a_bit) ^ a_c) << 4));
#pragma unroll
            for (int nb = 0; nb < 8; nb++) {
                int brow = nb * 16 + b_rloc;
                uint32_t r0, r1, r2, r3;
                ldsm4(r0, r1, r2, r3,
                      ksb + brow * FROW * 4 + (((2 * ks + b_bit) ^ (brow & 7)) << 4));
                uint32_t b0[2] = {r0, r1}, b1[2] = {r2, r3};
                mma_bf16(s[2 * nb], a, b0);
                mma_bf16(s[2 * nb + 1], a, b1);
            }
        }

        // online softmax
        float mx0 = -1e30f, mx1 = -1e30f;
#pragma unroll
        for (int n = 0; n < 16; n++) {
            mx0 = fmaxf(mx0, fmaxf(s[n][0], s[n][1]));
            mx1 = fmaxf(mx1, fmaxf(s[n][2], s[n][3]));
        }
        mx0 = fmaxf(mx0, __shfl_xor_sync(~0u, mx0, 1));
        mx0 = fmaxf(mx0, __shfl_xor_sync(~0u, mx0, 2));
        mx1 = fmaxf(mx1, __shfl_xor_sync(~0u, mx1, 1));
        mx1 = fmaxf(mx1, __shfl_xor_sync(~0u, mx1, 2));
        float nm0 = fmaxf(m0, mx0 * scale);
        float nm1 = fmaxf(m1, mx1 * scale);
        float al0 = __expf(m0 - nm0), al1 = __expf(m1 - nm1);
        m0 = nm0; m1 = nm1;
        float sum0 = 0.f, sum1 = 0.f;
#pragma unroll
        for (int n = 0; n < 16; n++) {
            float p0 = __expf(s[n][0] * scale - nm0);
            float p1 = __expf(s[n][1] * scale - nm0);
            float p2 = __expf(s[n][2] * scale - nm1);
            float p3 = __expf(s[n][3] * scale - nm1);
            sum0 += p0 + p1; sum1 += p2 + p3;
            s[n][0] = p0; s[n][1] = p1; s[n][2] = p2; s[n][3] = p3;
        }
        sum0 += __shfl_xor_sync(~0u, sum0, 1);
        sum0 += __shfl_xor_sync(~0u, sum0, 2);
        sum1 += __shfl_xor_sync(~0u, sum1, 1);
        sum1 += __shfl_xor_sync(~0u, sum1, 2);
        l0 = l0 * al0 + sum0;
        l1 = l1 * al1 + sum1;
#pragma unroll
        for (int n = 0; n < 12; n++) {
            o[n][0] *= al0; o[n][1] *= al0;
            o[n][2] *= al1; o[n][3] *= al1;
        }

        // O += P @ V : per jb, 6 trans-ldsm + 12 mma
#pragma unroll
        for (int jb = 0; jb < 8; jb++) {
            uint32_t a[4];
            a[0] = pkbf(s[2 * jb][0], s[2 * jb][1]);
            a[1] = pkbf(s[2 * jb][2], s[2 * jb][3]);
            a[2] = pkbf(s[2 * jb + 1][0], s[2 * jb + 1][1]);
            a[3] = pkbf(s[2 * jb + 1][2], s[2 * jb + 1][3]);
            int vrow = jb * 16 + v_rloc;
            uint32_t v_base = vsb + vrow * FROW * 4;
#pragma unroll
            for (int u = 0; u < 6; u++) {
                uint32_t r0, r1, r2, r3;
                ldsm4t(r0, r1, r2, r3,
                       v_base + (((2 * u + v_bit) ^ v_c) << 4));
                uint32_t b0[2] = {r0, r1}, b1[2] = {r2, r3};
                mma_bf16(o[2 * u], a, b0);
                mma_bf16(o[2 * u + 1], a, b1);
            }
        }
    }

    float inv0 = 1.f / l0, inv1 = 1.f / l1;
    int row0 = q0 + wrow + grp;
#pragma unroll
    for (int n = 0; n < 12; n++) {
        int c = n * 8 + tig * 2;
        float f0 = fw[b * Cdim + h * Dd + c];
        float f1 = fw[b * Cdim + h * Dd + c + 1];
        size_t ob0 = ((size_t)b * Nseq + row0) * Cdim + h * Dd + c;
        size_t ob1 = ((size_t)b * Nseq + row0 + 8) * Cdim + h * Dd + c;
        float2 qv0 = *(const float2*)(qout + ob0);
        float2 qv1 = *(const float2*)(qout + ob1);
        fusedbf[ob0 >> 1] = pkbf(f0 * qv0.x + (1.f - f0) * o[n][0] * inv0,
                                 f1 * qv0.y + (1.f - f1) * o[n][1] * inv0);
        fusedbf[ob1 >> 1] = pkbf(f0 * qv1.x + (1.f - f0) * o[n][2] * inv1,
                                 f1 * qv1.y + (1.f - f1) * o[n][3] * inv1);
    }
}

// ================= quantum embed GEMM (bf16 A): H = relu(A @ W1 + b1) =================
__global__ __launch_bounds__(256)
void embed_gemm(const uint32_t* __restrict__ qkvbf,
                const float* __restrict__ qW1, const float* __restrict__ qb1,
                const float* __restrict__ kW1, const float* __restrict__ kb1,
                float* __restrict__ Hq, float* __restrict__ Hk) {
    __shared__ uint32_t As[2][8][136];
    __shared__ uint32_t Bs[48][72];
    int tid = threadIdx.x;
    int m0 = blockIdx.x * 128;
    int pass = blockIdx.y;
    const float* W1 = pass ? kW1 : qW1;
    const float* b1 = pass ? kb1 : qb1;
    float* H = pass ? Hk : Hq;
    int qk_off32 = pass * 384;

    for (int i = tid; i < 768; i += 256) {
        int k2 = i >> 4, c4 = i & 15;
        float4 w0 = *(const float4*)(W1 + (2 * k2) * 64 + c4 * 4);
        float4 w1 = *(const float4*)(W1 + (2 * k2 + 1) * 64 + c4 * 4);
        *(uint4*)&Bs[k2][c4 * 4] = make_uint4(pkbf(w0.x, w1.x), pkbf(w0.y, w1.y),
                                              pkbf(w0.z, w1.z), pkbf(w0.w, w1.w));
    }

    int arow = tid >> 1, apart = tid & 1;
    int mrow = m0 + arow;
    const uint4* Ap4 = (const uint4*)(qkvbf + (size_t)(mrow >> 3) * 1152 + qk_off32 + (mrow & 7) * 48);

    int wid = tid >> 5, lane = tid & 31;
    int wm = (wid >> 2) * 64, wn = (wid & 3) * 16;
    int grp = lane >> 2, tig = lane & 3;
    float acc[4][2][4] = {};

    {
        uint4 av = Ap4[apart];
        As[0][apart * 4 + 0][arow] = av.x;
        As[0][apart * 4 + 1][arow] = av.y;
        As[0][apart * 4 + 2][arow] = av.z;
        As[0][apart * 4 + 3][arow] = av.w;
    }
    __syncthreads();

    int buf = 0;
    for (int s = 1; s <= 6; s++) {
        bool more = (s < 6);
        uint4 av;
        if (more) av = Ap4[s * 2 + apart];
        int kb = (s - 1) * 8;
        uint32_t a[4][4], b[2][2];
#pragma unroll
        for (int mi = 0; mi < 4; mi++) {
            int r = wm + mi * 16 + grp;
            a[mi][0] = As[buf][tig][r];
            a[mi][1] = As[buf][tig][r + 8];
            a[mi][2] = As[buf][tig + 4][r];
            a[mi][3] = As[buf][tig + 4][r + 8];
        }
#pragma unroll
        for (int nj = 0; nj < 2; nj++) {
            int c = wn + nj * 8 + grp;
            b[nj][0] = Bs[kb + tig][c];
            b[nj][1] = Bs[kb + tig + 4][c];
        }
#pragma unroll
        for (int mi = 0; mi < 4; mi++)
#pragma unroll
            for (int nj = 0; nj < 2; nj++) mma_bf16(acc[mi][nj], a[mi], b[nj]);
        if (more) {
            As[buf ^ 1][apart * 4 + 0][arow] = av.x;
            As[buf ^ 1][apart * 4 + 1][arow] = av.y;
            As[buf ^ 1][apart * 4 + 2][arow] = av.z;
            As[buf ^ 1][apart * 4 + 3][arow] = av.w;
            __syncthreads();
            buf ^= 1;
        }
    }

#pragma unroll
    for (int nj = 0; nj < 2; nj++) {
        int c = wn + nj * 8 + tig * 2;
        float bi0 = __ldg(&b1[c]), bi1 = __ldg(&b1[c + 1]);
#pragma unroll
        for (int mi = 0; mi < 4; mi++) {
            size_t r = m0 + wm + mi * 16 + grp;
            *(float2*)(H + r * 64 + c) =
                make_float2(fmaxf(acc[mi][nj][0] + bi0, 0.f), fmaxf(acc[mi][nj][1] + bi1, 0.f));
            *(float2*)(H + (r + 8) * 64 + c) =
                make_float2(fmaxf(acc[mi][nj][2] + bi0, 0.f), fmaxf(acc[mi][nj][3] + bi1, 0.f));
        }
    }
}

// ================= quantum middle: e -> state -> meas =================
__global__ __launch_bounds__(128)
void quantum_mid(const float* __restrict__ Hq, const float* __restrict__ Hk,
                 const float* __restrict__ qe_w2, const float* __restrict__ qe_b2,
                 const float* __restrict__ ke_w2, const float* __restrict__ ke_b2,
                 const float* __restrict__ gate_params, const float* __restrict__ ent_params,
                 const float* __restrict__ gumbel, float* __restrict__ meas_out) {
    __shared__ float w2q[1024], w2k[1024];
    __shared__ float gf[2][8], gcz[2][8], gsz[2][8], gs[2][8];
    int tid = threadIdx.x;
    for (int i = tid; i < 256; i += 128) {
        ((float4*)w2q)[i] = ((const float4*)qe_w2)[i];
        ((float4*)w2k)[i] = ((const float4*)ke_w2)[i];
    }
    if (tid < 16) {
        int l = tid >> 3, i = tid & 7;
        float ry = gate_params[(l * 8 + i) * 3 + 1];
        float rz = gate_params[(l * 8 + i) * 3 + 2];
        gf[l][i] = cosf(0.5f * ry);
        gcz[l][i] = cosf(rz);
        gsz[l][i] = sinf(rz);
    } else if (tid < 30) {
        int t = tid - 16, l = t / 7, i = t % 7;
        gs[l][i + 1] = 1.f / (1.f + expf(-ent_params[l * 7 + i]));
    }
    __syncthreads();

    int m = blockIdx.x * 128 + tid;
    float sre[8], sim[8];

#pragma unroll
    for (int pass = 0; pass < 2; pass++) {
        const float* Hrow = (pass == 0 ? Hq : Hk) + (size_t)m * 64;
        const float* w2 = (pass == 0 ? w2q : w2k);
        const float* b2 = (pass == 0 ? qe_b2 : ke_b2);
        float e[16];
#pragma unroll
        for (int i = 0; i < 16; i++) e[i] = __ldg(&b2[i]);
        const float4* h4 = (const float4*)Hrow;
#pragma unroll
        for (int j4 = 0; j4 < 16; j4++) {
            float4 hv = h4[j4];
            float hs[4] = {hv.x, hv.y, hv.z, hv.w};
#pragma unroll
            for (int s = 0; s < 4; s++) {
                float hj = hs[s];
                const float4* wr = (const float4*)&w2[(j4 * 4 + s) * 16];
#pragma unroll
                for (int i4 = 0; i4 < 4; i4++) {
                    float4 w = wr[i4];
                    e[i4 * 4 + 0] += hj * w.x; e[i4 * 4 + 1] += hj * w.y;
                    e[i4 * 4 + 2] += hj * w.z; e[i4 * 4 + 3] += hj * w.w;
                }
            }
        }
        float mx = e[0];
#pragma unroll
        for (int i = 1; i < 8; i++) mx = fmaxf(mx, e[i]);
        float ex[8], ssum = 0.f;
#pragma unroll
        for (int i = 0; i < 8; i++) { ex[i] = __expf(e[i] - mx); ssum += ex[i]; }
        float inv = 1.f / ssum;
#pragma unroll
        for (int i = 0; i < 8; i++) {
            float amp = ex[i] * inv;
            float cr = amp * __cosf(e[8 + i]), ci = amp * __sinf(e[8 + i]);
            if (pass == 0) { sre[i] = cr; sim[i] = ci; }
            else           { sre[i] += cr; sim[i] += ci; }
        }
    }

#pragma unroll
    for (int l = 0; l < 2; l++) {
#pragma unroll
        for (int i = 0; i < 8; i++) {
            float nr = sre[i] * gcz[l][i] - sim[i] * gsz[l][i];
            float ni = sre[i] * gsz[l][i] + sim[i] * gcz[l][i];
            sre[i] = nr * gf[l][i];
            sim[i] = ni * gf[l][i];
        }
#pragma unroll
        for (int i = 7; i >= 1; i--) {
            sre[i] += gs[l][i] * sre[i - 1];
            sim[i] += gs[l][i] * sim[i - 1];
        }
    }

    float p[8], mx = -1e30f;
#pragma unroll
    for (int i = 0; i < 8; i++) { p[i] = sre[i] * sre[i] + sim[i] * sim[i]; mx = fmaxf(mx, p[i]); }
    float ssum = 0.f;
#pragma unroll
    for (int i = 0; i < 8; i++) { p[i] = __expf(p[i] - mx); ssum += p[i]; }
    float sinv = 1.f / ssum;
    int b = m >> 13, n = (m >> 3) & 1023, h = m & 7;
    size_t goff = (size_t)(((b * 8 + h) << 10) + n) * 8;
    float4 g0 = __ldg((const float4*)(gumbel + goff));
    float4 g1 = __ldg((const float4*)(gumbel + goff + 4));
    float gv[8] = {g0.x, g0.y, g0.z, g0.w, g1.x, g1.y, g1.z, g1.w};
    float lg[8], mx2 = -1e30f;
#pragma unroll
    for (int i = 0; i < 8; i++) {
        lg[i] = 2.f * (__logf(p[i] * sinv + 1e-10f) + gv[i]);
        mx2 = fmaxf(mx2, lg[i]);
    }
    float meas[8], msum = 0.f;
#pragma unroll
    for (int i = 0; i < 8; i++) { meas[i] = __expf(lg[i] - mx2); msum += meas[i]; }
    float minv = 1.f / msum;
    float4 o0 = make_float4(meas[0] * minv, meas[1] * minv, meas[2] * minv, meas[3] * minv);
    float4 o1 = make_float4(meas[4] * minv, meas[5] * minv, meas[6] * minv, meas[7] * minv);
    *(float4*)(meas_out + (size_t)m * 8) = o0;
    *(float4*)(meas_out + (size_t)m * 8 + 4) = o1;
}

// ================= fused measure MLP (tf32): qout = (relu(meas@W1+b1)@W2+b2)*v =================
#define MD_T1_LD 136
#define MD_W2_LD 104
#define MD_SMEM ((8 * 136 + 8 * 72 + 64 * MD_T1_LD + 64 * MD_W2_LD) * 4)

__global__ __launch_bounds__(256)
void md_fused(const float* __restrict__ meas,
              const float* __restrict__ W1, const float* __restrict__ b1,
              const float* __restrict__ W2, const float* __restrict__ b2,
              const uint32_t* __restrict__ qkvbf, float* __restrict__ qout) {
    extern __shared__ float sm[];
    float* As8 = sm;
    float* W1s = sm + 8 * 136;
    float* T1  = sm + 8 * 136 + 8 * 72;
    float* W2s = T1 + 64 * MD_T1_LD;

    int tid = threadIdx.x;
    int m0 = blockIdx.x * 128;
    int wid = tid >> 5, lane = tid & 31;
    int grp = lane >> 2, tig = lane & 3;
    int wm = (wid >> 2) * 64;

    {
        int arow = tid >> 1, ak = (tid & 1) * 4;
        float4 v = *(const float4*)(meas + (size_t)(m0 + arow) * 8 + ak);
        As8[(ak + 0) * 136 + arow] = to_tf32(v.x);
        As8[(ak + 1) * 136 + arow] = to_tf32(v.y);
        As8[(ak + 2) * 136 + arow] = to_tf32(v.z);
        As8[(ak + 3) * 136 + arow] = to_tf32(v.w);
    }
    for (int i = tid; i < 128; i += 256) {
        int d = i >> 4, n4 = i & 15;
        float4 w = ((const float4*)W1)[i];
        float4 wc = make_float4(to_tf32(w.x), to_tf32(w.y), to_tf32(w.z), to_tf32(w.w));
        *(float4*)&W1s[d * 72 + n4 * 4] = wc;
    }
    for (int i = tid; i < 1536; i += 256) {
        int d = i / 24, n4 = i % 24;
        float4 w = ((const float4*)W2)[i];
        float4 wc = make_float4(to_tf32(w.x), to_tf32(w.y), to_tf32(w.z), to_tf32(w.w));
        *(float4*)&W2s[d * MD_W2_LD + n4 * 4] = wc;
    }
    __syncthreads();

    {
        int wn1 = (wid & 3) * 16;
        float acc1[4][2][4] = {};
        uint32_t a[4][4], b[2][2];
#pragma unroll
        for (int mi = 0; mi < 4; mi++) {
            int r = wm + mi * 16 + grp;
            a[mi][0] = __float_as_uint(As8[tig * 136 + r]);
            a[mi][1] = __float_as_uint(As8[tig * 136 + r + 8]);
            a[mi][2] = __float_as_uint(As8[(tig + 4) * 136 + r]);
            a[mi][3] = __float_as_uint(As8[(tig + 4) * 136 + r + 8]);
        }
#pragma unroll
        for (int nj = 0; nj < 2; nj++) {
            int c = wn1 + nj * 8 + grp;
            b[nj][0] = __float_as_uint(W1s[tig * 72 + c]);
            b[nj][1] = __float_as_uint(W1s[(tig + 4) * 72 + c]);
        }
#pragma unroll
        for (int mi = 0; mi < 4; mi++)
#pragma unroll
            for (int nj = 0; nj < 2; nj++) mma_tf32(acc1[mi][nj], a[mi], b[nj]);

#pragma unroll
        for (int nj = 0; nj < 2; nj++) {
            int c = wn1 + nj * 8 + tig * 2;
            float bi0 = __ldg(&b1[c]), bi1 = __ldg(&b1[c + 1]);
#pragma unroll
            for (int mi = 0; mi < 4; mi++) {
                int r = wm + mi * 16 + grp;
                T1[c * MD_T1_LD + r]           = to_tf32(fmaxf(acc1[mi][nj][0] + bi0, 0.f));
                T1[(c + 1) * MD_T1_LD + r]     = to_tf32(fmaxf(acc1[mi][nj][1] + bi1, 0.f));
                T1[c * MD_T1_LD + r + 8]       = to_tf32(fmaxf(acc1[mi][nj][2] + bi0, 0.f));
                T1[(c + 1) * MD_T1_LD + r + 8] = to_tf32(fmaxf(acc1[mi][nj][3] + bi1, 0.f));
            }
        }
    }
    __syncthreads();

    int wn = (wid & 3) * 24;
    float acc2[4][3][4] = {};
#pragma unroll
    for (int ks = 0; ks < 8; ks++) {
        uint32_t a[4][4], b[3][2];
#pragma unroll
        for (int mi = 0; mi < 4; mi++) {
            int r = wm + mi * 16 + grp;
            a[mi][0] = __float_as_uint(T1[(ks * 8 + tig) * MD_T1_LD + r]);
            a[mi][1] = __float_as_uint(T1[(ks * 8 + tig) * MD_T1_LD + r + 8]);
            a[mi][2] = __float_as_uint(T1[(ks * 8 + tig + 4) * MD_T1_LD + r]);
            a[mi][3] = __float_as_uint(T1[(ks * 8 + tig + 4) * MD_T1_LD + r + 8]);
        }
#pragma unroll
        for (int nj = 0; nj < 3; nj++) {
            int c = wn + nj * 8 + grp;
            b[nj][0] = __float_as_uint(W2s[(ks * 8 + tig) * MD_W2_LD + c]);
            b[nj][1] = __float_as_uint(W2s[(ks * 8 + tig + 4) * MD_W2_LD + c]);
        }
#pragma unroll
        for (int mi = 0; mi < 4; mi++)
#pragma unroll
            for (int nj = 0; nj < 3; nj++) mma_tf32(acc2[mi][nj], a[mi], b[nj]);
    }

#pragma unroll
    for (int nj = 0; nj < 3; nj++) {
        int c = wn + nj * 8 + tig * 2;
        float bi0 = __ldg(&b2[c]), bi1 = __ldg(&b2[c + 1]);
#pragma unroll
        for (int mi = 0; mi < 4; mi++) {
            int m = m0 + wm + mi * 16 + grp;
#pragma unroll
            for (int half = 0; half < 2; half++) {
                int mm = m + half * 8;
                size_t qrow = (size_t)(mm >> 3);
                int hh = mm & 7;
                uint32_t u = qkvbf[(qrow * 2304 + 1536 + hh * 96 + c) >> 1];
                float2 vv = __bfloat1622float2(*(__nv_bfloat162*)&u);
                float o0 = (acc2[mi][nj][half * 2 + 0] + bi0) * vv.x;
                float o1 = (acc2[mi][nj][half * 2 + 1] + bi1) * vv.y;
                *(float2*)(qout + qrow * 768 + hh * 96 + c) = make_float2(o0, o1);
            }
        }
    }
}

// ================= mean over N =================
__global__ void colmean_kernel(const float* __restrict__ x, float* __restrict__ xmean) {
    int b = blockIdx.y;
    int c = blockIdx.x * 256 + threadIdx.x;
    const float* p = x + (size_t)b * Nseq * Cdim + c;
    float s = 0.f;
    for (int n = 0; n < Nseq; n++) s += p[(size_t)n * Cdim];
    xmean[b * Cdim + c] = s * (1.0f / 1024.0f);
}

// ================= fw = sigmoid(xmean @ w_proj + b_proj) =================
__global__ void fw_kernel(const float* __restrict__ xmean, const float* __restrict__ w_proj,
                          const float* __restrict__ b_proj, float* __restrict__ fw) {
    __shared__ float xm[768];
    int b = blockIdx.x;
    int c = threadIdx.x;
    xm[c] = xmean[b * Cdim + c];
    __syncthreads();
    float s = b_proj[c];
    for (int k = 0; k < 768; k++) s += xm[k] * w_proj[(size_t)k * 768 + c];
    fw[b * Cdim + c] = 1.f / (1.f + expf(-s));
}

// ================= layernorm =================
__global__ void layernorm_kernel(const float* __restrict__ y, const float* __restrict__ gamma,
                                 const float* __restrict__ beta, float* __restrict__ out) {
    __shared__ float red1[8], red2[8];
    size_t row = blockIdx.x;
    const float* p = y + row * Cdim;
    int tid = threadIdx.x;
    float v[3];
    float s = 0.f;
#pragma unroll
    for (int i = 0; i < 3; i++) { v[i] = p[tid + i * 256]; s += v[i]; }
#pragma unroll
    for (int o = 16; o > 0; o >>= 1) s += __shfl_xor_sync(~0u, s, o);
    int w = tid >> 5, lane = tid & 31;
    if (lane == 0) red1[w] = s;
    __syncthreads();
    s = 0.f;
#pragma unroll
    for (int i = 0; i < 8; i++) s += red1[i];
    float mu = s * (1.0f / 768.0f);
    float vs = 0.f;
#pragma unroll
    for (int i = 0; i < 3; i++) { float d = v[i] - mu; vs += d * d; }
#pragma unroll
    for (int o = 16; o > 0; o >>= 1) vs += __shfl_xor_sync(~0u, vs, o);
    if (lane == 0) red2[w] = vs;
    __syncthreads();
    vs = 0.f;
#pragma unroll
    for (int i = 0; i < 8; i++) vs += red2[i];
    float inv = rsqrtf(vs * (1.0f / 768.0f) + 1e-5f);
#pragma unroll
    for (int i = 0; i < 3; i++) {
        int c = tid + i * 256;
        out[row * Cdim + c] = (v[i] - mu) * inv * gamma[c] + beta[c];
    }
}

// ================= launch =================
extern "C" void kernel_launch(void* const* d_in, const int* in_sizes, int n_in,
                              void* d_out, int out_size) {
    const float* x      = (const float*)d_in[0];
    const float* w_qkv  = (const float*)d_in[1];
    const float* b_qkv  = (const float*)d_in[2];
    const float* w_proj = (const float*)d_in[3];
    const float* b_proj = (const float*)d_in[4];
    const float* gamma  = (const float*)d_in[5];
    const float* beta   = (const float*)d_in[6];
    const float* qe_w1  = (const float*)d_in[7];
    const float* qe_b1  = (const float*)d_in[8];
    const float* qe_w2  = (const float*)d_in[9];
    const float* qe_b2  = (const float*)d_in[10];
    const float* ke_w1  = (const float*)d_in[11];
    const float* ke_b1  = (const float*)d_in[12];
    const float* ke_w2  = (const float*)d_in[13];
    const float* ke_b2  = (const float*)d_in[14];
    const float* gate_params = (const float*)d_in[19];
    const float* ent_params  = (const float*)d_in[20];
    const float* md_w1  = (const float*)d_in[21];
    const float* md_b1  = (const float*)d_in[22];
    const float* md_w2  = (const float*)d_in[23];
    const float* md_b2  = (const float*)d_in[24];
    const float* gumbel = (const float*)d_in[25];
    float* out = (float*)d_out;

    uint32_t *qkvbf, *fusedbf;
    float *qout, *y, *xmean, *fw, *hq, *hk, *meas;
    cudaGetSymbolAddress((void**)&qkvbf, g_qkv_bf);
    cudaGetSymbolAddress((void**)&fusedbf, g_fused_bf);
    cudaGetSymbolAddress((void**)&qout, g_qout);
    cudaGetSymbolAddress((void**)&y, g_y);
    cudaGetSymbolAddress((void**)&xmean, g_xmean);
    cudaGetSymbolAddress((void**)&fw, g_fw);
    cudaGetSymbolAddress((void**)&hq, g_hq);
    cudaGetSymbolAddress((void**)&hk, g_hk);
    cudaGetSymbolAddress((void**)&meas, g_meas);

    cudaFuncSetAttribute(flash_kernel, cudaFuncAttributeMaxDynamicSharedMemorySize, FLASH_SMEM);
    cudaFuncSetAttribute(md_fused, cudaFuncAttributeMaxDynamicSharedMemorySize, MD_SMEM);

    // gate path (depends only on x)
    colmean_kernel<<<dim3(3, 8), 256>>>(x, xmean);
    fw_kernel<<<8, 768>>>(xmean, w_proj, b_proj, fw);
    // qkv = x @ w_qkv + b_qkv  -> bf16
    mma_qkv<<<dim3(2304 / 128, 8192 / 128), 256>>>(x, w_qkv, b_qkv, qkvbf,
                                                   768, 768, 2304, 2304);
    // quantum path: embeds (GEMM) -> mid -> measure MLP (GEMM) -> qout
    embed_gemm<<<dim3(NTOK / 128, 2), 256>>>(qkvbf, qe_w1, qe_b1, ke_w1, ke_b1, hq, hk);
    quantum_mid<<<NTOK / 128, 128>>>(hq, hk, qe_w2, qe_b2, ke_w2, ke_b2,
                                     gate_params, ent_params, gumbel, meas);
    md_fused<<<NTOK / 128, 256, MD_SMEM>>>(meas, md_w1, md_b1, md_w2, md_b2, qkvbf, qout);
    // fused classical attention + gate blend -> fused (bf16)
    flash_kernel<<<dim3(8, 64), 256, FLASH_SMEM>>>(qkvbf, qout, fw, fusedbf);
    // y = x + fused @ w_proj + b_proj
    mma_proj<<<dim3(768 / 128, 8192 / 128), 256>>>(fusedbf, w_proj, b_proj, x, y,
                                                   768, 768, 768, 768);
    // layernorm
    layernorm_kernel<<<8192, 256>>>(y, gamma, beta, out);
}

// round 13
// speedup vs baseline: 1.4971x; 1.1865x over previous
#include <cuda_runtime.h>
#include <cuda_bf16.h>
#include <math.h>
#include <stdint.h>

// ---------------- scratch ----------------
#define Bsz 8
#define Nseq 1024
#define Cdim 768
#define Hh 8
#define Dd 96
#define Qq 8
#define NTOK (Bsz * Hh * Nseq)   // 65536, ordered m=(b,n,h)

__device__ uint32_t g_qkv_bf[Bsz * Nseq * 3 * Cdim / 2];   // bf16x2
__device__ uint32_t g_fused_bf[Bsz * Nseq * Cdim / 2];     // bf16x2
__device__ float g_qout[Bsz * Nseq * Cdim];
__device__ float g_y[Bsz * Nseq * Cdim];
__device__ float g_xmean[Bsz * Cdim];
__device__ float g_fw[Bsz * Cdim];
__device__ float g_hq[NTOK * 64];
__device__ float g_hk[NTOK * 64];
__device__ float g_meas[NTOK * 8];

// ---------------- mma helpers ----------------
__device__ __forceinline__ float to_tf32(float x) {
    uint32_t u;
    asm("cvt.rna.tf32.f32 %0, %1;" : "=r"(u) : "f"(x));
    return __uint_as_float(u);
}

__device__ __forceinline__ uint32_t pkbf(float x, float y) {
    __nv_bfloat162 t = __floats2bfloat162_rn(x, y);
    return *(uint32_t*)&t;
}

__device__ __forceinline__ void mma_tf32(float* c, const uint32_t* a, const uint32_t* b) {
    asm volatile(
        "mma.sync.aligned.m16n8k8.row.col.f32.tf32.tf32.f32 "
        "{%0,%1,%2,%3}, {%4,%5,%6,%7}, {%8,%9}, {%0,%1,%2,%3};"
        : "+f"(c[0]), "+f"(c[1]), "+f"(c[2]), "+f"(c[3])
        : "r"(a[0]), "r"(a[1]), "r"(a[2]), "r"(a[3]), "r"(b[0]), "r"(b[1]));
}

__device__ __forceinline__ void mma_bf16(float* c, const uint32_t* a, const uint32_t* b) {
    asm volatile(
        "mma.sync.aligned.m16n8k16.row.col.f32.bf16.bf16.f32 "
        "{%0,%1,%2,%3}, {%4,%5,%6,%7}, {%8,%9}, {%0,%1,%2,%3};"
        : "+f"(c[0]), "+f"(c[1]), "+f"(c[2]), "+f"(c[3])
        : "r"(a[0]), "r"(a[1]), "r"(a[2]), "r"(a[3]), "r"(b[0]), "r"(b[1]));
}

__device__ __forceinline__ void ldsm4(uint32_t& r0, uint32_t& r1, uint32_t& r2, uint32_t& r3,
                                      uint32_t addr) {
    asm volatile("ldmatrix.sync.aligned.m8n8.x4.shared.b16 {%0,%1,%2,%3}, [%4];"
                 : "=r"(r0), "=r"(r1), "=r"(r2), "=r"(r3) : "r"(addr));
}

__device__ __forceinline__ void ldsm4t(uint32_t& r0, uint32_t& r1, uint32_t& r2, uint32_t& r3,
                                       uint32_t addr) {
    asm volatile("ldmatrix.sync.aligned.m8n8.x4.trans.shared.b16 {%0,%1,%2,%3}, [%4];"
                 : "=r"(r0), "=r"(r1), "=r"(r2), "=r"(r3) : "r"(addr));
}

__device__ __forceinline__ void cpa16(uint32_t smem, const void* g) {
    asm volatile("cp.async.cg.shared.global [%0], [%1], 16;" :: "r"(smem), "l"(g));
}
__device__ __forceinline__ void cp_commit() {
    asm volatile("cp.async.commit_group;");
}
template <int N>
__device__ __forceinline__ void cp_wait() {
    asm volatile("cp.async.wait_group %0;" :: "n"(N));
}

// XOR-swizzled tile (GEMM): [128 rows][8 u32]; part swapped on (row>>2)&1.
#define SWZ(row, part) ((row) * 8 + (((part) ^ (((row) >> 2) & 1)) * 4))
#define TILE_U32 (128 * 8)
#define TILE_B (TILE_U32 * 4)

// ================= qkv GEMM: A fp32, B fp32, out bf16 =================
__global__ __launch_bounds__(256)
void mma_qkv(const float* __restrict__ A, const float* __restrict__ B,
             const float* __restrict__ bias, uint32_t* __restrict__ Cbf,
             int K, int lda, int ldb, int ldc) {
    __shared__ uint32_t As[2][TILE_U32];
    __shared__ uint32_t Bs[2][TILE_U32];
    int tid = threadIdx.x;
    int m0 = blockIdx.y * 128, n0 = blockIdx.x * 128;
    int arow = tid >> 1, apart = tid & 1;
    const float* Ap = A + (size_t)(m0 + arow) * lda + apart * 8;
    uint32_t a_st = SWZ(arow, apart);
    int bcol = tid & 127, bpart = tid >> 7;
    const float* Bp = B + (size_t)(bpart * 8) * ldb + n0 + bcol;
    uint32_t b_st = SWZ(bcol, bpart);

    int wid = tid >> 5, lane = tid & 31;
    int wm = (wid >> 2) * 64, wn = (wid & 3) * 32;
    int grp = lane >> 2, tig = lane & 3;
    float acc[4][4][4] = {};

    uint32_t asb = (uint32_t)__cvta_generic_to_shared(&As[0][0]);
    uint32_t bsb = (uint32_t)__cvta_generic_to_shared(&Bs[0][0]);
    uint32_t a_off[4], b_off[2];
#pragma unroll
    for (int mi = 0; mi < 4; mi++) {
        int r = wm + mi * 16 + (lane & 15);
        a_off[mi] = SWZ(r, lane >> 4) * 4;
    }
#pragma unroll
    for (int nb = 0; nb < 2; nb++) {
        int r = wn + nb * 16 + (lane & 7) + ((lane >> 4) << 3);
        b_off[nb] = SWZ(r, (lane >> 3) & 1) * 4;
    }

    {
        float4 a0 = *(const float4*)Ap;
        float4 a1 = *(const float4*)(Ap + 4);
        *(uint4*)&As[0][a_st] =
            make_uint4(pkbf(a0.x, a0.y), pkbf(a0.z, a0.w), pkbf(a1.x, a1.y), pkbf(a1.z, a1.w));
        float bv[8];
#pragma unroll
        for (int j = 0; j < 8; j++) bv[j] = Bp[(size_t)j * ldb];
        *(uint4*)&Bs[0][b_st] =
            make_uint4(pkbf(bv[0], bv[1]), pkbf(bv[2], bv[3]), pkbf(bv[4], bv[5]), pkbf(bv[6], bv[7]));
    }
    __syncthreads();

    int S = K / 16, buf = 0;
    for (int s = 1; s <= S; s++) {
        bool more = (s < S);
        float4 a0, a1;
        float bv[8];
        if (more) {
            int k0 = s * 16;
            a0 = *(const float4*)(Ap + k0);
            a1 = *(const float4*)(Ap + k0 + 4);
#pragma unroll
            for (int j = 0; j < 8; j++) bv[j] = Bp[(size_t)(k0 + j) * ldb];
        }
        uint32_t a[4][4], b[4][2];
        uint32_t ab = asb + buf * TILE_B, bb = bsb + buf * TILE_B;
#pragma unroll
        for (int mi = 0; mi < 4; mi++)
            ldsm4(a[mi][0], a[mi][1], a[mi][2], a[mi][3], ab + a_off[mi]);
#pragma unroll
        for (int nb = 0; nb < 2; nb++) {
            uint32_t r0, r1, r2, r3;
            ldsm4(r0, r1, r2, r3, bb + b_off[nb]);
            b[2 * nb][0] = r0; b[2 * nb][1] = r1;
            b[2 * nb + 1][0] = r2; b[2 * nb + 1][1] = r3;
        }
#pragma unroll
        for (int mi = 0; mi < 4; mi++)
#pragma unroll
            for (int nj = 0; nj < 4; nj++) mma_bf16(acc[mi][nj], a[mi], b[nj]);
        if (more) {
            *(uint4*)&As[buf ^ 1][a_st] =
                make_uint4(pkbf(a0.x, a0.y), pkbf(a0.z, a0.w), pkbf(a1.x, a1.y), pkbf(a1.z, a1.w));
            *(uint4*)&Bs[buf ^ 1][b_st] =
                make_uint4(pkbf(bv[0], bv[1]), pkbf(bv[2], bv[3]), pkbf(bv[4], bv[5]), pkbf(bv[6], bv[7]));
            __syncthreads();
            buf ^= 1;
        }
    }

#pragma unroll
    for (int nj = 0; nj < 4; nj++) {
        int c = n0 + wn + nj * 8 + tig * 2;
        float bi0 = bias[c], bi1 = bias[c + 1];
#pragma unroll
        for (int mi = 0; mi < 4; mi++) {
            size_t r = m0 + wm + mi * 16 + grp;
            Cbf[(r * ldc + c) >> 1] = pkbf(acc[mi][nj][0] + bi0, acc[mi][nj][1] + bi1);
            Cbf[((r + 8) * ldc + c) >> 1] = pkbf(acc[mi][nj][2] + bi0, acc[mi][nj][3] + bi1);
        }
    }
}

// ================= proj GEMM: A bf16, B fp32, out fp32 + resid =================
__global__ __launch_bounds__(256)
void mma_proj(const uint32_t* __restrict__ Abf, const float* __restrict__ B,
              const float* __restrict__ bias, const float* __restrict__ resid,
              float* __restrict__ C, int K, int lda, int ldb, int ldc) {
    __shared__ uint32_t As[2][TILE_U32];
    __shared__ uint32_t Bs[2][TILE_U32];
    int tid = threadIdx.x;
    int m0 = blockIdx.y * 128, n0 = blockIdx.x * 128;
    int arow = tid >> 1, apart = tid & 1;
    const uint4* Ap4 = (const uint4*)(Abf + (size_t)(m0 + arow) * (lda / 2)) + apart;
    uint32_t a_st = SWZ(arow, apart);
    int bcol = tid & 127, bpart = tid >> 7;
    const float* Bp = B + (size_t)(bpart * 8) * ldb + n0 + bcol;
    uint32_t b_st = SWZ(bcol, bpart);

    int wid = tid >> 5, lane = tid & 31;
    int wm = (wid >> 2) * 64, wn = (wid & 3) * 32;
    int grp = lane >> 2, tig = lane & 3;
    float acc[4][4][4] = {};

    uint32_t asb = (uint32_t)__cvta_generic_to_shared(&As[0][0]);
    uint32_t bsb = (uint32_t)__cvta_generic_to_shared(&Bs[0][0]);
    uint32_t a_off[4], b_off[2];
#pragma unroll
    for (int mi = 0; mi < 4; mi++) {
        int r = wm + mi * 16 + (lane & 15);
        a_off[mi] = SWZ(r, lane >> 4) * 4;
    }
#pragma unroll
    for (int nb = 0; nb < 2; nb++) {
        int r = wn + nb * 16 + (lane & 7) + ((lane >> 4) << 3);
        b_off[nb] = SWZ(r, (lane >> 3) & 1) * 4;
    }

    {
        *(uint4*)&As[0][a_st] = Ap4[0];
        float bv[8];
#pragma unroll
        for (int j = 0; j < 8; j++) bv[j] = Bp[(size_t)j * ldb];
        *(uint4*)&Bs[0][b_st] =
            make_uint4(pkbf(bv[0], bv[1]), pkbf(bv[2], bv[3]), pkbf(bv[4], bv[5]), pkbf(bv[6], bv[7]));
    }
    __syncthreads();

    int S = K / 16, buf = 0;
    for (int s = 1; s <= S; s++) {
        bool more = (s < S);
        uint4 av;
        float bv[8];
        if (more) {
            av = Ap4[s * 2];
            int k0 = s * 16;
#pragma unroll
            for (int j = 0; j < 8; j++) bv[j] = Bp[(size_t)(k0 + j) * ldb];
        }
        uint32_t a[4][4], b[4][2];
        uint32_t ab = asb + buf * TILE_B, bb = bsb + buf * TILE_B;
#pragma unroll
        for (int mi = 0; mi < 4; mi++)
            ldsm4(a[mi][0], a[mi][1], a[mi][2], a[mi][3], ab + a_off[mi]);
#pragma unroll
        for (int nb = 0; nb < 2; nb++) {
            uint32_t r0, r1, r2, r3;
            ldsm4(r0, r1, r2, r3, bb + b_off[nb]);
            b[2 * nb][0] = r0; b[2 * nb][1] = r1;
            b[2 * nb + 1][0] = r2; b[2 * nb + 1][1] = r3;
        }
#pragma unroll
        for (int mi = 0; mi < 4; mi++)
#pragma unroll
            for (int nj = 0; nj < 4; nj++) mma_bf16(acc[mi][nj], a[mi], b[nj]);
        if (more) {
            *(uint4*)&As[buf ^ 1][a_st] = av;
            *(uint4*)&Bs[buf ^ 1][b_st] =
                make_uint4(pkbf(bv[0], bv[1]), pkbf(bv[2], bv[3]), pkbf(bv[4], bv[5]), pkbf(bv[6], bv[7]));
            __syncthreads();
            buf ^= 1;
        }
    }

#pragma unroll
    for (int nj = 0; nj < 4; nj++) {
        int c = n0 + wn + nj * 8 + tig * 2;
        float bi0 = bias[c], bi1 = bias[c + 1];
#pragma unroll
        for (int mi = 0; mi < 4; mi++) {
            size_t r = m0 + wm + mi * 16 + grp;
            float2 r0 = *(const float2*)(resid + r * ldc + c);
            float2 r1 = *(const float2*)(resid + (r + 8) * ldc + c);
            *(float2*)(C + r * ldc + c) =
                make_float2(acc[mi][nj][0] + bi0 + r0.x, acc[mi][nj][1] + bi1 + r0.y);
            *(float2*)(C + (r + 8) * ldc + c) =
                make_float2(acc[mi][nj][2] + bi0 + r1.x, acc[mi][nj][3] + bi1 + r1.y);
        }
    }
}

// ================= fused flash attention (ldmatrix + cp.async pipeline) =================
// Tiles: [128 rows][64 u32 padded], data groups p=0..11, swizzle p' = p ^ (row&7).
// K/V double-buffered via cp.async.
#define FROW 64
#define FSWZ(row, p) ((row) * FROW + (((p) ^ ((row) & 7)) << 2))
#define FTILE_U32 (128 * FROW)
#define FTILE_B (FTILE_U32 * 4)
#define FLASH_SMEM (5 * FTILE_B)

__global__ __launch_bounds__(256, 1)
void flash_kernel(const uint32_t* __restrict__ qkvbf, const float* __restrict__ qout,
                  const float* __restrict__ fw, uint32_t* __restrict__ fusedbf) {
    extern __shared__ uint32_t smu[];
    uint32_t* Qs = smu;                       // [FTILE_U32]
    // K buffers at +1F,+2F ; V buffers at +3F,+4F

    int tid = threadIdx.x;
    int z = blockIdx.y;
    int b = z >> 3, h = z & 7;
    int q0 = blockIdx.x * 128;
    const uint32_t* qb32 = qkvbf + (size_t)b * Nseq * 1152 + h * 48;
    const uint32_t* kb32 = qb32 + 384;
    const uint32_t* vb32 = qb32 + 768;

    int lane = tid & 31, wid = tid >> 5;
    int grp = lane >> 2, tig = lane & 3;
    int wrow = wid * 16;

    uint32_t qsb = (uint32_t)__cvta_generic_to_shared(Qs);
    uint32_t ksb = qsb + FTILE_B;             // buffer 0; buffer 1 at +FTILE_B
    uint32_t vsb = qsb + 3 * FTILE_B;

    // precomputed fragment address components
    int a_row = wrow + (lane & 15);
    int a_bit = lane >> 4;
    uint32_t a_base = qsb + a_row * FROW * 4;
    int a_c = a_row & 7;
    int b_rloc = (lane & 7) + ((lane >> 4) << 3);
    int b_bit = (lane >> 3) & 1;
    int v_rloc = (lane & 7) + (((lane >> 3) & 1) << 3);
    int v_bit = lane >> 4;
    int v_c = v_rloc & 7;

    // per-thread staging coords (6 chunks of K + 6 of V per tile)
    int st_r[6], st_p[6];
    uint32_t st_sw[6];
#pragma unroll
    for (int j = 0; j < 6; j++) {
        int i = tid + j * 256;
        st_r[j] = i / 12; st_p[j] = i % 12;
        st_sw[j] = FSWZ(st_r[j], st_p[j]) * 4;
    }

    // stage Q (regular stores) + prefetch KV tile 0
    for (int i = tid; i < 1536; i += 256) {
        int r = i / 12, p = i % 12;
        uint4 v = *(const uint4*)(qb32 + (size_t)(q0 + r) * 1152 + p * 4);
        *(uint4*)&Qs[FSWZ(r, p)] = v;
    }
#pragma unroll
    for (int j = 0; j < 6; j++) {
        cpa16(ksb + st_sw[j], kb32 + (size_t)st_r[j] * 1152 + st_p[j] * 4);
        cpa16(vsb + st_sw[j], vb32 + (size_t)st_r[j] * 1152 + st_p[j] * 4);
    }
    cp_commit();

    float o[12][4] = {};
    float m0 = -1e30f, m1 = -1e30f, l0 = 0.f, l1 = 0.f;
    const float scale = 0.10206207261596577f;

    int buf = 0;
    for (int t = 0; t < 8; t++) {
        if (t < 7) {
            int kv1 = (t + 1) * 128;
            uint32_t kd = ksb + (buf ^ 1) * FTILE_B;
            uint32_t vd = vsb + (buf ^ 1) * FTILE_B;
#pragma unroll
            for (int j = 0; j < 6; j++) {
                cpa16(kd + st_sw[j], kb32 + (size_t)(kv1 + st_r[j]) * 1152 + st_p[j] * 4);
                cpa16(vd + st_sw[j], vb32 + (size_t)(kv1 + st_r[j]) * 1152 + st_p[j] * 4);
            }
            cp_commit();
            cp_wait<1>();
        } else {
            cp_wait<0>();
        }
        __syncthreads();

        uint32_t kbase = ksb + buf * FTILE_B;
        uint32_t vbase = vsb + buf * FTILE_B;

        // S = Q @ K^T
        float s[16][4] = {};
#pragma unroll
        for (int ks = 0; ks < 6; ks++) {
            uint32_t a[4];
            ldsm4(a[0], a[1], a[2], a[3],
                  a_base + (((2 * ks + a_bit) ^ a_c) << 4));
#pragma unroll
            for (int nb = 0; nb < 8; nb++) {
                int brow = nb * 16 + b_rloc;
                uint32_t r0, r1, r2, r3;
                ldsm4(r0, r1, r2, r3,
                      kbase + brow * FROW * 4 + (((2 * ks + b_bit) ^ (brow & 7)) << 4));
                uint32_t b0[2] = {r0, r1}, b1[2] = {r2, r3};
                mma_bf16(s[2 * nb], a, b0);
                mma_bf16(s[2 * nb + 1], a, b1);
            }
        }

        // online softmax
        float mx0 = -1e30f, mx1 = -1e30f;
#pragma unroll
        for (int n = 0; n < 16; n++) {
            mx0 = fmaxf(mx0, fmaxf(s[n][0], s[n][1]));
            mx1 = fmaxf(mx1, fmaxf(s[n][2], s[n][3]));
        }
        mx0 = fmaxf(mx0, __shfl_xor_sync(~0u, mx0, 1));
        mx0 = fmaxf(mx0, __shfl_xor_sync(~0u, mx0, 2));
        mx1 = fmaxf(mx1, __shfl_xor_sync(~0u, mx1, 1));
        mx1 = fmaxf(mx1, __shfl_xor_sync(~0u, mx1, 2));
        float nm0 = fmaxf(m0, mx0 * scale);
        float nm1 = fmaxf(m1, mx1 * scale);
        float al0 = __expf(m0 - nm0), al1 = __expf(m1 - nm1);
        m0 = nm0; m1 = nm1;
        float sum0 = 0.f, sum1 = 0.f;
#pragma unroll
        for (int n = 0; n < 16; n++) {
            float p0 = __expf(s[n][0] * scale - nm0);
            float p1 = __expf(s[n][1] * scale - nm0);
            float p2 = __expf(s[n][2] * scale - nm1);
            float p3 = __expf(s[n][3] * scale - nm1);
            sum0 += p0 + p1; sum1 += p2 + p3;
            s[n][0] = p0; s[n][1] = p1; s[n][2] = p2; s[n][3] = p3;
        }
        sum0 += __shfl_xor_sync(~0u, sum0, 1);
        sum0 += __shfl_xor_sync(~0u, sum0, 2);
        sum1 += __shfl_xor_sync(~0u, sum1, 1);
        sum1 += __shfl_xor_sync(~0u, sum1, 2);
        l0 = l0 * al0 + sum0;
        l1 = l1 * al1 + sum1;
#pragma unroll
        for (int n = 0; n < 12; n++) {
            o[n][0] *= al0; o[n][1] *= al0;
            o[n][2] *= al1; o[n][3] *= al1;
        }

        // O += P @ V
#pragma unroll
        for (int jb = 0; jb < 8; jb++) {
            uint32_t a[4];
            a[0] = pkbf(s[2 * jb][0], s[2 * jb][1]);
            a[1] = pkbf(s[2 * jb][2], s[2 * jb][3]);
            a[2] = pkbf(s[2 * jb + 1][0], s[2 * jb + 1][1]);
            a[3] = pkbf(s[2 * jb + 1][2], s[2 * jb + 1][3]);
            int vrow = jb * 16 + v_rloc;
            uint32_t v_base = vbase + vrow * FROW * 4;
#pragma unroll
            for (int u = 0; u < 6; u++) {
                uint32_t r0, r1, r2, r3;
                ldsm4t(r0, r1, r2, r3,
                       v_base + (((2 * u + v_bit) ^ v_c) << 4));
                uint32_t b0[2] = {r0, r1}, b1[2] = {r2, r3};
                mma_bf16(o[2 * u], a, b0);
                mma_bf16(o[2 * u + 1], a, b1);
            }
        }
        __syncthreads();
        buf ^= 1;
    }

    float inv0 = 1.f / l0, inv1 = 1.f / l1;
    int row0 = q0 + wrow + grp;
#pragma unroll
    for (int n = 0; n < 12; n++) {
        int c = n * 8 + tig * 2;
        float f0 = fw[b * Cdim + h * Dd + c];
        float f1 = fw[b * Cdim + h * Dd + c + 1];
        size_t ob0 = ((size_t)b * Nseq + row0) * Cdim + h * Dd + c;
        size_t ob1 = ((size_t)b * Nseq + row0 + 8) * Cdim + h * Dd + c;
        float2 qv0 = *(const float2*)(qout + ob0);
        float2 qv1 = *(const float2*)(qout + ob1);
        fusedbf[ob0 >> 1] = pkbf(f0 * qv0.x + (1.f - f0) * o[n][0] * inv0,
                                 f1 * qv0.y + (1.f - f1) * o[n][1] * inv0);
        fusedbf[ob1 >> 1] = pkbf(f0 * qv1.x + (1.f - f0) * o[n][2] * inv1,
                                 f1 * qv1.y + (1.f - f1) * o[n][3] * inv1);
    }
}

// ================= quantum embed GEMM (bf16 A): H = relu(A @ W1 + b1) =================
__global__ __launch_bounds__(256)
void embed_gemm(const uint32_t* __restrict__ qkvbf,
                const float* __restrict__ qW1, const float* __restrict__ qb1,
                const float* __restrict__ kW1, const float* __restrict__ kb1,
                float* __restrict__ Hq, float* __restrict__ Hk) {
    __shared__ uint32_t As[2][8][136];
    __shared__ uint32_t Bs[48][72];
    int tid = threadIdx.x;
    int m0 = blockIdx.x * 128;
    int pass = blockIdx.y;
    const float* W1 = pass ? kW1 : qW1;
    const float* b1 = pass ? kb1 : qb1;
    float* H = pass ? Hk : Hq;
    int qk_off32 = pass * 384;

    for (int i = tid; i < 768; i += 256) {
        int k2 = i >> 4, c4 = i & 15;
        float4 w0 = *(const float4*)(W1 + (2 * k2) * 64 + c4 * 4);
        float4 w1 = *(const float4*)(W1 + (2 * k2 + 1) * 64 + c4 * 4);
        *(uint4*)&Bs[k2][c4 * 4] = make_uint4(pkbf(w0.x, w1.x), pkbf(w0.y, w1.y),
                                              pkbf(w0.z, w1.z), pkbf(w0.w, w1.w));
    }

    int arow = tid >> 1, apart = tid & 1;
    int mrow = m0 + arow;
    const uint4* Ap4 = (const uint4*)(qkvbf + (size_t)(mrow >> 3) * 1152 + qk_off32 + (mrow & 7) * 48);

    int wid = tid >> 5, lane = tid & 31;
    int wm = (wid >> 2) * 64, wn = (wid & 3) * 16;
    int grp = lane >> 2, tig = lane & 3;
    float acc[4][2][4] = {};

    {
        uint4 av = Ap4[apart];
        As[0][apart * 4 + 0][arow] = av.x;
        As[0][apart * 4 + 1][arow] = av.y;
        As[0][apart * 4 + 2][arow] = av.z;
        As[0][apart * 4 + 3][arow] = av.w;
    }
    __syncthreads();

    int buf = 0;
    for (int s = 1; s <= 6; s++) {
        bool more = (s < 6);
        uint4 av;
        if (more) av = Ap4[s * 2 + apart];
        int kb = (s - 1) * 8;
        uint32_t a[4][4], b[2][2];
#pragma unroll
        for (int mi = 0; mi < 4; mi++) {
            int r = wm + mi * 16 + grp;
            a[mi][0] = As[buf][tig][r];
            a[mi][1] = As[buf][tig][r + 8];
            a[mi][2] = As[buf][tig + 4][r];
            a[mi][3] = As[buf][tig + 4][r + 8];
        }
#pragma unroll
        for (int nj = 0; nj < 2; nj++) {
            int c = wn + nj * 8 + grp;
            b[nj][0] = Bs[kb + tig][c];
            b[nj][1] = Bs[kb + tig + 4][c];
        }
#pragma unroll
        for (int mi = 0; mi < 4; mi++)
#pragma unroll
            for (int nj = 0; nj < 2; nj++) mma_bf16(acc[mi][nj], a[mi], b[nj]);
        if (more) {
            As[buf ^ 1][apart * 4 + 0][arow] = av.x;
            As[buf ^ 1][apart * 4 + 1][arow] = av.y;
            As[buf ^ 1][apart * 4 + 2][arow] = av.z;
            As[buf ^ 1][apart * 4 + 3][arow] = av.w;
            __syncthreads();
            buf ^= 1;
        }
    }

#pragma unroll
    for (int nj = 0; nj < 2; nj++) {
        int c = wn + nj * 8 + tig * 2;
        float bi0 = __ldg(&b1[c]), bi1 = __ldg(&b1[c + 1]);
#pragma unroll
        for (int mi = 0; mi < 4; mi++) {
            size_t r = m0 + wm + mi * 16 + grp;
            *(float2*)(H + r * 64 + c) =
                make_float2(fmaxf(acc[mi][nj][0] + bi0, 0.f), fmaxf(acc[mi][nj][1] + bi1, 0.f));
            *(float2*)(H + (r + 8) * 64 + c) =
                make_float2(fmaxf(acc[mi][nj][2] + bi0, 0.f), fmaxf(acc[mi][nj][3] + bi1, 0.f));
        }
    }
}

// ================= quantum middle: e -> state -> meas =================
__global__ __launch_bounds__(128)
void quantum_mid(const float* __restrict__ Hq, const float* __restrict__ Hk,
                 const float* __restrict__ qe_w2, const float* __restrict__ qe_b2,
                 const float* __restrict__ ke_w2, const float* __restrict__ ke_b2,
                 const float* __restrict__ gate_params, const float* __restrict__ ent_params,
                 const float* __restrict__ gumbel, float* __restrict__ meas_out) {
    __shared__ float w2q[1024], w2k[1024];
    __shared__ float gf[2][8], gcz[2][8], gsz[2][8], gs[2][8];
    int tid = threadIdx.x;
    for (int i = tid; i < 256; i += 128) {
        ((float4*)w2q)[i] = ((const float4*)qe_w2)[i];
        ((float4*)w2k)[i] = ((const float4*)ke_w2)[i];
    }
    if (tid < 16) {
        int l = tid >> 3, i = tid & 7;
        float ry = gate_params[(l * 8 + i) * 3 + 1];
        float rz = gate_params[(l * 8 + i) * 3 + 2];
        gf[l][i] = cosf(0.5f * ry);
        gcz[l][i] = cosf(rz);
        gsz[l][i] = sinf(rz);
    } else if (tid < 30) {
        int t = tid - 16, l = t / 7, i = t % 7;
        gs[l][i + 1] = 1.f / (1.f + expf(-ent_params[l * 7 + i]));
    }
    __syncthreads();

    int m = blockIdx.x * 128 + tid;
    float sre[8], sim[8];

#pragma unroll
    for (int pass = 0; pass < 2; pass++) {
        const float* Hrow = (pass == 0 ? Hq : Hk) + (size_t)m * 64;
        const float* w2 = (pass == 0 ? w2q : w2k);
        const float* b2 = (pass == 0 ? qe_b2 : ke_b2);
        float e[16];
#pragma unroll
        for (int i = 0; i < 16; i++) e[i] = __ldg(&b2[i]);
        const float4* h4 = (const float4*)Hrow;
#pragma unroll
        for (int j4 = 0; j4 < 16; j4++) {
            float4 hv = h4[j4];
            float hs[4] = {hv.x, hv.y, hv.z, hv.w};
#pragma unroll
            for (int s = 0; s < 4; s++) {
                float hj = hs[s];
                const float4* wr = (const float4*)&w2[(j4 * 4 + s) * 16];
#pragma unroll
                for (int i4 = 0; i4 < 4; i4++) {
                    float4 w = wr[i4];
                    e[i4 * 4 + 0] += hj * w.x; e[i4 * 4 + 1] += hj * w.y;
                    e[i4 * 4 + 2] += hj * w.z; e[i4 * 4 + 3] += hj * w.w;
                }
            }
        }
        float mx = e[0];
#pragma unroll
        for (int i = 1; i < 8; i++) mx = fmaxf(mx, e[i]);
        float ex[8], ssum = 0.f;
#pragma unroll
        for (int i = 0; i < 8; i++) { ex[i] = __expf(e[i] - mx); ssum += ex[i]; }
        float inv = 1.f / ssum;
#pragma unroll
        for (int i = 0; i < 8; i++) {
            float amp = ex[i] * inv;
            float cr = amp * __cosf(e[8 + i]), ci = amp * __sinf(e[8 + i]);
            if (pass == 0) { sre[i] = cr; sim[i] = ci; }
            else           { sre[i] += cr; sim[i] += ci; }
        }
    }

#pragma unroll
    for (int l = 0; l < 2; l++) {
#pragma unroll
        for (int i = 0; i < 8; i++) {
            float nr = sre[i] * gcz[l][i] - sim[i] * gsz[l][i];
            float ni = sre[i] * gsz[l][i] + sim[i] * gcz[l][i];
            sre[i] = nr * gf[l][i];
            sim[i] = ni * gf[l][i];
        }
#pragma unroll
        for (int i = 7; i >= 1; i--) {
            sre[i] += gs[l][i] * sre[i - 1];
            sim[i] += gs[l][i] * sim[i - 1];
        }
    }

    float p[8], mx = -1e30f;
#pragma unroll
    for (int i = 0; i < 8; i++) { p[i] = sre[i] * sre[i] + sim[i] * sim[i]; mx = fmaxf(mx, p[i]); }
    float ssum = 0.f;
#pragma unroll
    for (int i = 0; i < 8; i++) { p[i] = __expf(p[i] - mx); ssum += p[i]; }
    float sinv = 1.f / ssum;
    int b = m >> 13, n = (m >> 3) & 1023, h = m & 7;
    size_t goff = (size_t)(((b * 8 + h) << 10) + n) * 8;
    float4 g0 = __ldg((const float4*)(gumbel + goff));
    float4 g1 = __ldg((const float4*)(gumbel + goff + 4));
    float gv[8] = {g0.x, g0.y, g0.z, g0.w, g1.x, g1.y, g1.z, g1.w};
    float lg[8], mx2 = -1e30f;
#pragma unroll
    for (int i = 0; i < 8; i++) {
        lg[i] = 2.f * (__logf(p[i] * sinv + 1e-10f) + gv[i]);
        mx2 = fmaxf(mx2, lg[i]);
    }
    float meas[8], msum = 0.f;
#pragma unroll
    for (int i = 0; i < 8; i++) { meas[i] = __expf(lg[i] - mx2); msum += meas[i]; }
    float minv = 1.f / msum;
    float4 o0 = make_float4(meas[0] * minv, meas[1] * minv, meas[2] * minv, meas[3] * minv);
    float4 o1 = make_float4(meas[4] * minv, meas[5] * minv, meas[6] * minv, meas[7] * minv);
    *(float4*)(meas_out + (size_t)m * 8) = o0;
    *(float4*)(meas_out + (size_t)m * 8 + 4) = o1;
}

// ================= fused measure MLP (tf32): qout = (relu(meas@W1+b1)@W2+b2)*v =================
#define MD_T1_LD 136
#define MD_W2_LD 104
#define MD_SMEM ((8 * 136 + 8 * 72 + 64 * MD_T1_LD + 64 * MD_W2_LD) * 4)

__global__ __launch_bounds__(256)
void md_fused(const float* __restrict__ meas,
              const float* __restrict__ W1, const float* __restrict__ b1,
              const float* __restrict__ W2, const float* __restrict__ b2,
              const uint32_t* __restrict__ qkvbf, float* __restrict__ qout) {
    extern __shared__ float sm[];
    float* As8 = sm;
    float* W1s = sm + 8 * 136;
    float* T1  = sm + 8 * 136 + 8 * 72;
    float* W2s = T1 + 64 * MD_T1_LD;

    int tid = threadIdx.x;
    int m0 = blockIdx.x * 128;
    int wid = tid >> 5, lane = tid & 31;
    int grp = lane >> 2, tig = lane & 3;
    int wm = (wid >> 2) * 64;

    {
        int arow = tid >> 1, ak = (tid & 1) * 4;
        float4 v = *(const float4*)(meas + (size_t)(m0 + arow) * 8 + ak);
        As8[(ak + 0) * 136 + arow] = to_tf32(v.x);
        As8[(ak + 1) * 136 + arow] = to_tf32(v.y);
        As8[(ak + 2) * 136 + arow] = to_tf32(v.z);
        As8[(ak + 3) * 136 + arow] = to_tf32(v.w);
    }
    for (int i = tid; i < 128; i += 256) {
        int d = i >> 4, n4 = i & 15;
        float4 w = ((const float4*)W1)[i];
        float4 wc = make_float4(to_tf32(w.x), to_tf32(w.y), to_tf32(w.z), to_tf32(w.w));
        *(float4*)&W1s[d * 72 + n4 * 4] = wc;
    }
    for (int i = tid; i < 1536; i += 256) {
        int d = i / 24, n4 = i % 24;
        float4 w = ((const float4*)W2)[i];
        float4 wc = make_float4(to_tf32(w.x), to_tf32(w.y), to_tf32(w.z), to_tf32(w.w));
        *(float4*)&W2s[d * MD_W2_LD + n4 * 4] = wc;
    }
    __syncthreads();

    {
        int wn1 = (wid & 3) * 16;
        float acc1[4][2][4] = {};
        uint32_t a[4][4], b[2][2];
#pragma unroll
        for (int mi = 0; mi < 4; mi++) {
            int r = wm + mi * 16 + grp;
            a[mi][0] = __float_as_uint(As8[tig * 136 + r]);
            a[mi][1] = __float_as_uint(As8[tig * 136 + r + 8]);
            a[mi][2] = __float_as_uint(As8[(tig + 4) * 136 + r]);
            a[mi][3] = __float_as_uint(As8[(tig + 4) * 136 + r + 8]);
        }
#pragma unroll
        for (int nj = 0; nj < 2; nj++) {
            int c = wn1 + nj * 8 + grp;
            b[nj][0] = __float_as_uint(W1s[tig * 72 + c]);
            b[nj][1] = __float_as_uint(W1s[(tig + 4) * 72 + c]);
        }
#pragma unroll
        for (int mi = 0; mi < 4; mi++)
#pragma unroll
            for (int nj = 0; nj < 2; nj++) mma_tf32(acc1[mi][nj], a[mi], b[nj]);

#pragma unroll
        for (int nj = 0; nj < 2; nj++) {
            int c = wn1 + nj * 8 + tig * 2;
            float bi0 = __ldg(&b1[c]), bi1 = __ldg(&b1[c + 1]);
#pragma unroll
            for (int mi = 0; mi < 4; mi++) {
                int r = wm + mi * 16 + grp;
                T1[c * MD_T1_LD + r]           = to_tf32(fmaxf(acc1[mi][nj][0] + bi0, 0.f));
                T1[(c + 1) * MD_T1_LD + r]     = to_tf32(fmaxf(acc1[mi][nj][1] + bi1, 0.f));
                T1[c * MD_T1_LD + r + 8]       = to_tf32(fmaxf(acc1[mi][nj][2] + bi0, 0.f));
                T1[(c + 1) * MD_T1_LD + r + 8] = to_tf32(fmaxf(acc1[mi][nj][3] + bi1, 0.f));
            }
        }
    }
    __syncthreads();

    int wn = (wid & 3) * 24;
    float acc2[4][3][4] = {};
#pragma unroll
    for (int ks = 0; ks < 8; ks++) {
        uint32_t a[4][4], b[3][2];
#pragma unroll
        for (int mi = 0; mi < 4; mi++) {
            int r = wm + mi * 16 + grp;
            a[mi][0] = __float_as_uint(T1[(ks * 8 + tig) * MD_T1_LD + r]);
            a[mi][1] = __float_as_uint(T1[(ks * 8 + tig) * MD_T1_LD + r + 8]);
            a[mi][2] = __float_as_uint(T1[(ks * 8 + tig + 4) * MD_T1_LD + r]);
            a[mi][3] = __float_as_uint(T1[(ks * 8 + tig + 4) * MD_T1_LD + r + 8]);
        }
#pragma unroll
        for (int nj = 0; nj < 3; nj++) {
            int c = wn + nj * 8 + grp;
            b[nj][0] = __float_as_uint(W2s[(ks * 8 + tig) * MD_W2_LD + c]);
            b[nj][1] = __float_as_uint(W2s[(ks * 8 + tig + 4) * MD_W2_LD + c]);
        }
#pragma unroll
        for (int mi = 0; mi < 4; mi++)
#pragma unroll
            for (int nj = 0; nj < 3; nj++) mma_tf32(acc2[mi][nj], a[mi], b[nj]);
    }

#pragma unroll
    for (int nj = 0; nj < 3; nj++) {
        int c = wn + nj * 8 + tig * 2;
        float bi0 = __ldg(&b2[c]), bi1 = __ldg(&b2[c + 1]);
#pragma unroll
        for (int mi = 0; mi < 4; mi++) {
            int m = m0 + wm + mi * 16 + grp;
#pragma unroll
            for (int half = 0; half < 2; half++) {
                int mm = m + half * 8;
                size_t qrow = (size_t)(mm >> 3);
                int hh = mm & 7;
                uint32_t u = qkvbf[(qrow * 2304 + 1536 + hh * 96 + c) >> 1];
                float2 vv = __bfloat1622float2(*(__nv_bfloat162*)&u);
                float o0 = (acc2[mi][nj][half * 2 + 0] + bi0) * vv.x;
                float o1 = (acc2[mi][nj][half * 2 + 1] + bi1) * vv.y;
                *(float2*)(qout + qrow * 768 + hh * 96 + c) = make_float2(o0, o1);
            }
        }
    }
}

// ================= mean over N =================
__global__ void colmean_kernel(const float* __restrict__ x, float* __restrict__ xmean) {
    int b = blockIdx.y;
    int c = blockIdx.x * 256 + threadIdx.x;
    const float* p = x + (size_t)b * Nseq * Cdim + c;
    float s = 0.f;
    for (int n = 0; n < Nseq; n++) s += p[(size_t)n * Cdim];
    xmean[b * Cdim + c] = s * (1.0f / 1024.0f);
}

// ================= fw = sigmoid(xmean @ w_proj + b_proj) =================
__global__ void fw_kernel(const float* __restrict__ xmean, const float* __restrict__ w_proj,
                          const float* __restrict__ b_proj, float* __restrict__ fw) {
    __shared__ float xm[768];
    int b = blockIdx.x;
    int c = threadIdx.x;
    xm[c] = xmean[b * Cdim + c];
    __syncthreads();
    float s = b_proj[c];
    for (int k = 0; k < 768; k++) s += xm[k] * w_proj[(size_t)k * 768 + c];
    fw[b * Cdim + c] = 1.f / (1.f + expf(-s));
}

// ================= layernorm =================
__global__ void layernorm_kernel(const float* __restrict__ y, const float* __restrict__ gamma,
                                 const float* __restrict__ beta, float* __restrict__ out) {
    __shared__ float red1[8], red2[8];
    size_t row = blockIdx.x;
    const float* p = y + row * Cdim;
    int tid = threadIdx.x;
    float v[3];
    float s = 0.f;
#pragma unroll
    for (int i = 0; i < 3; i++) { v[i] = p[tid + i * 256]; s += v[i]; }
#pragma unroll
    for (int o = 16; o > 0; o >>= 1) s += __shfl_xor_sync(~0u, s, o);
    int w = tid >> 5, lane = tid & 31;
    if (lane == 0) red1[w] = s;
    __syncthreads();
    s = 0.f;
#pragma unroll
    for (int i = 0; i < 8; i++) s += red1[i];
    float mu = s * (1.0f / 768.0f);
    float vs = 0.f;
#pragma unroll
    for (int i = 0; i < 3; i++) { float d = v[i] - mu; vs += d * d; }
#pragma unroll
    for (int o = 16; o > 0; o >>= 1) vs += __shfl_xor_sync(~0u, vs, o);
    if (lane == 0) red2[w] = vs;
    __syncthreads();
    vs = 0.f;
#pragma unroll
    for (int i = 0; i < 8; i++) vs += red2[i];
    float inv = rsqrtf(vs * (1.0f / 768.0f) + 1e-5f);
#pragma unroll
    for (int i = 0; i < 3; i++) {
        int c = tid + i * 256;
        out[row * Cdim + c] = (v[i] - mu) * inv * gamma[c] + beta[c];
    }
}

// ================= launch =================
extern "C" void kernel_launch(void* const* d_in, const int* in_sizes, int n_in,
                              void* d_out, int out_size) {
    const float* x      = (const float*)d_in[0];
    const float* w_qkv  = (const float*)d_in[1];
    const float* b_qkv  = (const float*)d_in[2];
    const float* w_proj = (const float*)d_in[3];
    const float* b_proj = (const float*)d_in[4];
    const float* gamma  = (const float*)d_in[5];
    const float* beta   = (const float*)d_in[6];
    const float* qe_w1  = (const float*)d_in[7];
    const float* qe_b1  = (const float*)d_in[8];
    const float* qe_w2  = (const float*)d_in[9];
    const float* qe_b2  = (const float*)d_in[10];
    const float* ke_w1  = (const float*)d_in[11];
    const float* ke_b1  = (const float*)d_in[12];
    const float* ke_w2  = (const float*)d_in[13];
    const float* ke_b2  = (const float*)d_in[14];
    const float* gate_params = (const float*)d_in[19];
    const float* ent_params  = (const float*)d_in[20];
    const float* md_w1  = (const float*)d_in[21];
    const float* md_b1  = (const float*)d_in[22];
    const float* md_w2  = (const float*)d_in[23];
    const float* md_b2  = (const float*)d_in[24];
    const float* gumbel = (const float*)d_in[25];
    float* out = (float*)d_out;

    uint32_t *qkvbf, *fusedbf;
    float *qout, *y, *xmean, *fw, *hq, *hk, *meas;
    cudaGetSymbolAddress((void**)&qkvbf, g_qkv_bf);
    cudaGetSymbolAddress((void**)&fusedbf, g_fused_bf);
    cudaGetSymbolAddress((void**)&qout, g_qout);
    cudaGetSymbolAddress((void**)&y, g_y);
    cudaGetSymbolAddress((void**)&xmean, g_xmean);
    cudaGetSymbolAddress((void**)&fw, g_fw);
    cudaGetSymbolAddress((void**)&hq, g_hq);
    cudaGetSymbolAddress((void**)&hk, g_hk);
    cudaGetSymbolAddress((void**)&meas, g_meas);

    cudaFuncSetAttribute(flash_kernel, cudaFuncAttributeMaxDynamicSharedMemorySize, FLASH_SMEM);
    cudaFuncSetAttribute(md_fused, cudaFuncAttributeMaxDynamicSharedMemorySize, MD_SMEM);

    // gate path (depends only on x)
    colmean_kernel<<<dim3(3, 8), 256>>>(x, xmean);
    fw_kernel<<<8, 768>>>(xmean, w_proj, b_proj, fw);
    // qkv = x @ w_qkv + b_qkv  -> bf16
    mma_qkv<<<dim3(2304 / 128, 8192 / 128), 256>>>(x, w_qkv, b_qkv, qkvbf,
                                                   768, 768, 2304, 2304);
    // quantum path: embeds (GEMM) -> mid -> measure MLP (GEMM) -> qout
    embed_gemm<<<dim3(NTOK / 128, 2), 256>>>(qkvbf, qe_w1, qe_b1, ke_w1, ke_b1, hq, hk);
    quantum_mid<<<NTOK / 128, 128>>>(hq, hk, qe_w2, qe_b2, ke_w2, ke_b2,
                                     gate_params, ent_params, gumbel, meas);
    md_fused<<<NTOK / 128, 256, MD_SMEM>>>(meas, md_w1, md_b1, md_w2, md_b2, qkvbf, qout);
    // fused classical attention + gate blend -> fused (bf16)
    flash_kernel<<<dim3(8, 64), 256, FLASH_SMEM>>>(qkvbf, qout, fw, fusedbf);
    // y = x + fused @ w_proj + b_proj
    mma_proj<<<dim3(768 / 128, 8192 / 128), 256>>>(fusedbf, w_proj, b_proj, x, y,
                                                   768, 768, 768, 768);
    // layernorm
    layernorm_kernel<<<8192, 256>>>(y, gamma, beta, out);
}

// round 14
// speedup vs baseline: 1.7179x; 1.1475x over previous
#include <cuda_runtime.h>
#include <cuda_bf16.h>
#include <math.h>
#include <stdint.h>

// ---------------- scratch ----------------
#define Bsz 8
#define Nseq 1024
#define Cdim 768
#define Hh 8
#define Dd 96
#define Qq 8
#define NTOK (Bsz * Hh * Nseq)   // 65536, ordered m=(b,n,h)

__device__ uint32_t g_qkv_bf[Bsz * Nseq * 3 * Cdim / 2];   // bf16x2
__device__ uint32_t g_fused_bf[Bsz * Nseq * Cdim / 2];     // bf16x2
__device__ uint32_t g_x_bf[Bsz * Nseq * Cdim / 2];         // bf16x2
__device__ __nv_bfloat16 g_wqT[3 * Cdim * Cdim];           // w_qkv^T [2304][768]
__device__ __nv_bfloat16 g_wpT[Cdim * Cdim];               // w_proj^T [768][768]
__device__ float g_qout[Bsz * Nseq * Cdim];
__device__ float g_y[Bsz * Nseq * Cdim];
__device__ float g_xmean[Bsz * Cdim];
__device__ float g_fw[Bsz * Cdim];
__device__ float g_hq[NTOK * 64];
__device__ float g_hk[NTOK * 64];
__device__ float g_meas[NTOK * 8];

// ---------------- mma helpers ----------------
__device__ __forceinline__ float to_tf32(float x) {
    uint32_t u;
    asm("cvt.rna.tf32.f32 %0, %1;" : "=r"(u) : "f"(x));
    return __uint_as_float(u);
}

__device__ __forceinline__ uint32_t pkbf(float x, float y) {
    __nv_bfloat162 t = __floats2bfloat162_rn(x, y);
    return *(uint32_t*)&t;
}

__device__ __forceinline__ void mma_tf32(float* c, const uint32_t* a, const uint32_t* b) {
    asm volatile(
        "mma.sync.aligned.m16n8k8.row.col.f32.tf32.tf32.f32 "
        "{%0,%1,%2,%3}, {%4,%5,%6,%7}, {%8,%9}, {%0,%1,%2,%3};"
        : "+f"(c[0]), "+f"(c[1]), "+f"(c[2]), "+f"(c[3])
        : "r"(a[0]), "r"(a[1]), "r"(a[2]), "r"(a[3]), "r"(b[0]), "r"(b[1]));
}

__device__ __forceinline__ void mma_bf16(float* c, const uint32_t* a, const uint32_t* b) {
    asm volatile(
        "mma.sync.aligned.m16n8k16.row.col.f32.bf16.bf16.f32 "
        "{%0,%1,%2,%3}, {%4,%5,%6,%7}, {%8,%9}, {%0,%1,%2,%3};"
        : "+f"(c[0]), "+f"(c[1]), "+f"(c[2]), "+f"(c[3])
        : "r"(a[0]), "r"(a[1]), "r"(a[2]), "r"(a[3]), "r"(b[0]), "r"(b[1]));
}

__device__ __forceinline__ void ldsm4(uint32_t& r0, uint32_t& r1, uint32_t& r2, uint32_t& r3,
                                      uint32_t addr) {
    asm volatile("ldmatrix.sync.aligned.m8n8.x4.shared.b16 {%0,%1,%2,%3}, [%4];"
                 : "=r"(r0), "=r"(r1), "=r"(r2), "=r"(r3) : "r"(addr));
}

__device__ __forceinline__ void ldsm4t(uint32_t& r0, uint32_t& r1, uint32_t& r2, uint32_t& r3,
                                       uint32_t addr) {
    asm volatile("ldmatrix.sync.aligned.m8n8.x4.trans.shared.b16 {%0,%1,%2,%3}, [%4];"
                 : "=r"(r0), "=r"(r1), "=r"(r2), "=r"(r3) : "r"(addr));
}

__device__ __forceinline__ void cpa16(uint32_t smem, const void* g) {
    asm volatile("cp.async.cg.shared.global [%0], [%1], 16;" :: "r"(smem), "l"(g));
}
__device__ __forceinline__ void cp_commit() {
    asm volatile("cp.async.commit_group;");
}
template <int N>
__device__ __forceinline__ void cp_wait() {
    asm volatile("cp.async.wait_group %0;" :: "n"(N));
}

// XOR-swizzled tile (GEMM): [128 rows][8 u32]; part swapped on (row>>2)&1.
#define SWZ(row, part) ((row) * 8 + (((part) ^ (((row) >> 2) & 1)) * 4))
#define TILE_U32 (128 * 8)
#define TILE_B (TILE_U32 * 4)

// ================= pre-conversion kernels =================
__global__ void cvt_x(const float* __restrict__ x, uint32_t* __restrict__ xbf) {
    size_t i = (size_t)blockIdx.x * 256 + threadIdx.x;
    float2 v = ((const float2*)x)[i];
    xbf[i] = pkbf(v.x, v.y);
}

// W[K][N] fp32 -> WT[N][K] bf16, 32x32 smem tiles
__global__ void cvt_wT(const float* __restrict__ W, __nv_bfloat16* __restrict__ WT,
                       int Kd, int Nd) {
    __shared__ float t[32][33];
    int bx = blockIdx.x, by = blockIdx.y;
    int tx = threadIdx.x, ty = threadIdx.y;
#pragma unroll
    for (int i = 0; i < 4; i++) {
        int r = ty + i * 8;
        t[r][tx] = W[(size_t)(by * 32 + r) * Nd + bx * 32 + tx];
    }
    __syncthreads();
#pragma unroll
    for (int i = 0; i < 4; i++) {
        int r = ty + i * 8;
        WT[(size_t)(bx * 32 + r) * Kd + by * 32 + tx] = __float2bfloat16(t[tx][r]);
    }
}

// ================= unified bf16 cp.async GEMM =================
// A: bf16 [M][lda] (as u32 pairs). BT: bf16 [N][K] (transposed weights).
// If Cbf != null: bf16 out (+bias). Else fp32 out (+bias+resid).
__global__ __launch_bounds__(256)
void mma_bf(const uint32_t* __restrict__ Abf, const __nv_bfloat16* __restrict__ BT,
            const float* __restrict__ bias, const float* __restrict__ resid,
            float* __restrict__ Cf, uint32_t* __restrict__ Cbf,
            int K, int lda, int ldc) {
    __shared__ uint32_t As[2][TILE_U32];
    __shared__ uint32_t Bs[2][TILE_U32];
    int tid = threadIdx.x;
    int m0 = blockIdx.y * 128, n0 = blockIdx.x * 128;
    int arow = tid >> 1, apart = tid & 1;
    const uint32_t* a_gp = Abf + (size_t)(m0 + arow) * (lda / 2) + apart * 4;
    uint32_t a_st = SWZ(arow, apart) * 4;
    int brow = tid >> 1, bpart = tid & 1;
    const __nv_bfloat16* b_gp = BT + (size_t)(n0 + brow) * K + bpart * 8;
    uint32_t b_st = SWZ(brow, bpart) * 4;

    int wid = tid >> 5, lane = tid & 31;
    int wm = (wid >> 2) * 64, wn = (wid & 3) * 32;
    int grp = lane >> 2, tig = lane & 3;
    float acc[4][4][4] = {};

    uint32_t asb = (uint32_t)__cvta_generic_to_shared(&As[0][0]);
    uint32_t bsb = (uint32_t)__cvta_generic_to_shared(&Bs[0][0]);
    uint32_t a_off[4], b_off[2];
#pragma unroll
    for (int mi = 0; mi < 4; mi++) {
        int r = wm + mi * 16 + (lane & 15);
        a_off[mi] = SWZ(r, lane >> 4) * 4;
    }
#pragma unroll
    for (int nb = 0; nb < 2; nb++) {
        int r = wn + nb * 16 + (lane & 7) + ((lane >> 4) << 3);
        b_off[nb] = SWZ(r, (lane >> 3) & 1) * 4;
    }

    // prefetch stage 0
    cpa16(asb + a_st, a_gp);
    cpa16(bsb + b_st, b_gp);
    cp_commit();

    int S = K / 16, buf = 0;
    for (int s = 0; s < S; s++) {
        if (s + 1 < S) {
            cpa16(asb + (buf ^ 1) * TILE_B + a_st, a_gp + (s + 1) * 8);
            cpa16(bsb + (buf ^ 1) * TILE_B + b_st, b_gp + (size_t)(s + 1) * 16);
            cp_commit();
            cp_wait<1>();
        } else {
            cp_wait<0>();
        }
        __syncthreads();

        uint32_t a[4][4], b[4][2];
        uint32_t ab = asb + buf * TILE_B, bb = bsb + buf * TILE_B;
#pragma unroll
        for (int mi = 0; mi < 4; mi++)
            ldsm4(a[mi][0], a[mi][1], a[mi][2], a[mi][3], ab + a_off[mi]);
#pragma unroll
        for (int nb = 0; nb < 2; nb++) {
            uint32_t r0, r1, r2, r3;
            ldsm4(r0, r1, r2, r3, bb + b_off[nb]);
            b[2 * nb][0] = r0; b[2 * nb][1] = r1;
            b[2 * nb + 1][0] = r2; b[2 * nb + 1][1] = r3;
        }
#pragma unroll
        for (int mi = 0; mi < 4; mi++)
#pragma unroll
            for (int nj = 0; nj < 4; nj++) mma_bf16(acc[mi][nj], a[mi], b[nj]);
        __syncthreads();
        buf ^= 1;
    }

#pragma unroll
    for (int nj = 0; nj < 4; nj++) {
        int c = n0 + wn + nj * 8 + tig * 2;
        float bi0 = bias[c], bi1 = bias[c + 1];
#pragma unroll
        for (int mi = 0; mi < 4; mi++) {
            size_t r = m0 + wm + mi * 16 + grp;
            if (Cbf) {
                Cbf[(r * ldc + c) >> 1] = pkbf(acc[mi][nj][0] + bi0, acc[mi][nj][1] + bi1);
                Cbf[((r + 8) * ldc + c) >> 1] = pkbf(acc[mi][nj][2] + bi0, acc[mi][nj][3] + bi1);
            } else {
                float2 r0 = *(const float2*)(resid + r * ldc + c);
                float2 r1 = *(const float2*)(resid + (r + 8) * ldc + c);
                *(float2*)(Cf + r * ldc + c) =
                    make_float2(acc[mi][nj][0] + bi0 + r0.x, acc[mi][nj][1] + bi1 + r0.y);
                *(float2*)(Cf + (r + 8) * ldc + c) =
                    make_float2(acc[mi][nj][2] + bi0 + r1.x, acc[mi][nj][3] + bi1 + r1.y);
            }
        }
    }
}

// ================= fused flash attention (ldmatrix + cp.async pipeline) =================
#define FROW 64
#define FSWZ(row, p) ((row) * FROW + (((p) ^ ((row) & 7)) << 2))
#define FTILE_U32 (128 * FROW)
#define FTILE_B (FTILE_U32 * 4)
#define FLASH_SMEM (5 * FTILE_B)

__global__ __launch_bounds__(256, 1)
void flash_kernel(const uint32_t* __restrict__ qkvbf, const float* __restrict__ qout,
                  const float* __restrict__ fw, uint32_t* __restrict__ fusedbf) {
    extern __shared__ uint32_t smu[];
    uint32_t* Qs = smu;

    int tid = threadIdx.x;
    int z = blockIdx.y;
    int b = z >> 3, h = z & 7;
    int q0 = blockIdx.x * 128;
    const uint32_t* qb32 = qkvbf + (size_t)b * Nseq * 1152 + h * 48;
    const uint32_t* kb32 = qb32 + 384;
    const uint32_t* vb32 = qb32 + 768;

    int lane = tid & 31, wid = tid >> 5;
    int grp = lane >> 2, tig = lane & 3;
    int wrow = wid * 16;

    uint32_t qsb = (uint32_t)__cvta_generic_to_shared(Qs);
    uint32_t ksb = qsb + FTILE_B;
    uint32_t vsb = qsb + 3 * FTILE_B;

    int a_row = wrow + (lane & 15);
    int a_bit = lane >> 4;
    uint32_t a_base = qsb + a_row * FROW * 4;
    int a_c = a_row & 7;
    int b_rloc = (lane & 7) + ((lane >> 4) << 3);
    int b_bit = (lane >> 3) & 1;
    int v_rloc = (lane & 7) + (((lane >> 3) & 1) << 3);
    int v_bit = lane >> 4;
    int v_c = v_rloc & 7;

    int st_r[6], st_p[6];
    uint32_t st_sw[6];
#pragma unroll
    for (int j = 0; j < 6; j++) {
        int i = tid + j * 256;
        st_r[j] = i / 12; st_p[j] = i % 12;
        st_sw[j] = FSWZ(st_r[j], st_p[j]) * 4;
    }

    for (int i = tid; i < 1536; i += 256) {
        int r = i / 12, p = i % 12;
        uint4 v = *(const uint4*)(qb32 + (size_t)(q0 + r) * 1152 + p * 4);
        *(uint4*)&Qs[FSWZ(r, p)] = v;
    }
#pragma unroll
    for (int j = 0; j < 6; j++) {
        cpa16(ksb + st_sw[j], kb32 + (size_t)st_r[j] * 1152 + st_p[j] * 4);
        cpa16(vsb + st_sw[j], vb32 + (size_t)st_r[j] * 1152 + st_p[j] * 4);
    }
    cp_commit();

    float o[12][4] = {};
    float m0 = -1e30f, m1 = -1e30f, l0 = 0.f, l1 = 0.f;
    const float scale = 0.10206207261596577f;

    int buf = 0;
    for (int t = 0; t < 8; t++) {
        if (t < 7) {
            int kv1 = (t + 1) * 128;
            uint32_t kd = ksb + (buf ^ 1) * FTILE_B;
            uint32_t vd = vsb + (buf ^ 1) * FTILE_B;
#pragma unroll
            for (int j = 0; j < 6; j++) {
                cpa16(kd + st_sw[j], kb32 + (size_t)(kv1 + st_r[j]) * 1152 + st_p[j] * 4);
                cpa16(vd + st_sw[j], vb32 + (size_t)(kv1 + st_r[j]) * 1152 + st_p[j] * 4);
            }
            cp_commit();
            cp_wait<1>();
        } else {
            cp_wait<0>();
        }
        __syncthreads();

        uint32_t kbase = ksb + buf * FTILE_B;
        uint32_t vbase = vsb + buf * FTILE_B;

        float s[16][4] = {};
#pragma unroll
        for (int ks = 0; ks < 6; ks++) {
            uint32_t a[4];
            ldsm4(a[0], a[1], a[2], a[3],
                  a_base + (((2 * ks + a_bit) ^ a_c) << 4));
#pragma unroll
            for (int nb = 0; nb < 8; nb++) {
                int brow = nb * 16 + b_rloc;
                uint32_t r0, r1, r2, r3;
                ldsm4(r0, r1, r2, r3,
                      kbase + brow * FROW * 4 + (((2 * ks + b_bit) ^ (brow & 7)) << 4));
                uint32_t b0[2] = {r0, r1}, b1[2] = {r2, r3};
                mma_bf16(s[2 * nb], a, b0);
                mma_bf16(s[2 * nb + 1], a, b1);
            }
        }

        float mx0 = -1e30f, mx1 = -1e30f;
#pragma unroll
        for (int n = 0; n < 16; n++) {
            mx0 = fmaxf(mx0, fmaxf(s[n][0], s[n][1]));
            mx1 = fmaxf(mx1, fmaxf(s[n][2], s[n][3]));
        }
        mx0 = fmaxf(mx0, __shfl_xor_sync(~0u, mx0, 1));
        mx0 = fmaxf(mx0, __shfl_xor_sync(~0u, mx0, 2));
        mx1 = fmaxf(mx1, __shfl_xor_sync(~0u, mx1, 1));
        mx1 = fmaxf(mx1, __shfl_xor_sync(~0u, mx1, 2));
        float nm0 = fmaxf(m0, mx0 * scale);
        float nm1 = fmaxf(m1, mx1 * scale);
        float al0 = __expf(m0 - nm0), al1 = __expf(m1 - nm1);
        m0 = nm0; m1 = nm1;
        float sum0 = 0.f, sum1 = 0.f;
#pragma unroll
        for (int n = 0; n < 16; n++) {
            float p0 = __expf(s[n][0] * scale - nm0);
            float p1 = __expf(s[n][1] * scale - nm0);
            float p2 = __expf(s[n][2] * scale - nm1);
            float p3 = __expf(s[n][3] * scale - nm1);
            sum0 += p0 + p1; sum1 += p2 + p3;
            s[n][0] = p0; s[n][1] = p1; s[n][2] = p2; s[n][3] = p3;
        }
        sum0 += __shfl_xor_sync(~0u, sum0, 1);
        sum0 += __shfl_xor_sync(~0u, sum0, 2);
        sum1 += __shfl_xor_sync(~0u, sum1, 1);
        sum1 += __shfl_xor_sync(~0u, sum1, 2);
        l0 = l0 * al0 + sum0;
        l1 = l1 * al1 + sum1;
#pragma unroll
        for (int n = 0; n < 12; n++) {
            o[n][0] *= al0; o[n][1] *= al0;
            o[n][2] *= al1; o[n][3] *= al1;
        }

#pragma unroll
        for (int jb = 0; jb < 8; jb++) {
            uint32_t a[4];
            a[0] = pkbf(s[2 * jb][0], s[2 * jb][1]);
            a[1] = pkbf(s[2 * jb][2], s[2 * jb][3]);
            a[2] = pkbf(s[2 * jb + 1][0], s[2 * jb + 1][1]);
            a[3] = pkbf(s[2 * jb + 1][2], s[2 * jb + 1][3]);
            int vrow = jb * 16 + v_rloc;
            uint32_t v_base = vbase + vrow * FROW * 4;
#pragma unroll
            for (int u = 0; u < 6; u++) {
                uint32_t r0, r1, r2, r3;
                ldsm4t(r0, r1, r2, r3,
                       v_base + (((2 * u + v_bit) ^ v_c) << 4));
                uint32_t b0[2] = {r0, r1}, b1[2] = {r2, r3};
                mma_bf16(o[2 * u], a, b0);
                mma_bf16(o[2 * u + 1], a, b1);
            }
        }
        __syncthreads();
        buf ^= 1;
    }

    float inv0 = 1.f / l0, inv1 = 1.f / l1;
    int row0 = q0 + wrow + grp;
#pragma unroll
    for (int n = 0; n < 12; n++) {
        int c = n * 8 + tig * 2;
        float f0 = fw[b * Cdim + h * Dd + c];
        float f1 = fw[b * Cdim + h * Dd + c + 1];
        size_t ob0 = ((size_t)b * Nseq + row0) * Cdim + h * Dd + c;
        size_t ob1 = ((size_t)b * Nseq + row0 + 8) * Cdim + h * Dd + c;
        float2 qv0 = *(const float2*)(qout + ob0);
        float2 qv1 = *(const float2*)(qout + ob1);
        fusedbf[ob0 >> 1] = pkbf(f0 * qv0.x + (1.f - f0) * o[n][0] * inv0,
                                 f1 * qv0.y + (1.f - f1) * o[n][1] * inv0);
        fusedbf[ob1 >> 1] = pkbf(f0 * qv1.x + (1.f - f0) * o[n][2] * inv1,
                                 f1 * qv1.y + (1.f - f1) * o[n][3] * inv1);
    }
}

// ================= quantum embed GEMM (bf16 A): H = relu(A @ W1 + b1) =================
__global__ __launch_bounds__(256)
void embed_gemm(const uint32_t* __restrict__ qkvbf,
                const float* __restrict__ qW1, const float* __restrict__ qb1,
                const float* __restrict__ kW1, const float* __restrict__ kb1,
                float* __restrict__ Hq, float* __restrict__ Hk) {
    __shared__ uint32_t As[2][8][136];
    __shared__ uint32_t Bs[48][72];
    int tid = threadIdx.x;
    int m0 = blockIdx.x * 128;
    int pass = blockIdx.y;
    const float* W1 = pass ? kW1 : qW1;
    const float* b1 = pass ? kb1 : qb1;
    float* H = pass ? Hk : Hq;
    int qk_off32 = pass * 384;

    for (int i = tid; i < 768; i += 256) {
        int k2 = i >> 4, c4 = i & 15;
        float4 w0 = *(const float4*)(W1 + (2 * k2) * 64 + c4 * 4);
        float4 w1 = *(const float4*)(W1 + (2 * k2 + 1) * 64 + c4 * 4);
        *(uint4*)&Bs[k2][c4 * 4] = make_uint4(pkbf(w0.x, w1.x), pkbf(w0.y, w1.y),
                                              pkbf(w0.z, w1.z), pkbf(w0.w, w1.w));
    }

    int arow = tid >> 1, apart = tid & 1;
    int mrow = m0 + arow;
    const uint4* Ap4 = (const uint4*)(qkvbf + (size_t)(mrow >> 3) * 1152 + qk_off32 + (mrow & 7) * 48);

    int wid = tid >> 5, lane = tid & 31;
    int wm = (wid >> 2) * 64, wn = (wid & 3) * 16;
    int grp = lane >> 2, tig = lane & 3;
    float acc[4][2][4] = {};

    {
        uint4 av = Ap4[apart];
        As[0][apart * 4 + 0][arow] = av.x;
        As[0][apart * 4 + 1][arow] = av.y;
        As[0][apart * 4 + 2][arow] = av.z;
        As[0][apart * 4 + 3][arow] = av.w;
    }
    __syncthreads();

    int buf = 0;
    for (int s = 1; s <= 6; s++) {
        bool more = (s < 6);
        uint4 av;
        if (more) av = Ap4[s * 2 + apart];
        int kb = (s - 1) * 8;
        uint32_t a[4][4], b[2][2];
#pragma unroll
        for (int mi = 0; mi < 4; mi++) {
            int r = wm + mi * 16 + grp;
            a[mi][0] = As[buf][tig][r];
            a[mi][1] = As[buf][tig][r + 8];
            a[mi][2] = As[buf][tig + 4][r];
            a[mi][3] = As[buf][tig + 4][r + 8];
        }
#pragma unroll
        for (int nj = 0; nj < 2; nj++) {
            int c = wn + nj * 8 + grp;
            b[nj][0] = Bs[kb + tig][c];
            b[nj][1] = Bs[kb + tig + 4][c];
        }
#pragma unroll
        for (int mi = 0; mi < 4; mi++)
#pragma unroll
            for (int nj = 0; nj < 2; nj++) mma_bf16(acc[mi][nj], a[mi], b[nj]);
        if (more) {
            As[buf ^ 1][apart * 4 + 0][arow] = av.x;
            As[buf ^ 1][apart * 4 + 1][arow] = av.y;
            As[buf ^ 1][apart * 4 + 2][arow] = av.z;
            As[buf ^ 1][apart * 4 + 3][arow] = av.w;
            __syncthreads();
            buf ^= 1;
        }
    }

#pragma unroll
    for (int nj = 0; nj < 2; nj++) {
        int c = wn + nj * 8 + tig * 2;
        float bi0 = __ldg(&b1[c]), bi1 = __ldg(&b1[c + 1]);
#pragma unroll
        for (int mi = 0; mi < 4; mi++) {
            size_t r = m0 + wm + mi * 16 + grp;
            *(float2*)(H + r * 64 + c) =
                make_float2(fmaxf(acc[mi][nj][0] + bi0, 0.f), fmaxf(acc[mi][nj][1] + bi1, 0.f));
            *(float2*)(H + (r + 8) * 64 + c) =
                make_float2(fmaxf(acc[mi][nj][2] + bi0, 0.f), fmaxf(acc[mi][nj][3] + bi1, 0.f));
        }
    }
}

// ================= quantum middle: e -> state -> meas =================
__global__ __launch_bounds__(128)
void quantum_mid(const float* __restrict__ Hq, const float* __restrict__ Hk,
                 const float* __restrict__ qe_w2, const float* __restrict__ qe_b2,
                 const float* __restrict__ ke_w2, const float* __restrict__ ke_b2,
                 const float* __restrict__ gate_params, const float* __restrict__ ent_params,
                 const float* __restrict__ gumbel, float* __restrict__ meas_out) {
    __shared__ float w2q[1024], w2k[1024];
    __shared__ float gf[2][8], gcz[2][8], gsz[2][8], gs[2][8];
    int tid = threadIdx.x;
    for (int i = tid; i < 256; i += 128) {
        ((float4*)w2q)[i] = ((const float4*)qe_w2)[i];
        ((float4*)w2k)[i] = ((const float4*)ke_w2)[i];
    }
    if (tid < 16) {
        int l = tid >> 3, i = tid & 7;
        float ry = gate_params[(l * 8 + i) * 3 + 1];
        float rz = gate_params[(l * 8 + i) * 3 + 2];
        gf[l][i] = cosf(0.5f * ry);
        gcz[l][i] = cosf(rz);
        gsz[l][i] = sinf(rz);
    } else if (tid < 30) {
        int t = tid - 16, l = t / 7, i = t % 7;
        gs[l][i + 1] = 1.f / (1.f + expf(-ent_params[l * 7 + i]));
    }
    __syncthreads();

    int m = blockIdx.x * 128 + tid;
    float sre[8], sim[8];

#pragma unroll
    for (int pass = 0; pass < 2; pass++) {
        const float* Hrow = (pass == 0 ? Hq : Hk) + (size_t)m * 64;
        const float* w2 = (pass == 0 ? w2q : w2k);
        const float* b2 = (pass == 0 ? qe_b2 : ke_b2);
        float e[16];
#pragma unroll
        for (int i = 0; i < 16; i++) e[i] = __ldg(&b2[i]);
        const float4* h4 = (const float4*)Hrow;
#pragma unroll
        for (int j4 = 0; j4 < 16; j4++) {
            float4 hv = h4[j4];
            float hs[4] = {hv.x, hv.y, hv.z, hv.w};
#pragma unroll
            for (int s = 0; s < 4; s++) {
                float hj = hs[s];
                const float4* wr = (const float4*)&w2[(j4 * 4 + s) * 16];
#pragma unroll
                for (int i4 = 0; i4 < 4; i4++) {
                    float4 w = wr[i4];
                    e[i4 * 4 + 0] += hj * w.x; e[i4 * 4 + 1] += hj * w.y;
                    e[i4 * 4 + 2] += hj * w.z; e[i4 * 4 + 3] += hj * w.w;
                }
            }
        }
        float mx = e[0];
#pragma unroll
        for (int i = 1; i < 8; i++) mx = fmaxf(mx, e[i]);
        float ex[8], ssum = 0.f;
#pragma unroll
        for (int i = 0; i < 8; i++) { ex[i] = __expf(e[i] - mx); ssum += ex[i]; }
        float inv = 1.f / ssum;
#pragma unroll
        for (int i = 0; i < 8; i++) {
            float amp = ex[i] * inv;
            float cr = amp * __cosf(e[8 + i]), ci = amp * __sinf(e[8 + i]);
            if (pass == 0) { sre[i] = cr; sim[i] = ci; }
            else           { sre[i] += cr; sim[i] += ci; }
        }
    }

#pragma unroll
    for (int l = 0; l < 2; l++) {
#pragma unroll
        for (int i = 0; i < 8; i++) {
            float nr = sre[i] * gcz[l][i] - sim[i] * gsz[l][i];
            float ni = sre[i] * gsz[l][i] + sim[i] * gcz[l][i];
            sre[i] = nr * gf[l][i];
            sim[i] = ni * gf[l][i];
        }
#pragma unroll
        for (int i = 7; i >= 1; i--) {
            sre[i] += gs[l][i] * sre[i - 1];
            sim[i] += gs[l][i] * sim[i - 1];
        }
    }

    float p[8], mx = -1e30f;
#pragma unroll
    for (int i = 0; i < 8; i++) { p[i] = sre[i] * sre[i] + sim[i] * sim[i]; mx = fmaxf(mx, p[i]); }
    float ssum = 0.f;
#pragma unroll
    for (int i = 0; i < 8; i++) { p[i] = __expf(p[i] - mx); ssum += p[i]; }
    float sinv = 1.f / ssum;
    int b = m >> 13, n = (m >> 3) & 1023, h = m & 7;
    size_t goff = (size_t)(((b * 8 + h) << 10) + n) * 8;
    float4 g0 = __ldg((const float4*)(gumbel + goff));
    float4 g1 = __ldg((const float4*)(gumbel + goff + 4));
    float gv[8] = {g0.x, g0.y, g0.z, g0.w, g1.x, g1.y, g1.z, g1.w};
    float lg[8], mx2 = -1e30f;
#pragma unroll
    for (int i = 0; i < 8; i++) {
        lg[i] = 2.f * (__logf(p[i] * sinv + 1e-10f) + gv[i]);
        mx2 = fmaxf(mx2, lg[i]);
    }
    float meas[8], msum = 0.f;
#pragma unroll
    for (int i = 0; i < 8; i++) { meas[i] = __expf(lg[i] - mx2); msum += meas[i]; }
    float minv = 1.f / msum;
    float4 o0 = make_float4(meas[0] * minv, meas[1] * minv, meas[2] * minv, meas[3] * minv);
    float4 o1 = make_float4(meas[4] * minv, meas[5] * minv, meas[6] * minv, meas[7] * minv);
    *(float4*)(meas_out + (size_t)m * 8) = o0;
    *(float4*)(meas_out + (size_t)m * 8 + 4) = o1;
}

// ================= fused measure MLP (tf32): qout = (relu(meas@W1+b1)@W2+b2)*v =================
#define MD_T1_LD 136
#define MD_W2_LD 104
#define MD_SMEM ((8 * 136 + 8 * 72 + 64 * MD_T1_LD + 64 * MD_W2_LD) * 4)

__global__ __launch_bounds__(256)
void md_fused(const float* __restrict__ meas,
              const float* __restrict__ W1, const float* __restrict__ b1,
              const float* __restrict__ W2, const float* __restrict__ b2,
              const uint32_t* __restrict__ qkvbf, float* __restrict__ qout) {
    extern __shared__ float sm[];
    float* As8 = sm;
    float* W1s = sm + 8 * 136;
    float* T1  = sm + 8 * 136 + 8 * 72;
    float* W2s = T1 + 64 * MD_T1_LD;

    int tid = threadIdx.x;
    int m0 = blockIdx.x * 128;
    int wid = tid >> 5, lane = tid & 31;
    int grp = lane >> 2, tig = lane & 3;
    int wm = (wid >> 2) * 64;

    {
        int arow = tid >> 1, ak = (tid & 1) * 4;
        float4 v = *(const float4*)(meas + (size_t)(m0 + arow) * 8 + ak);
        As8[(ak + 0) * 136 + arow] = to_tf32(v.x);
        As8[(ak + 1) * 136 + arow] = to_tf32(v.y);
        As8[(ak + 2) * 136 + arow] = to_tf32(v.z);
        As8[(ak + 3) * 136 + arow] = to_tf32(v.w);
    }
    for (int i = tid; i < 128; i += 256) {
        int d = i >> 4, n4 = i & 15;
        float4 w = ((const float4*)W1)[i];
        float4 wc = make_float4(to_tf32(w.x), to_tf32(w.y), to_tf32(w.z), to_tf32(w.w));
        *(float4*)&W1s[d * 72 + n4 * 4] = wc;
    }
    for (int i = tid; i < 1536; i += 256) {
        int d = i / 24, n4 = i % 24;
        float4 w = ((const float4*)W2)[i];
        float4 wc = make_float4(to_tf32(w.x), to_tf32(w.y), to_tf32(w.z), to_tf32(w.w));
        *(float4*)&W2s[d * MD_W2_LD + n4 * 4] = wc;
    }
    __syncthreads();

    {
        int wn1 = (wid & 3) * 16;
        float acc1[4][2][4] = {};
        uint32_t a[4][4], b[2][2];
#pragma unroll
        for (int mi = 0; mi < 4; mi++) {
            int r = wm + mi * 16 + grp;
            a[mi][0] = __float_as_uint(As8[tig * 136 + r]);
            a[mi][1] = __float_as_uint(As8[tig * 136 + r + 8]);
            a[mi][2] = __float_as_uint(As8[(tig + 4) * 136 + r]);
            a[mi][3] = __float_as_uint(As8[(tig + 4) * 136 + r + 8]);
        }
#pragma unroll
        for (int nj = 0; nj < 2; nj++) {
            int c = wn1 + nj * 8 + grp;
            b[nj][0] = __float_as_uint(W1s[tig * 72 + c]);
            b[nj][1] = __float_as_uint(W1s[(tig + 4) * 72 + c]);
        }
#pragma unroll
        for (int mi = 0; mi < 4; mi++)
#pragma unroll
            for (int nj = 0; nj < 2; nj++) mma_tf32(acc1[mi][nj], a[mi], b[nj]);

#pragma unroll
        for (int nj = 0; nj < 2; nj++) {
            int c = wn1 + nj * 8 + tig * 2;
            float bi0 = __ldg(&b1[c]), bi1 = __ldg(&b1[c + 1]);
#pragma unroll
            for (int mi = 0; mi < 4; mi++) {
                int r = wm + mi * 16 + grp;
                T1[c * MD_T1_LD + r]           = to_tf32(fmaxf(acc1[mi][nj][0] + bi0, 0.f));
                T1[(c + 1) * MD_T1_LD + r]     = to_tf32(fmaxf(acc1[mi][nj][1] + bi1, 0.f));
                T1[c * MD_T1_LD + r + 8]       = to_tf32(fmaxf(acc1[mi][nj][2] + bi0, 0.f));
                T1[(c + 1) * MD_T1_LD + r + 8] = to_tf32(fmaxf(acc1[mi][nj][3] + bi1, 0.f));
            }
        }
    }
    __syncthreads();

    int wn = (wid & 3) * 24;
    float acc2[4][3][4] = {};
#pragma unroll
    for (int ks = 0; ks < 8; ks++) {
        uint32_t a[4][4], b[3][2];
#pragma unroll
        for (int mi = 0; mi < 4; mi++) {
            int r = wm + mi * 16 + grp;
            a[mi][0] = __float_as_uint(T1[(ks * 8 + tig) * MD_T1_LD + r]);
            a[mi][1] = __float_as_uint(T1[(ks * 8 + tig) * MD_T1_LD + r + 8]);
            a[mi][2] = __float_as_uint(T1[(ks * 8 + tig + 4) * MD_T1_LD + r]);
            a[mi][3] = __float_as_uint(T1[(ks * 8 + tig + 4) * MD_T1_LD + r + 8]);
        }
#pragma unroll
        for (int nj = 0; nj < 3; nj++) {
            int c = wn + nj * 8 + grp;
            b[nj][0] = __float_as_uint(W2s[(ks * 8 + tig) * MD_W2_LD + c]);
            b[nj][1] = __float_as_uint(W2s[(ks * 8 + tig + 4) * MD_W2_LD + c]);
        }
#pragma unroll
        for (int mi = 0; mi < 4; mi++)
#pragma unroll
            for (int nj = 0; nj < 3; nj++) mma_tf32(acc2[mi][nj], a[mi], b[nj]);
    }

#pragma unroll
    for (int nj = 0; nj < 3; nj++) {
        int c = wn + nj * 8 + tig * 2;
        float bi0 = __ldg(&b2[c]), bi1 = __ldg(&b2[c + 1]);
#pragma unroll
        for (int mi = 0; mi < 4; mi++) {
            int m = m0 + wm + mi * 16 + grp;
#pragma unroll
            for (int half = 0; half < 2; half++) {
                int mm = m + half * 8;
                size_t qrow = (size_t)(mm >> 3);
                int hh = mm & 7;
                uint32_t u = qkvbf[(qrow * 2304 + 1536 + hh * 96 + c) >> 1];
                float2 vv = __bfloat1622float2(*(__nv_bfloat162*)&u);
                float o0 = (acc2[mi][nj][half * 2 + 0] + bi0) * vv.x;
                float o1 = (acc2[mi][nj][half * 2 + 1] + bi1) * vv.y;
                *(float2*)(qout + qrow * 768 + hh * 96 + c) = make_float2(o0, o1);
            }
        }
    }
}

// ================= mean over N =================
__global__ void colmean_kernel(const float* __restrict__ x, float* __restrict__ xmean) {
    int b = blockIdx.y;
    int c = blockIdx.x * 256 + threadIdx.x;
    const float* p = x + (size_t)b * Nseq * Cdim + c;
    float s = 0.f;
    for (int n = 0; n < Nseq; n++) s += p[(size_t)n * Cdim];
    xmean[b * Cdim + c] = s * (1.0f / 1024.0f);
}

// ================= fw = sigmoid(xmean @ w_proj + b_proj) =================
__global__ void fw_kernel(const float* __restrict__ xmean, const float* __restrict__ w_proj,
                          const float* __restrict__ b_proj, float* __restrict__ fw) {
    __shared__ float xm[768];
    int b = blockIdx.x;
    int c = threadIdx.x;
    xm[c] = xmean[b * Cdim + c];
    __syncthreads();
    float s = b_proj[c];
    for (int k = 0; k < 768; k++) s += xm[k] * w_proj[(size_t)k * 768 + c];
    fw[b * Cdim + c] = 1.f / (1.f + expf(-s));
}

// ================= layernorm =================
__global__ void layernorm_kernel(const float* __restrict__ y, const float* __restrict__ gamma,
                                 const float* __restrict__ beta, float* __restrict__ out) {
    __shared__ float red1[8], red2[8];
    size_t row = blockIdx.x;
    const float* p = y + row * Cdim;
    int tid = threadIdx.x;
    float v[3];
    float s = 0.f;
#pragma unroll
    for (int i = 0; i < 3; i++) { v[i] = p[tid + i * 256]; s += v[i]; }
#pragma unroll
    for (int o = 16; o > 0; o >>= 1) s += __shfl_xor_sync(~0u, s, o);
    int w = tid >> 5, lane = tid & 31;
    if (lane == 0) red1[w] = s;
    __syncthreads();
    s = 0.f;
#pragma unroll
    for (int i = 0; i < 8; i++) s += red1[i];
    float mu = s * (1.0f / 768.0f);
    float vs = 0.f;
#pragma unroll
    for (int i = 0; i < 3; i++) { float d = v[i] - mu; vs += d * d; }
#pragma unroll
    for (int o = 16; o > 0; o >>= 1) vs += __shfl_xor_sync(~0u, vs, o);
    if (lane == 0) red2[w] = vs;
    __syncthreads();
    vs = 0.f;
#pragma unroll
    for (int i = 0; i < 8; i++) vs += red2[i];
    float inv = rsqrtf(vs * (1.0f / 768.0f) + 1e-5f);
#pragma unroll
    for (int i = 0; i < 3; i++) {
        int c = tid + i * 256;
        out[row * Cdim + c] = (v[i] - mu) * inv * gamma[c] + beta[c];
    }
}

// ================= launch =================
extern "C" void kernel_launch(void* const* d_in, const int* in_sizes, int n_in,
                              void* d_out, int out_size) {
    const float* x      = (const float*)d_in[0];
    const float* w_qkv  = (const float*)d_in[1];
    const float* b_qkv  = (const float*)d_in[2];
    const float* w_proj = (const float*)d_in[3];
    const float* b_proj = (const float*)d_in[4];
    const float* gamma  = (const float*)d_in[5];
    const float* beta   = (const float*)d_in[6];
    const float* qe_w1  = (const float*)d_in[7];
    const float* qe_b1  = (const float*)d_in[8];
    const float* qe_w2  = (const float*)d_in[9];
    const float* qe_b2  = (const float*)d_in[10];
    const float* ke_w1  = (const float*)d_in[11];
    const float* ke_b1  = (const float*)d_in[12];
    const float* ke_w2  = (const float*)d_in[13];
    const float* ke_b2  = (const float*)d_in[14];
    const float* gate_params = (const float*)d_in[19];
    const float* ent_params  = (const float*)d_in[20];
    const float* md_w1  = (const float*)d_in[21];
    const float* md_b1  = (const float*)d_in[22];
    const float* md_w2  = (const float*)d_in[23];
    const float* md_b2  = (const float*)d_in[24];
    const float* gumbel = (const float*)d_in[25];
    float* out = (float*)d_out;

    uint32_t *qkvbf, *fusedbf, *xbf;
    __nv_bfloat16 *wqT, *wpT;
    float *qout, *y, *xmean, *fw, *hq, *hk, *meas;
    cudaGetSymbolAddress((void**)&qkvbf, g_qkv_bf);
    cudaGetSymbolAddress((void**)&fusedbf, g_fused_bf);
    cudaGetSymbolAddress((void**)&xbf, g_x_bf);
    cudaGetSymbolAddress((void**)&wqT, g_wqT);
    cudaGetSymbolAddress((void**)&wpT, g_wpT);
    cudaGetSymbolAddress((void**)&qout, g_qout);
    cudaGetSymbolAddress((void**)&y, g_y);
    cudaGetSymbolAddress((void**)&xmean, g_xmean);
    cudaGetSymbolAddress((void**)&fw, g_fw);
    cudaGetSymbolAddress((void**)&hq, g_hq);
    cudaGetSymbolAddress((void**)&hk, g_hk);
    cudaGetSymbolAddress((void**)&meas, g_meas);

    cudaFuncSetAttribute(flash_kernel, cudaFuncAttributeMaxDynamicSharedMemorySize, FLASH_SMEM);
    cudaFuncSetAttribute(md_fused, cudaFuncAttributeMaxDynamicSharedMemorySize, MD_SMEM);

    // pre-conversions
    cvt_x<<<(Bsz * Nseq * Cdim / 2) / 256, 256>>>(x, xbf);
    cvt_wT<<<dim3(2304 / 32, 768 / 32), dim3(32, 8)>>>(w_qkv, wqT, 768, 2304);
    cvt_wT<<<dim3(768 / 32, 768 / 32), dim3(32, 8)>>>(w_proj, wpT, 768, 768);
    // gate path (depends only on x)
    colmean_kernel<<<dim3(3, 8), 256>>>(x, xmean);
    fw_kernel<<<8, 768>>>(xmean, w_proj, b_proj, fw);
    // qkv = x @ w_qkv + b_qkv  -> bf16
    mma_bf<<<dim3(2304 / 128, 8192 / 128), 256>>>(xbf, wqT, b_qkv, nullptr,
                                                  nullptr, qkvbf, 768, 768, 2304);
    // quantum path: embeds (GEMM) -> mid -> measure MLP (GEMM) -> qout
    embed_gemm<<<dim3(NTOK / 128, 2), 256>>>(qkvbf, qe_w1, qe_b1, ke_w1, ke_b1, hq, hk);
    quantum_mid<<<NTOK / 128, 128>>>(hq, hk, qe_w2, qe_b2, ke_w2, ke_b2,
                                     gate_params, ent_params, gumbel, meas);
    md_fused<<<NTOK / 128, 256, MD_SMEM>>>(meas, md_w1, md_b1, md_w2, md_b2, qkvbf, qout);
    // fused classical attention + gate blend -> fused (bf16)
    flash_kernel<<<dim3(8, 64), 256, FLASH_SMEM>>>(qkvbf, qout, fw, fusedbf);
    // y = x + fused @ w_proj + b_proj
    mma_bf<<<dim3(768 / 128, 8192 / 128), 256>>>(fusedbf, wpT, b_proj, x,
                                                 y, nullptr, 768, 768, 768);
    // layernorm
    layernorm_kernel<<<8192, 256>>>(y, gamma, beta, out);
}